// round 10
// baseline (speedup 1.0000x reference)
#include <cuda_runtime.h>
#include <cuda_bf16.h>
#include <math.h>
#include <stdint.h>

#define NPTS 32768
#define TOTAL 2336
#define KPAD1 2368         // GEMM1 K padded (74 blocks of 32)
#define NST1 74
#define KPAD2 2432         // GEMM2 K (76 blocks)
#define NST2 76
#define TWOTOTAL 4672
#define INNER 64
#define AW1 4736           // g_Abf row: 74 blocks x [hi32|lo32]
#define VW 4864            // g_Vbf / g_WT2 row: 76 blocks x [hi32|lo32]
#define WTS 4736           // g_WT row width (74 blocks)
#define WTROWS 4864        // permuted W1 rows (19 tiles x 256)
#define NTILES 19
#define NGRP 292           // TOTAL / 8
#define CWBLK (152 * 74)   // convW blocks
#define CW2BLK 584         // convW2 blocks (584*256 = 149504 = 2336*64)

// ---------------- scratch (static device memory; zero-initialized) -----------
__device__ float g_p[NPTS * 3];
__device__ __align__(128) __nv_bfloat16 g_Abf[(size_t)NPTS * AW1];
__device__ __align__(128) __nv_bfloat16 g_Vbf[(size_t)NPTS * VW];
__device__ __align__(128) __nv_bfloat16 g_WT[(size_t)WTROWS * WTS];
__device__ __align__(128) __nv_bfloat16 g_WT2[(size_t)64 * VW];
__device__ float g_sspart[(size_t)NPTS * NTILES];
__device__ float g_down[NPTS * INNER];     // used by FFMA fallback only

// ---------------- common helpers ---------------------------------------------
__device__ __forceinline__ uint32_t smem_u32(const void* p) {
    uint32_t a;
    asm("{ .reg .u64 t; cvta.to.shared.u64 t, %1; cvt.u32.u64 %0, t; }" : "=r"(a) : "l"(p));
    return a;
}
__device__ __forceinline__ float sigmoidf_(float x) { return 1.0f / (1.0f + expf(-x)); }
__device__ __forceinline__ float gelu_tanh(float x) {
    float x3 = x * x * x;
    return 0.5f * x * (1.0f + tanhf(0.7978845608028654f * (x + 0.044715f * x3)));
}
__device__ __forceinline__ int wrapi(int v, int d) {
    if (v < 0) v += d; else if (v >= d) v -= d; return v;
}
__device__ const int FACE3[6][3] = {{1,0,0},{-1,0,0},{0,1,0},{0,-1,0},{0,0,1},{0,0,-1}};
__device__ const int ST8[8][4]   = {{1,0,0,0},{-1,0,0,0},{0,1,0,0},{0,-1,0,0},
                                    {0,0,1,0},{0,0,-1,0},{0,0,0,1},{0,0,0,-1}};

// cp.async helpers (baseline PTX)
#define CP_ASYNC16(smem, gmem) \
    asm volatile("cp.async.cg.shared.global [%0], [%1], 16;" :: "r"(smem), "l"(gmem) : "memory")
#define CP_COMMIT() asm volatile("cp.async.commit_group;" ::: "memory")
#define CP_WAIT2()  asm volatile("cp.async.wait_group 2;" ::: "memory")
#define CP_WAIT1()  asm volatile("cp.async.wait_group 1;" ::: "memory")
#define CP_WAIT0()  asm volatile("cp.async.wait_group 0;" ::: "memory")

#if defined(__CUDA_ARCH_FEAT_SM103_ALL)
// ---------------- tcgen05 helpers (sm_103a pass only) -------------------------
__device__ __forceinline__ uint32_t elect_one() {
    uint32_t p;
    asm volatile("{ .reg .pred p; elect.sync _|p, 0xFFFFFFFF; selp.b32 %0,1,0,p; }" : "=r"(p));
    return p;
}
#define MBARRIER_INIT(addr, cnt) \
    asm volatile("mbarrier.init.shared.b64 [%0], %1;" :: "r"(addr), "r"(cnt) : "memory")
#define MBARRIER_WAIT_PARITY(addr, parity) do { \
    uint32_t _m = (addr); uint32_t _p = (parity); uint32_t _d; \
    asm volatile("{ .reg .pred p; mbarrier.try_wait.parity.acquire.cta.shared::cta.b64 p, [%1], %2; selp.b32 %0,1,0,p; }" \
        : "=r"(_d) : "r"(_m), "r"(_p) : "memory"); \
    if (!_d) { \
        asm volatile("{ .reg .pred P1; WL_%=: mbarrier.try_wait.parity.acquire.cta.shared::cta.b64 P1, [%0], %1, 0x989680; @P1 bra.uni WD_%=; bra.uni WL_%=; WD_%=: }" \
            :: "r"(_m), "r"(_p) : "memory"); \
    } } while (0)
#define CPA_MBAR_ARRIVE_NOINC(mbar) \
    asm volatile("cp.async.mbarrier.arrive.noinc.shared::cta.b64 [%0];" :: "r"(mbar) : "memory")
#define TC_ALLOC(slot, n)  asm volatile("tcgen05.alloc.cta_group::1.sync.aligned.shared::cta.b32 [%0], %1;" :: "r"(slot), "r"(n) : "memory")
#define TC_DEALLOC(t, n)   asm volatile("tcgen05.dealloc.cta_group::1.sync.aligned.b32 %0, %1;" :: "r"(t), "r"(n))
#define TC_RELINQ()        asm volatile("tcgen05.relinquish_alloc_permit.cta_group::1.sync.aligned;")
#define TC_COMMIT(mbar)    asm volatile("tcgen05.commit.cta_group::1.mbarrier::arrive::one.shared::cluster.b64 [%0];" :: "r"(mbar) : "memory")
#define TC_WAIT_LD()       asm volatile("tcgen05.wait::ld.sync.aligned;" ::: "memory")
#define TC_FENCE_AFTER()   asm volatile("tcgen05.fence::after_thread_sync;" ::: "memory")
#define FENCE_ASYNC_SH()   asm volatile("fence.proxy.async.shared::cta;" ::: "memory")
#define TC_LD_X32(r, addr) \
    asm volatile("tcgen05.ld.sync.aligned.32x32b.x32.b32 " \
        "{%0,%1,%2,%3,%4,%5,%6,%7,%8,%9,%10,%11,%12,%13,%14,%15," \
        "%16,%17,%18,%19,%20,%21,%22,%23,%24,%25,%26,%27,%28,%29,%30,%31}, [%32];" \
        : "=r"((r)[0]),"=r"((r)[1]),"=r"((r)[2]),"=r"((r)[3]),"=r"((r)[4]),"=r"((r)[5]),"=r"((r)[6]),"=r"((r)[7]), \
          "=r"((r)[8]),"=r"((r)[9]),"=r"((r)[10]),"=r"((r)[11]),"=r"((r)[12]),"=r"((r)[13]),"=r"((r)[14]),"=r"((r)[15]), \
          "=r"((r)[16]),"=r"((r)[17]),"=r"((r)[18]),"=r"((r)[19]),"=r"((r)[20]),"=r"((r)[21]),"=r"((r)[22]),"=r"((r)[23]), \
          "=r"((r)[24]),"=r"((r)[25]),"=r"((r)[26]),"=r"((r)[27]),"=r"((r)[28]),"=r"((r)[29]),"=r"((r)[30]),"=r"((r)[31]) \
        : "r"(addr))
static constexpr uint64_t SMEM_DESC_BASE =
    (uint64_t(2) << 61) | (uint64_t(1) << 46) | (uint64_t(64) << 32) | (uint64_t(1) << 16);
__device__ __forceinline__ uint64_t make_desc(uint32_t addr) {
    return SMEM_DESC_BASE | ((uint64_t)(addr >> 4) & 0x3FFF);
}
__device__ __forceinline__ void mma_f16_ss(uint32_t d, uint64_t a, uint64_t b,
                                           uint32_t idesc, uint32_t en) {
    asm volatile("{ .reg .pred p; setp.ne.u32 p, %4, 0;"
                 "tcgen05.mma.cta_group::1.kind::f16 [%0], %1, %2, %3, {%5,%5,%5,%5}, p; }"
                 :: "r"(d), "l"(a), "l"(b), "r"(idesc), "r"(en), "r"(0u) : "memory");
}
#endif

// ---------------- K1: per-point preamble MLP -> p ----------------------------
__global__ void k1_preamble(const float* __restrict__ pos, const float* __restrict__ t,
                            const float* __restrict__ sph_proj,
                            const float* __restrict__ tb1, const float* __restrict__ tb2,
                            const float* __restrict__ gn1, const float* __restrict__ gw1,
                            const float* __restrict__ gn2, const float* __restrict__ gw2,
                            const float* __restrict__ gn3, const float* __restrict__ gw3)
{
    int i = blockIdx.x * blockDim.x + threadIdx.x;
    if (i >= NPTS) return;

    float x = pos[i * 3 + 0], y = pos[i * 3 + 1], z = pos[i * 3 + 2];
    float rho = sqrtf(x * x + y * y + z * z);
    float phi = atan2f(y, x);
    float cz = z / rho;
    cz = fminf(1.0f, fmaxf(-1.0f, cz));
    float theta = acosf(cz);

    float h[12];
#pragma unroll
    for (int j = 0; j < 8; j++)
        h[j] = rho * sph_proj[j] + phi * sph_proj[8 + j] + theta * sph_proj[16 + j];
    float tv = t[i];
    float ct = cosf(tv + tb1[0]);
    float st = sinf(tv + tb2[0]);
    h[8] = ct; h[9] = st;
    h[10] = ct * sigmoidf_(ct);
    h[11] = st * sigmoidf_(st);

    float ss = 0.f;
#pragma unroll
    for (int j = 0; j < 12; j++) ss += h[j] * h[j];
    float sc = 1.0f / (sqrtf(ss / 12.0f) + 1e-8f);
    float hn[12];
#pragma unroll
    for (int j = 0; j < 12; j++) hn[j] = gn1[j] * h[j] * sc;
    float y1[32];
#pragma unroll
    for (int j = 0; j < 32; j++) y1[j] = 0.f;
#pragma unroll
    for (int r = 0; r < 12; r++) {
        float a = hn[r];
#pragma unroll
        for (int j = 0; j < 32; j++) y1[j] += a * gw1[r * 32 + j];
    }
    float h2[16];
#pragma unroll
    for (int k = 0; k < 16; k++) h2[k] = y1[k] * gelu_tanh(y1[16 + k]);

    ss = 0.f;
#pragma unroll
    for (int j = 0; j < 16; j++) ss += h2[j] * h2[j];
    sc = 1.0f / (sqrtf(ss / 16.0f) + 1e-8f);
    float hn2[16];
#pragma unroll
    for (int j = 0; j < 16; j++) hn2[j] = gn2[j] * h2[j] * sc;
    float y2[32];
#pragma unroll
    for (int j = 0; j < 32; j++) y2[j] = 0.f;
#pragma unroll
    for (int r = 0; r < 16; r++) {
        float a = hn2[r];
#pragma unroll
        for (int j = 0; j < 32; j++) y2[j] += a * gw2[r * 32 + j];
    }
    float h3[16];
#pragma unroll
    for (int k = 0; k < 16; k++) h3[k] = y2[k] * gelu_tanh(y2[16 + k]);

    ss = 0.f;
#pragma unroll
    for (int j = 0; j < 16; j++) ss += h3[j] * h3[j];
    sc = 1.0f / (sqrtf(ss / 16.0f) + 1e-8f);
    float z3[3] = {0.f, 0.f, 0.f};
#pragma unroll
    for (int r = 0; r < 16; r++) {
        float a = gn3[r] * h3[r] * sc;
#pragma unroll
        for (int j = 0; j < 3; j++) z3[j] += a * gw3[r * 3 + j];
    }
    g_p[i * 3 + 0] = sigmoidf_(z3[0]);
    g_p[i * 3 + 1] = sigmoidf_(z3[1]);
    g_p[i * 3 + 2] = sigmoidf_(z3[2]);
}

// ---------------- K2m: fused gather + convW + convW2 (branch on blockIdx) -----
__global__ void __launch_bounds__(256) k2m(const float* __restrict__ t,
                          const float* __restrict__ table0, const float* __restrict__ table1,
                          const float* __restrict__ table2, const float* __restrict__ table3,
                          const float* __restrict__ st1, const float* __restrict__ st2,
                          const float* __restrict__ tf, const float* __restrict__ vn1,
                          const float* __restrict__ vw1, const float* __restrict__ vw2,
                          const float* __restrict__ vn2)
{
    int bid = blockIdx.x;
    __shared__ const float* segp[47];
    __shared__ __align__(16) float red[256];
    __shared__ float sh[32][33];

    if (bid < NPTS) {
        // -------- gather + rmsnorm(vn1) -> hi/lo bf16 (256 threads) --------
        int i = bid;
        float p0 = g_p[i * 3 + 0], p1 = g_p[i * 3 + 1], p2 = g_p[i * 3 + 2];
        float tt = t[i];

        int s = threadIdx.x;
        if (s < 47) {
            const float* base = nullptr;
            if (s < 28) {
                int tb = s / 7;
                int o = s % 7;
                int d, F; const float* T;
                if (tb == 0)      { d = 128; F = 16;  T = table0; }
                else if (tb == 1) { d = 64;  F = 32;  T = table1; }
                else if (tb == 2) { d = 32;  F = 64;  T = table2; }
                else              { d = 16;  F = 128; T = table3; }
                int ix = (int)(p0 * (float)(d - 1));
                int iy = (int)(p1 * (float)(d - 1));
                int iz = (int)(p2 * (float)(d - 1));
                if (o > 0) {
                    ix = wrapi(ix + FACE3[o - 1][0], d);
                    iy = wrapi(iy + FACE3[o - 1][1], d);
                    iz = wrapi(iz + FACE3[o - 1][2], d);
                }
                base = T + (size_t)((ix * d + iy) * d + iz) * F;
            } else if (s < 46) {
                int grp = (s - 28) / 9;
                int o = (s - 28) % 9;
                if (grp == 0) {
                    int a = (int)(p0 * 15.0f), b = (int)(p1 * 15.0f),
                        c = (int)(p2 * 15.0f), e = (int)(tt * 63.0f);
                    if (o > 0) {
                        a = wrapi(a + ST8[o - 1][0], 16);
                        b = wrapi(b + ST8[o - 1][1], 16);
                        c = wrapi(c + ST8[o - 1][2], 16);
                        e = wrapi(e + ST8[o - 1][3], 64);
                    }
                    base = st1 + (size_t)(((a * 16 + b) * 16 + c) * 64 + e) * 64;
                } else {
                    int a = (int)(p0 * 63.0f), b = (int)(p1 * 63.0f),
                        c = (int)(p2 * 31.0f), e = (int)(tt * 15.0f);
                    if (o > 0) {
                        a = wrapi(a + ST8[o - 1][0], 64);
                        b = wrapi(b + ST8[o - 1][1], 64);
                        c = wrapi(c + ST8[o - 1][2], 32);
                        e = wrapi(e + ST8[o - 1][3], 16);
                    }
                    base = st2 + (size_t)(((a * 64 + b) * 32 + c) * 16 + e) * 8;
                }
            } else {
                int a = (int)(p0 * 3.0f), b = (int)(p1 * 3.0f),
                    c = (int)(p2 * 3.0f), e = (int)(tt * 65535.0f);
                base = tf + (size_t)(((a * 4 + b) * 4 + c) * 65536 + e) * 8;
            }
            segp[s] = base;
        }
        __syncthreads();

        float4 v0[2], v1[2];
        float ss = 0.f;
#pragma unroll
        for (int gi = 0; gi < 2; gi++) {
            int g = threadIdx.x + gi * 256;
            if (g < NGRP) {
                int f0 = g * 8;
                int seg, off;
                if (f0 < 112)       { seg = f0 >> 4;                 off = f0 & 15; }
                else if (f0 < 336)  { int q = f0 - 112;  seg = 7  + (q >> 5); off = q & 31; }
                else if (f0 < 784)  { int q = f0 - 336;  seg = 14 + (q >> 6); off = q & 63; }
                else if (f0 < 1680) { int q = f0 - 784;  seg = 21 + (q >> 7); off = q & 127; }
                else if (f0 < 2256) { int q = f0 - 1680; seg = 28 + (q >> 6); off = q & 63; }
                else if (f0 < 2328) { int q = f0 - 2256; seg = 37 + (q >> 3); off = q & 7; }
                else                { seg = 46;                      off = f0 - 2328; }
                const float* sp = segp[seg] + off;
                float4 a = *(const float4*)sp;
                float4 b = *(const float4*)(sp + 4);
                v0[gi] = a; v1[gi] = b;
                ss += a.x * a.x + a.y * a.y + a.z * a.z + a.w * a.w
                    + b.x * b.x + b.y * b.y + b.z * b.z + b.w * b.w;
            }
        }
        red[threadIdx.x] = ss;
        __syncthreads();
        for (int w = 128; w > 0; w >>= 1) {
            if (threadIdx.x < w) red[threadIdx.x] += red[threadIdx.x + w];
            __syncthreads();
        }
        float rms = sqrtf(red[0] / (float)TOTAL);
        float sc = 1.0f / (rms + 1e-8f);
        __nv_bfloat16* orow = g_Abf + (size_t)i * AW1;
#pragma unroll
        for (int gi = 0; gi < 2; gi++) {
            int g = threadIdx.x + gi * 256;
            if (g < NGRP) {
                int f0 = g * 8;
                float4 n0 = *(const float4*)&vn1[f0];
                float4 n1 = *(const float4*)&vn1[f0 + 4];
                float v[8] = { v0[gi].x * n0.x * sc, v0[gi].y * n0.y * sc,
                               v0[gi].z * n0.z * sc, v0[gi].w * n0.w * sc,
                               v1[gi].x * n1.x * sc, v1[gi].y * n1.y * sc,
                               v1[gi].z * n1.z * sc, v1[gi].w * n1.w * sc };
                uint32_t hi[4], lo[4];
#pragma unroll
                for (int j = 0; j < 4; j++) {
                    __nv_bfloat16 h0 = __float2bfloat16(v[2 * j]);
                    __nv_bfloat16 h1 = __float2bfloat16(v[2 * j + 1]);
                    __nv_bfloat16 l0 = __float2bfloat16(v[2 * j] - __bfloat162float(h0));
                    __nv_bfloat16 l1 = __float2bfloat16(v[2 * j + 1] - __bfloat162float(h1));
                    hi[j] = (uint32_t)(*(unsigned short*)&h0) | ((uint32_t)(*(unsigned short*)&h1) << 16);
                    lo[j] = (uint32_t)(*(unsigned short*)&l0) | ((uint32_t)(*(unsigned short*)&l1) << 16);
                }
                int blk = f0 >> 5, pos = f0 & 31;
                *(uint4*)(orow + blk * 64 + pos)      = make_uint4(hi[0], hi[1], hi[2], hi[3]);
                *(uint4*)(orow + blk * 64 + 32 + pos) = make_uint4(lo[0], lo[1], lo[2], lo[3]);
            }
        }
    } else if (bid < NPTS + CWBLK) {
        // -------- convW: permuted transpose + split vw1 -> g_WT --------
        int b2 = bid - NPTS;
        int n0 = (b2 % 152) * 32, k0 = (b2 / 152) * 32;
        int tx = threadIdx.x & 31, ty = threadIdx.x >> 5;   // 32 x 8
        int tile = n0 >> 8, half = (n0 >> 7) & 1;
        int f0 = tile * 128 + (n0 & 127);
#pragma unroll
        for (int ii = 0; ii < 4; ii++) {
            int r = ty + ii * 8;
            int k = k0 + r;
            int f = f0 + tx;
            float v = 0.f;
            if (f < TOTAL && k < TOTAL)
                v = vw1[(size_t)k * TWOTOTAL + half * TOTAL + f];
            sh[r][tx] = v;
        }
        __syncthreads();
#pragma unroll
        for (int ii = 0; ii < 4; ii++) {
            int r = ty + ii * 8;
            int n = n0 + r;
            float v = sh[tx][r];
            __nv_bfloat16 h = __float2bfloat16(v);
            float hf = __bfloat162float(h);
            __nv_bfloat16 l = __float2bfloat16(v - hf);
            size_t base = (size_t)n * WTS + (size_t)(k0 * 2);
            g_WT[base + tx] = h;
            g_WT[base + 32 + tx] = l;
        }
    } else {
        // -------- convW2: (vn2 * vw2)^T split -> g_WT2 --------
        int idx = (bid - NPTS - CWBLK) * 256 + threadIdx.x;
        if (idx < TOTAL * 64) {
            int k = idx >> 6, n = idx & 63;
            float v = vn2[k] * vw2[idx];
            __nv_bfloat16 h = __float2bfloat16(v);
            float hf = __bfloat162float(h);
            __nv_bfloat16 l = __float2bfloat16(v - hf);
            size_t base = (size_t)n * VW + (size_t)((k >> 5) * 64);
            g_WT2[base + (k & 31)] = h;
            g_WT2[base + 32 + (k & 31)] = l;
        }
    }
}

// ---------------- K3: warp-specialized GEMM1 + fused geglu epilogue -----------
#define SMEM1 (1024 + 3 * 65536)

__global__ void __launch_bounds__(256, 1) k3_gemm1(const __nv_bfloat16* __restrict__ Abf,
                                                   const __nv_bfloat16* __restrict__ WT,
                                                   __nv_bfloat16* __restrict__ Vbf,
                                                   float* __restrict__ sspart)
{
    extern __shared__ char smem[];
    uint32_t sbase = smem_u32(smem);
    int tid = threadIdx.x;
    int wid = tid >> 5, lid = tid & 31;
    int tile = blockIdx.x;
    int bm = blockIdx.y * 256;
    int bn = tile * 256;

#if defined(__CUDA_ARCH_FEAT_SM103_ALL)
    const uint32_t TSLOT = sbase;
    const uint32_t FUL0 = sbase + 16, FUL1 = sbase + 24, FUL2 = sbase + 32;
    const uint32_t EMP0 = sbase + 40, EMP1 = sbase + 48, EMP2 = sbase + 56;
    const uint32_t DONE = sbase + 64;
    const uint32_t SDATA = sbase + 1024;

    if (wid == 0) TC_ALLOC(TSLOT, 512);
    if (tid == 0) {
        MBARRIER_INIT(FUL0, 224); MBARRIER_INIT(FUL1, 224); MBARRIER_INIT(FUL2, 224);
        MBARRIER_INIT(EMP0, 1);   MBARRIER_INIT(EMP1, 1);   MBARRIER_INIT(EMP2, 1);
        MBARRIER_INIT(DONE, 1);
    }
    __syncthreads();
    uint32_t tmem;
    asm volatile("ld.shared.b32 %0, [%1];" : "=r"(tmem) : "r"(TSLOT));

    const uint32_t IDESC = (1u << 4) | (1u << 7) | (1u << 10) | (32u << 17) | (8u << 24);

    if (wid >= 1) {
        int ptid = tid - 32;
        int pe0 = 1, pe1 = 1, pe2 = 1;
        const __nv_bfloat16* Abase = Abf + (size_t)bm * AW1;
        const __nv_bfloat16* Wbase = WT + (size_t)bn * WTS;
        for (int s = 0; s < NST1; s++) {
            int b = s % 3;
            uint32_t emp = (b == 0) ? EMP0 : (b == 1) ? EMP1 : EMP2;
            uint32_t ful = (b == 0) ? FUL0 : (b == 1) ? FUL1 : FUL2;
            if (b == 0)      { MBARRIER_WAIT_PARITY(emp, pe0); pe0 ^= 1; }
            else if (b == 1) { MBARRIER_WAIT_PARITY(emp, pe1); pe1 ^= 1; }
            else             { MBARRIER_WAIT_PARITY(emp, pe2); pe2 ^= 1; }
            uint32_t ab = SDATA + b * 65536;
            int ks = s * 64;
            for (int idx = ptid; idx < 4096; idx += 224) {
                int half = idx >> 11;
                int r = (idx & 2047) >> 3, c = idx & 7;
                uint32_t off = (uint32_t)(r * 128 + c * 16);
                uint32_t sw = off ^ ((off >> 3) & 0x70);
                if (half == 0)
                    CP_ASYNC16(ab + sw, (const void*)(Abase + (size_t)r * AW1 + ks + c * 8));
                else
                    CP_ASYNC16(ab + 32768 + sw, (const void*)(Wbase + (size_t)r * WTS + ks + c * 8));
            }
            CPA_MBAR_ARRIVE_NOINC(ful);
        }
    } else if (elect_one()) {
        int pf0 = 0, pf1 = 0, pf2 = 0;
        for (int s = 0; s < NST1; s++) {
            int b = s % 3;
            uint32_t ful = (b == 0) ? FUL0 : (b == 1) ? FUL1 : FUL2;
            uint32_t emp = (b == 0) ? EMP0 : (b == 1) ? EMP1 : EMP2;
            if (b == 0)      { MBARRIER_WAIT_PARITY(ful, pf0); pf0 ^= 1; }
            else if (b == 1) { MBARRIER_WAIT_PARITY(ful, pf1); pf1 ^= 1; }
            else             { MBARRIER_WAIT_PARITY(ful, pf2); pf2 ^= 1; }
            FENCE_ASYNC_SH();
            uint32_t ab = SDATA + b * 65536;
            uint64_t bd = make_desc(ab + 32768);
#pragma unroll
            for (int half = 0; half < 2; half++) {
                uint64_t ad = make_desc(ab + half * 16384);
                uint32_t dt = tmem + half * 256;
                uint32_t en0 = (s > 0) ? 1u : 0u;
                mma_f16_ss(dt, ad + 0, bd + 0, IDESC, en0);
                mma_f16_ss(dt, ad + 2, bd + 2, IDESC, 1u);
                mma_f16_ss(dt, ad + 4, bd + 0, IDESC, 1u);
                mma_f16_ss(dt, ad + 6, bd + 2, IDESC, 1u);
                mma_f16_ss(dt, ad + 0, bd + 4, IDESC, 1u);
                mma_f16_ss(dt, ad + 2, bd + 6, IDESC, 1u);
            }
            TC_COMMIT(emp);
        }
        TC_COMMIT(DONE);
    }
    MBARRIER_WAIT_PARITY(DONE, 0);
    TC_FENCE_AFTER();

    {
        int m = bm + ((wid < 4) ? 0 : 128) + (wid & 3) * 32 + lid;
        uint32_t dbase = tmem + ((wid < 4) ? 0 : 256);
        float ssacc = 0.f;
#pragma unroll
        for (int cp = 0; cp < 4; cp++) {
            uint32_t ra[32], rg[32];
            TC_LD_X32(ra, dbase + cp * 32);
            TC_LD_X32(rg, dbase + 128 + cp * 32);
            TC_WAIT_LD();
            uint32_t o[32];
#pragma unroll
            for (int j = 0; j < 32; j += 2) {
                float a0 = __uint_as_float(ra[j]),     a1 = __uint_as_float(ra[j + 1]);
                float g0 = __uint_as_float(rg[j]),     g1 = __uint_as_float(rg[j + 1]);
                float v0 = a0 * gelu_tanh(g0), v1 = a1 * gelu_tanh(g1);
                ssacc += v0 * v0 + v1 * v1;
                __nv_bfloat16 h0 = __float2bfloat16(v0);
                __nv_bfloat16 h1 = __float2bfloat16(v1);
                __nv_bfloat16 l0 = __float2bfloat16(v0 - __bfloat162float(h0));
                __nv_bfloat16 l1 = __float2bfloat16(v1 - __bfloat162float(h1));
                unsigned short uh0 = *(unsigned short*)&h0, uh1 = *(unsigned short*)&h1;
                unsigned short ul0 = *(unsigned short*)&l0, ul1 = *(unsigned short*)&l1;
                o[j >> 1]        = (uint32_t)uh0 | ((uint32_t)uh1 << 16);
                o[16 + (j >> 1)] = (uint32_t)ul0 | ((uint32_t)ul1 << 16);
            }
            int fb = tile * 4 + cp;
            uint4* dst = (uint4*)(Vbf + (size_t)m * VW + fb * 64);
#pragma unroll
            for (int q = 0; q < 8; q++)
                dst[q] = make_uint4(o[4 * q], o[4 * q + 1], o[4 * q + 2], o[4 * q + 3]);
        }
        sspart[(size_t)m * NTILES + tile] = ssacc;
    }
    __syncthreads();
    if (wid == 0) {
        TC_RELINQ();
        TC_DEALLOC(tmem, 512);
    }
#else
    // ---- FFMA fallback (generic pass; never selected on sm_103a) ----
    float* Da   = (float*)smem;
    float* As   = Da + 128 * 128;
    float* Bs   = As + 16 * 128;
    float* ssrd = Bs + 16 * 128;
    int tx = tid % 16, ty = tid / 16;
    for (int pass = 0; pass < 2; pass++) {
        int pm = bm + pass * 128;
        for (int half = 0; half < 2; half++) {
            int pn = bn + half * 128;
            float acc[8][8];
#pragma unroll
            for (int a = 0; a < 8; a++)
#pragma unroll
                for (int b = 0; b < 8; b++) acc[a][b] = 0.f;
            for (int k0 = 0; k0 < KPAD1; k0 += 16) {
                __syncthreads();
                for (int idx = tid; idx < 2048; idx += 256) {
                    int row = idx >> 4, kk = idx & 15;
                    int k = k0 + kk;
                    size_t pb = (size_t)(k >> 5) * 64 + (k & 31);
                    const __nv_bfloat16* ar = Abf + (size_t)(pm + row) * AW1 + pb;
                    const __nv_bfloat16* wr = WT + (size_t)(pn + row) * WTS + pb;
                    As[kk * 128 + row] = __bfloat162float(ar[0]) + __bfloat162float(ar[32]);
                    Bs[kk * 128 + row] = __bfloat162float(wr[0]) + __bfloat162float(wr[32]);
                }
                __syncthreads();
#pragma unroll
                for (int k = 0; k < 16; k++) {
                    float af[8], bf[8];
#pragma unroll
                    for (int a = 0; a < 8; a++) af[a] = As[k * 128 + ty * 8 + a];
#pragma unroll
                    for (int b = 0; b < 8; b++) bf[b] = Bs[k * 128 + tx * 8 + b];
#pragma unroll
                    for (int a = 0; a < 8; a++)
#pragma unroll
                        for (int b = 0; b < 8; b++) acc[a][b] += af[a] * bf[b];
                }
            }
            __syncthreads();
            if (half == 0) {
#pragma unroll
                for (int a = 0; a < 8; a++)
#pragma unroll
                    for (int b = 0; b < 8; b++)
                        Da[(ty * 8 + a) * 128 + tx * 8 + b] = acc[a][b];
            } else {
#pragma unroll
                for (int a = 0; a < 8; a++) {
                    int row = ty * 8 + a;
                    float ssp = 0.f;
#pragma unroll
                    for (int b = 0; b < 8; b++) {
                        int col = tx * 8 + b;
                        float av = Da[row * 128 + col];
                        float v = av * gelu_tanh(acc[a][b]);
                        ssp += v * v;
                        __nv_bfloat16 h = __float2bfloat16(v);
                        __nv_bfloat16 l = __float2bfloat16(v - __bfloat162float(h));
                        int f = tile * 128 + col;
                        int fb = f >> 5, pos = f & 31;
                        Vbf[(size_t)(pm + row) * VW + fb * 64 + pos] = h;
                        Vbf[(size_t)(pm + row) * VW + fb * 64 + 32 + pos] = l;
                    }
                    ssrd[row * 16 + tx] = ssp;
                }
            }
            __syncthreads();
        }
        if (tid < 128) {
            float sm = 0.f;
            for (int j = 0; j < 16; j++) sm += ssrd[tid * 16 + j];
            sspart[(size_t)(pm + tid) * NTILES + tile] = sm;
        }
        __syncthreads();
    }
#endif
}

// ---------------- K5: GEMM2 + fused row-scale + final linear -> out -----------
#define SMEM5 (1024 + 3 * 24576)
__global__ void __launch_bounds__(256, 1) k5_gemm2(const __nv_bfloat16* __restrict__ Vbf,
                                                   const __nv_bfloat16* __restrict__ WT2,
                                                   const float* __restrict__ t,
                                                   const float* __restrict__ fw,
                                                   const float* __restrict__ fbias,
                                                   const float* __restrict__ sspart,
                                                   float* __restrict__ out)
{
    extern __shared__ char smem[];
    uint32_t sbase = smem_u32(smem);
    int tid = threadIdx.x;
    int wid = tid >> 5, lid = tid & 31;
    int bm = blockIdx.x * 128;

#if defined(__CUDA_ARCH_FEAT_SM103_ALL)
    const uint32_t TSLOT = sbase;
    const uint32_t MB0 = sbase + 16;
    const uint32_t MB1 = sbase + 24;
    const uint32_t MB2 = sbase + 32;
    const uint32_t SDATA = sbase + 1024;

    if (wid == 0) TC_ALLOC(TSLOT, 64);
    if (tid == 0) { MBARRIER_INIT(MB0, 1); MBARRIER_INIT(MB1, 1); MBARRIER_INIT(MB2, 1); }
    __syncthreads();
    uint32_t tmem;
    asm volatile("ld.shared.b32 %0, [%1];" : "=r"(tmem) : "r"(TSLOT));

    const uint32_t IDESC = (1u << 4) | (1u << 7) | (1u << 10) | (8u << 17) | (8u << 24);

    auto load_stage = [&](int s) {
        int buf = s % 3;
        int ks = s * 64;
        uint32_t ab = SDATA + buf * 24576;
        uint32_t wb = ab + 16384;
        const __nv_bfloat16* Asrc = Vbf + (size_t)bm * VW + ks;
        const __nv_bfloat16* Wsrc = WT2 + ks;
#pragma unroll
        for (int j = 0; j < 4; j++) {
            int idx = tid + j * 256;
            int row = idx >> 3, c = idx & 7;
            uint32_t off = (uint32_t)(row * 128 + c * 16);
            uint32_t sw = off ^ ((off >> 3) & 0x70);
            CP_ASYNC16(ab + sw, (const void*)(Asrc + (size_t)row * VW + c * 8));
        }
#pragma unroll
        for (int j = 0; j < 2; j++) {
            int idx = tid + j * 256;
            int row = idx >> 3, c = idx & 7;
            uint32_t off = (uint32_t)(row * 128 + c * 16);
            uint32_t sw = off ^ ((off >> 3) & 0x70);
            CP_ASYNC16(wb + sw, (const void*)(Wsrc + (size_t)row * VW + c * 8));
        }
        CP_COMMIT();
    };

    int ph0 = 0, ph1 = 0, ph2 = 0;
    load_stage(0);
    load_stage(1);
    for (int s = 0; s < NST2; s++) {
        if (s + 2 < NST2) {
            if (s >= 1) {
                int b = (s - 1) % 3;
                if (b == 0)      { MBARRIER_WAIT_PARITY(MB0, ph0); ph0 ^= 1; }
                else if (b == 1) { MBARRIER_WAIT_PARITY(MB1, ph1); ph1 ^= 1; }
                else             { MBARRIER_WAIT_PARITY(MB2, ph2); ph2 ^= 1; }
            }
            load_stage(s + 2);
        }
        if (s + 2 < NST2)      CP_WAIT2();
        else if (s + 1 < NST2) CP_WAIT1();
        else                   CP_WAIT0();
        __syncthreads();
        FENCE_ASYNC_SH();
        if (wid == 0) {
            if (elect_one()) {
                int buf = s % 3;
                uint32_t ab = SDATA + buf * 24576;
                uint64_t ad = make_desc(ab);
                uint64_t bd = make_desc(ab + 16384);
                uint32_t en0 = (s > 0) ? 1u : 0u;
                mma_f16_ss(tmem, ad + 0, bd + 0, IDESC, en0);
                mma_f16_ss(tmem, ad + 2, bd + 2, IDESC, 1u);
                mma_f16_ss(tmem, ad + 4, bd + 0, IDESC, 1u);
                mma_f16_ss(tmem, ad + 6, bd + 2, IDESC, 1u);
                mma_f16_ss(tmem, ad + 0, bd + 4, IDESC, 1u);
                mma_f16_ss(tmem, ad + 2, bd + 6, IDESC, 1u);
                if (buf == 0) TC_COMMIT(MB0);
                else if (buf == 1) TC_COMMIT(MB1);
                else TC_COMMIT(MB2);
            }
        }
    }
    {
        int b = (NST2 - 1) % 3;   // 75 % 3 = 0
        if (b == 0)      MBARRIER_WAIT_PARITY(MB0, ph0);
        else if (b == 1) MBARRIER_WAIT_PARITY(MB1, ph1);
        else             MBARRIER_WAIT_PARITY(MB2, ph2);
    }
    TC_FENCE_AFTER();

    if (wid < 4) {
        int m = bm + wid * 32 + lid;
        uint32_t r[32], r2[32];
        TC_LD_X32(r, tmem);
        TC_LD_X32(r2, tmem + 32);
        TC_WAIT_LD();

        // fused k6: deferred rmsnorm scale + final linear
        const float* sp = sspart + (size_t)m * NTILES;
        float ss = 0.f;
#pragma unroll
        for (int q = 0; q < NTILES; q++) ss += sp[q];
        float sc = 1.0f / (sqrtf(ss / (float)TOTAL) + 1e-8f);

        float o0 = 0.f, o1 = 0.f, o2 = 0.f, o3 = 0.f;
#pragma unroll
        for (int q = 0; q < 32; q++) {
            float a = __uint_as_float(r[q]);
            o0 += a * fw[q * 4 + 0]; o1 += a * fw[q * 4 + 1];
            o2 += a * fw[q * 4 + 2]; o3 += a * fw[q * 4 + 3];
        }
#pragma unroll
        for (int q = 0; q < 32; q++) {
            float a = __uint_as_float(r2[q]);
            o0 += a * fw[(32 + q) * 4 + 0]; o1 += a * fw[(32 + q) * 4 + 1];
            o2 += a * fw[(32 + q) * 4 + 2]; o3 += a * fw[(32 + q) * 4 + 3];
        }
        o0 *= sc; o1 *= sc; o2 *= sc; o3 *= sc;
        o0 += fbias[0]; o1 += fbias[1]; o2 += fbias[2]; o3 += fbias[3];
        float p0 = g_p[m * 3 + 0], p1 = g_p[m * 3 + 1], p2 = g_p[m * 3 + 2];
        float tv = t[m];
        o0 += p0 * fw[256 + 0] + p1 * fw[260 + 0] + p2 * fw[264 + 0] + tv * fw[268 + 0];
        o1 += p0 * fw[256 + 1] + p1 * fw[260 + 1] + p2 * fw[264 + 1] + tv * fw[268 + 1];
        o2 += p0 * fw[256 + 2] + p1 * fw[260 + 2] + p2 * fw[264 + 2] + tv * fw[268 + 2];
        o3 += p0 * fw[256 + 3] + p1 * fw[260 + 3] + p2 * fw[264 + 3] + tv * fw[268 + 3];
        *(float4*)(out + (size_t)m * 4) = make_float4(o0, o1, o2, o3);
    }
    __syncthreads();
    if (wid == 0) {
        TC_RELINQ();
        TC_DEALLOC(tmem, 64);
    }
#else
    // ---- FFMA fallback (256 threads) ----
    float* Ds = (float*)smem;            // 64 x 64 staging
    float* Bs = Ds + 64 * 64;            // [16][64]
    for (int m0 = 0; m0 < 128; m0 += 64) {
        int mrow = (tid >> 2);
        int m = bm + m0 + mrow;
        int nq = (tid & 3) * 16;
        float acc[16];
#pragma unroll
        for (int a = 0; a < 16; a++) acc[a] = 0.f;
        for (int k0 = 0; k0 < KPAD2; k0 += 16) {
            __syncthreads();
            for (int idx = tid; idx < 1024; idx += 256) {
                int kk = idx >> 6, n = idx & 63;
                int k = k0 + kk;
                const __nv_bfloat16* wr = WT2 + (size_t)n * VW + (size_t)(k >> 5) * 64 + (k & 31);
                Bs[kk * 64 + n] = __bfloat162float(wr[0]) + __bfloat162float(wr[32]);
            }
            __syncthreads();
#pragma unroll
            for (int kk = 0; kk < 16; kk++) {
                int k = k0 + kk;
                const __nv_bfloat16* ar = Vbf + (size_t)m * VW + (size_t)(k >> 5) * 64 + (k & 31);
                float av = __bfloat162float(ar[0]) + __bfloat162float(ar[32]);
#pragma unroll
                for (int a = 0; a < 16; a++) acc[a] += av * Bs[kk * 64 + nq + a];
            }
        }
        __syncthreads();
        for (int a = 0; a < 16; a++) Ds[mrow * 64 + nq + a] = acc[a];
        __syncthreads();
        if (tid < 64) {
            int m2 = bm + m0 + tid;
            const float* sp = sspart + (size_t)m2 * NTILES;
            float ss = 0.f;
            for (int q = 0; q < NTILES; q++) ss += sp[q];
            float sc = 1.0f / (sqrtf(ss / (float)TOTAL) + 1e-8f);
            float o0 = 0.f, o1 = 0.f, o2 = 0.f, o3 = 0.f;
            for (int q = 0; q < 64; q++) {
                float a = Ds[tid * 64 + q];
                o0 += a * fw[q * 4 + 0]; o1 += a * fw[q * 4 + 1];
                o2 += a * fw[q * 4 + 2]; o3 += a * fw[q * 4 + 3];
            }
            o0 *= sc; o1 *= sc; o2 *= sc; o3 *= sc;
            o0 += fbias[0]; o1 += fbias[1]; o2 += fbias[2]; o3 += fbias[3];
            float p0 = g_p[m2 * 3 + 0], p1 = g_p[m2 * 3 + 1], p2 = g_p[m2 * 3 + 2];
            float tv = t[m2];
            o0 += p0 * fw[256 + 0] + p1 * fw[260 + 0] + p2 * fw[264 + 0] + tv * fw[268 + 0];
            o1 += p0 * fw[256 + 1] + p1 * fw[260 + 1] + p2 * fw[264 + 1] + tv * fw[268 + 1];
            o2 += p0 * fw[256 + 2] + p1 * fw[260 + 2] + p2 * fw[264 + 2] + tv * fw[268 + 2];
            o3 += p0 * fw[256 + 3] + p1 * fw[260 + 3] + p2 * fw[264 + 3] + tv * fw[268 + 3];
            *(float4*)(out + (size_t)m2 * 4) = make_float4(o0, o1, o2, o3);
        }
        __syncthreads();
    }
#endif
}

// ---------------- launcher ----------------------------------------------------
extern "C" void kernel_launch(void* const* d_in, const int* in_sizes, int n_in,
                              void* d_out, int out_size)
{
    const float* pos      = (const float*)d_in[0];
    const float* t        = (const float*)d_in[2];
    const float* table0   = (const float*)d_in[3];
    const float* table1   = (const float*)d_in[4];
    const float* table2   = (const float*)d_in[5];
    const float* table3   = (const float*)d_in[6];
    const float* st1      = (const float*)d_in[7];
    const float* st2      = (const float*)d_in[8];
    const float* tf       = (const float*)d_in[9];
    const float* sph_proj = (const float*)d_in[10];
    const float* tb1      = (const float*)d_in[11];
    const float* tb2      = (const float*)d_in[12];
    const float* gn1      = (const float*)d_in[13];
    const float* gw1      = (const float*)d_in[14];
    const float* gn2      = (const float*)d_in[15];
    const float* gw2      = (const float*)d_in[16];
    const float* gn3      = (const float*)d_in[17];
    const float* gw3      = (const float*)d_in[18];
    const float* vn1      = (const float*)d_in[19];
    const float* vw1      = (const float*)d_in[20];
    const float* vn2      = (const float*)d_in[21];
    const float* vw2      = (const float*)d_in[22];
    const float* fw       = (const float*)d_in[23];
    const float* fb       = (const float*)d_in[24];
    float* out = (float*)d_out;

    cudaFuncSetAttribute(k3_gemm1, cudaFuncAttributeMaxDynamicSharedMemorySize, SMEM1);
    cudaFuncSetAttribute(k5_gemm2, cudaFuncAttributeMaxDynamicSharedMemorySize, SMEM5);

    k1_preamble<<<NPTS / 256, 256>>>(pos, t, sph_proj, tb1, tb2,
                                     gn1, gw1, gn2, gw2, gn3, gw3);

    k2m<<<NPTS + CWBLK + CW2BLK, 256>>>(t, table0, table1, table2, table3,
                                        st1, st2, tf, vn1, vw1, vw2, vn2);

    __nv_bfloat16* Abf; cudaGetSymbolAddress((void**)&Abf, g_Abf);
    __nv_bfloat16* Vbf; cudaGetSymbolAddress((void**)&Vbf, g_Vbf);
    __nv_bfloat16* WT;  cudaGetSymbolAddress((void**)&WT,  g_WT);
    __nv_bfloat16* WT2; cudaGetSymbolAddress((void**)&WT2, g_WT2);
    float* Sp;          cudaGetSymbolAddress((void**)&Sp,  g_sspart);

    dim3 g1(NTILES, NPTS / 256);          // (19, 128)
    k3_gemm1<<<g1, 256, SMEM1>>>(Abf, WT, Vbf, Sp);

    k5_gemm2<<<NPTS / 128, 256, SMEM5>>>(Vbf, WT2, t, fw, fb, Sp, out);
}

// round 11
// speedup vs baseline: 1.0088x; 1.0088x over previous
#include <cuda_runtime.h>
#include <cuda_bf16.h>
#include <math.h>
#include <stdint.h>

#define NPTS 32768
#define TOTAL 2336
#define KPAD1 2368         // GEMM1 K padded (74 blocks of 32)
#define NST1 74
#define KPAD2 2432         // GEMM2 K (76 blocks)
#define NST2 76
#define TWOTOTAL 4672
#define INNER 64
#define AW1 4736           // g_Abf row: 74 blocks x [hi32|lo32]
#define VW 4864            // g_Vbf / g_WT2 row: 76 blocks x [hi32|lo32]
#define WTS 4736           // g_WT row width (74 blocks)
#define WTROWS 4864        // permuted W1 rows (19 tiles x 256)
#define NTILES 19
#define NGRP 292           // TOTAL / 8
#define CWBLK (152 * 74)   // convW blocks
#define CW2BLK 584         // convW2 blocks (584*256 = 149504 = 2336*64)

// ---------------- scratch (static device memory; zero-initialized) -----------
__device__ float g_p[NPTS * 3];
__device__ __align__(128) __nv_bfloat16 g_Abf[(size_t)NPTS * AW1];
__device__ __align__(128) __nv_bfloat16 g_Vbf[(size_t)NPTS * VW];
__device__ __align__(128) __nv_bfloat16 g_WT[(size_t)WTROWS * WTS];
__device__ __align__(128) __nv_bfloat16 g_WT2[(size_t)64 * VW];
__device__ float g_sspart[(size_t)NPTS * NTILES];
__device__ float g_down[NPTS * INNER];     // used by FFMA fallback only

// ---------------- common helpers ---------------------------------------------
__device__ __forceinline__ uint32_t smem_u32(const void* p) {
    uint32_t a;
    asm("{ .reg .u64 t; cvta.to.shared.u64 t, %1; cvt.u32.u64 %0, t; }" : "=r"(a) : "l"(p));
    return a;
}
__device__ __forceinline__ float sigmoidf_(float x) { return 1.0f / (1.0f + expf(-x)); }
__device__ __forceinline__ float gelu_tanh(float x) {
    float x3 = x * x * x;
    return 0.5f * x * (1.0f + tanhf(0.7978845608028654f * (x + 0.044715f * x3)));
}
__device__ __forceinline__ int wrapi(int v, int d) {
    if (v < 0) v += d; else if (v >= d) v -= d; return v;
}
__device__ const int FACE3[6][3] = {{1,0,0},{-1,0,0},{0,1,0},{0,-1,0},{0,0,1},{0,0,-1}};
__device__ const int ST8[8][4]   = {{1,0,0,0},{-1,0,0,0},{0,1,0,0},{0,-1,0,0},
                                    {0,0,1,0},{0,0,-1,0},{0,0,0,1},{0,0,0,-1}};

// cp.async helpers (baseline PTX)
#define CP_ASYNC16(smem, gmem) \
    asm volatile("cp.async.cg.shared.global [%0], [%1], 16;" :: "r"(smem), "l"(gmem) : "memory")
#define CP_COMMIT() asm volatile("cp.async.commit_group;" ::: "memory")
#define CP_WAIT2()  asm volatile("cp.async.wait_group 2;" ::: "memory")
#define CP_WAIT1()  asm volatile("cp.async.wait_group 1;" ::: "memory")
#define CP_WAIT0()  asm volatile("cp.async.wait_group 0;" ::: "memory")

#if defined(__CUDA_ARCH_FEAT_SM103_ALL)
// ---------------- tcgen05 helpers (sm_103a pass only) -------------------------
__device__ __forceinline__ uint32_t elect_one() {
    uint32_t p;
    asm volatile("{ .reg .pred p; elect.sync _|p, 0xFFFFFFFF; selp.b32 %0,1,0,p; }" : "=r"(p));
    return p;
}
#define MBARRIER_INIT(addr, cnt) \
    asm volatile("mbarrier.init.shared.b64 [%0], %1;" :: "r"(addr), "r"(cnt) : "memory")
#define MBARRIER_WAIT_PARITY(addr, parity) do { \
    uint32_t _m = (addr); uint32_t _p = (parity); uint32_t _d; \
    asm volatile("{ .reg .pred p; mbarrier.try_wait.parity.acquire.cta.shared::cta.b64 p, [%1], %2; selp.b32 %0,1,0,p; }" \
        : "=r"(_d) : "r"(_m), "r"(_p) : "memory"); \
    if (!_d) { \
        asm volatile("{ .reg .pred P1; WL_%=: mbarrier.try_wait.parity.acquire.cta.shared::cta.b64 P1, [%0], %1, 0x989680; @P1 bra.uni WD_%=; bra.uni WL_%=; WD_%=: }" \
            :: "r"(_m), "r"(_p) : "memory"); \
    } } while (0)
#define CPA_MBAR_ARRIVE_NOINC(mbar) \
    asm volatile("cp.async.mbarrier.arrive.noinc.shared::cta.b64 [%0];" :: "r"(mbar) : "memory")
#define TC_ALLOC(slot, n)  asm volatile("tcgen05.alloc.cta_group::1.sync.aligned.shared::cta.b32 [%0], %1;" :: "r"(slot), "r"(n) : "memory")
#define TC_DEALLOC(t, n)   asm volatile("tcgen05.dealloc.cta_group::1.sync.aligned.b32 %0, %1;" :: "r"(t), "r"(n))
#define TC_RELINQ()        asm volatile("tcgen05.relinquish_alloc_permit.cta_group::1.sync.aligned;")
#define TC_COMMIT(mbar)    asm volatile("tcgen05.commit.cta_group::1.mbarrier::arrive::one.shared::cluster.b64 [%0];" :: "r"(mbar) : "memory")
#define TC_WAIT_LD()       asm volatile("tcgen05.wait::ld.sync.aligned;" ::: "memory")
#define TC_FENCE_AFTER()   asm volatile("tcgen05.fence::after_thread_sync;" ::: "memory")
#define FENCE_ASYNC_SH()   asm volatile("fence.proxy.async.shared::cta;" ::: "memory")
#define TC_LD_X32(r, addr) \
    asm volatile("tcgen05.ld.sync.aligned.32x32b.x32.b32 " \
        "{%0,%1,%2,%3,%4,%5,%6,%7,%8,%9,%10,%11,%12,%13,%14,%15," \
        "%16,%17,%18,%19,%20,%21,%22,%23,%24,%25,%26,%27,%28,%29,%30,%31}, [%32];" \
        : "=r"((r)[0]),"=r"((r)[1]),"=r"((r)[2]),"=r"((r)[3]),"=r"((r)[4]),"=r"((r)[5]),"=r"((r)[6]),"=r"((r)[7]), \
          "=r"((r)[8]),"=r"((r)[9]),"=r"((r)[10]),"=r"((r)[11]),"=r"((r)[12]),"=r"((r)[13]),"=r"((r)[14]),"=r"((r)[15]), \
          "=r"((r)[16]),"=r"((r)[17]),"=r"((r)[18]),"=r"((r)[19]),"=r"((r)[20]),"=r"((r)[21]),"=r"((r)[22]),"=r"((r)[23]), \
          "=r"((r)[24]),"=r"((r)[25]),"=r"((r)[26]),"=r"((r)[27]),"=r"((r)[28]),"=r"((r)[29]),"=r"((r)[30]),"=r"((r)[31]) \
        : "r"(addr))
static constexpr uint64_t SMEM_DESC_BASE =
    (uint64_t(2) << 61) | (uint64_t(1) << 46) | (uint64_t(64) << 32) | (uint64_t(1) << 16);
__device__ __forceinline__ uint64_t make_desc(uint32_t addr) {
    return SMEM_DESC_BASE | ((uint64_t)(addr >> 4) & 0x3FFF);
}
__device__ __forceinline__ void mma_f16_ss(uint32_t d, uint64_t a, uint64_t b,
                                           uint32_t idesc, uint32_t en) {
    asm volatile("{ .reg .pred p; setp.ne.u32 p, %4, 0;"
                 "tcgen05.mma.cta_group::1.kind::f16 [%0], %1, %2, %3, {%5,%5,%5,%5}, p; }"
                 :: "r"(d), "l"(a), "l"(b), "r"(idesc), "r"(en), "r"(0u) : "memory");
}
#endif

// ---------------- K1: per-point preamble MLP -> p ----------------------------
__global__ void k1_preamble(const float* __restrict__ pos, const float* __restrict__ t,
                            const float* __restrict__ sph_proj,
                            const float* __restrict__ tb1, const float* __restrict__ tb2,
                            const float* __restrict__ gn1, const float* __restrict__ gw1,
                            const float* __restrict__ gn2, const float* __restrict__ gw2,
                            const float* __restrict__ gn3, const float* __restrict__ gw3)
{
    int i = blockIdx.x * blockDim.x + threadIdx.x;
    if (i >= NPTS) return;

    float x = pos[i * 3 + 0], y = pos[i * 3 + 1], z = pos[i * 3 + 2];
    float rho = sqrtf(x * x + y * y + z * z);
    float phi = atan2f(y, x);
    float cz = z / rho;
    cz = fminf(1.0f, fmaxf(-1.0f, cz));
    float theta = acosf(cz);

    float h[12];
#pragma unroll
    for (int j = 0; j < 8; j++)
        h[j] = rho * sph_proj[j] + phi * sph_proj[8 + j] + theta * sph_proj[16 + j];
    float tv = t[i];
    float ct = cosf(tv + tb1[0]);
    float st = sinf(tv + tb2[0]);
    h[8] = ct; h[9] = st;
    h[10] = ct * sigmoidf_(ct);
    h[11] = st * sigmoidf_(st);

    float ss = 0.f;
#pragma unroll
    for (int j = 0; j < 12; j++) ss += h[j] * h[j];
    float sc = 1.0f / (sqrtf(ss / 12.0f) + 1e-8f);
    float hn[12];
#pragma unroll
    for (int j = 0; j < 12; j++) hn[j] = gn1[j] * h[j] * sc;
    float y1[32];
#pragma unroll
    for (int j = 0; j < 32; j++) y1[j] = 0.f;
#pragma unroll
    for (int r = 0; r < 12; r++) {
        float a = hn[r];
#pragma unroll
        for (int j = 0; j < 32; j++) y1[j] += a * gw1[r * 32 + j];
    }
    float h2[16];
#pragma unroll
    for (int k = 0; k < 16; k++) h2[k] = y1[k] * gelu_tanh(y1[16 + k]);

    ss = 0.f;
#pragma unroll
    for (int j = 0; j < 16; j++) ss += h2[j] * h2[j];
    sc = 1.0f / (sqrtf(ss / 16.0f) + 1e-8f);
    float hn2[16];
#pragma unroll
    for (int j = 0; j < 16; j++) hn2[j] = gn2[j] * h2[j] * sc;
    float y2[32];
#pragma unroll
    for (int j = 0; j < 32; j++) y2[j] = 0.f;
#pragma unroll
    for (int r = 0; r < 16; r++) {
        float a = hn2[r];
#pragma unroll
        for (int j = 0; j < 32; j++) y2[j] += a * gw2[r * 32 + j];
    }
    float h3[16];
#pragma unroll
    for (int k = 0; k < 16; k++) h3[k] = y2[k] * gelu_tanh(y2[16 + k]);

    ss = 0.f;
#pragma unroll
    for (int j = 0; j < 16; j++) ss += h3[j] * h3[j];
    sc = 1.0f / (sqrtf(ss / 16.0f) + 1e-8f);
    float z3[3] = {0.f, 0.f, 0.f};
#pragma unroll
    for (int r = 0; r < 16; r++) {
        float a = gn3[r] * h3[r] * sc;
#pragma unroll
        for (int j = 0; j < 3; j++) z3[j] += a * gw3[r * 3 + j];
    }
    g_p[i * 3 + 0] = sigmoidf_(z3[0]);
    g_p[i * 3 + 1] = sigmoidf_(z3[1]);
    g_p[i * 3 + 2] = sigmoidf_(z3[2]);
}

// ---------------- K2m: fused gather + convW + convW2 (branch on blockIdx) -----
__global__ void __launch_bounds__(256) k2m(const float* __restrict__ t,
                          const float* __restrict__ table0, const float* __restrict__ table1,
                          const float* __restrict__ table2, const float* __restrict__ table3,
                          const float* __restrict__ st1, const float* __restrict__ st2,
                          const float* __restrict__ tf, const float* __restrict__ vn1,
                          const float* __restrict__ vw1, const float* __restrict__ vw2,
                          const float* __restrict__ vn2)
{
    int bid = blockIdx.x;
    __shared__ const float* segp[47];
    __shared__ __align__(16) float red[256];
    __shared__ float sh[32][33];

    if (bid < NPTS) {
        // -------- gather + rmsnorm(vn1) -> hi/lo bf16 (256 threads) --------
        int i = bid;
        float p0 = g_p[i * 3 + 0], p1 = g_p[i * 3 + 1], p2 = g_p[i * 3 + 2];
        float tt = t[i];

        int s = threadIdx.x;
        if (s < 47) {
            const float* base = nullptr;
            if (s < 28) {
                int tb = s / 7;
                int o = s % 7;
                int d, F; const float* T;
                if (tb == 0)      { d = 128; F = 16;  T = table0; }
                else if (tb == 1) { d = 64;  F = 32;  T = table1; }
                else if (tb == 2) { d = 32;  F = 64;  T = table2; }
                else              { d = 16;  F = 128; T = table3; }
                int ix = (int)(p0 * (float)(d - 1));
                int iy = (int)(p1 * (float)(d - 1));
                int iz = (int)(p2 * (float)(d - 1));
                if (o > 0) {
                    ix = wrapi(ix + FACE3[o - 1][0], d);
                    iy = wrapi(iy + FACE3[o - 1][1], d);
                    iz = wrapi(iz + FACE3[o - 1][2], d);
                }
                base = T + (size_t)((ix * d + iy) * d + iz) * F;
            } else if (s < 46) {
                int grp = (s - 28) / 9;
                int o = (s - 28) % 9;
                if (grp == 0) {
                    int a = (int)(p0 * 15.0f), b = (int)(p1 * 15.0f),
                        c = (int)(p2 * 15.0f), e = (int)(tt * 63.0f);
                    if (o > 0) {
                        a = wrapi(a + ST8[o - 1][0], 16);
                        b = wrapi(b + ST8[o - 1][1], 16);
                        c = wrapi(c + ST8[o - 1][2], 16);
                        e = wrapi(e + ST8[o - 1][3], 64);
                    }
                    base = st1 + (size_t)(((a * 16 + b) * 16 + c) * 64 + e) * 64;
                } else {
                    int a = (int)(p0 * 63.0f), b = (int)(p1 * 63.0f),
                        c = (int)(p2 * 31.0f), e = (int)(tt * 15.0f);
                    if (o > 0) {
                        a = wrapi(a + ST8[o - 1][0], 64);
                        b = wrapi(b + ST8[o - 1][1], 64);
                        c = wrapi(c + ST8[o - 1][2], 32);
                        e = wrapi(e + ST8[o - 1][3], 16);
                    }
                    base = st2 + (size_t)(((a * 64 + b) * 32 + c) * 16 + e) * 8;
                }
            } else {
                int a = (int)(p0 * 3.0f), b = (int)(p1 * 3.0f),
                    c = (int)(p2 * 3.0f), e = (int)(tt * 65535.0f);
                base = tf + (size_t)(((a * 4 + b) * 4 + c) * 65536 + e) * 8;
            }
            segp[s] = base;
        }
        __syncthreads();

        float4 v0[2], v1[2];
        float ss = 0.f;
#pragma unroll
        for (int gi = 0; gi < 2; gi++) {
            int g = threadIdx.x + gi * 256;
            if (g < NGRP) {
                int f0 = g * 8;
                int seg, off;
                if (f0 < 112)       { seg = f0 >> 4;                 off = f0 & 15; }
                else if (f0 < 336)  { int q = f0 - 112;  seg = 7  + (q >> 5); off = q & 31; }
                else if (f0 < 784)  { int q = f0 - 336;  seg = 14 + (q >> 6); off = q & 63; }
                else if (f0 < 1680) { int q = f0 - 784;  seg = 21 + (q >> 7); off = q & 127; }
                else if (f0 < 2256) { int q = f0 - 1680; seg = 28 + (q >> 6); off = q & 63; }
                else if (f0 < 2328) { int q = f0 - 2256; seg = 37 + (q >> 3); off = q & 7; }
                else                { seg = 46;                      off = f0 - 2328; }
                const float* sp = segp[seg] + off;
                float4 a = *(const float4*)sp;
                float4 b = *(const float4*)(sp + 4);
                v0[gi] = a; v1[gi] = b;
                ss += a.x * a.x + a.y * a.y + a.z * a.z + a.w * a.w
                    + b.x * b.x + b.y * b.y + b.z * b.z + b.w * b.w;
            }
        }
        red[threadIdx.x] = ss;
        __syncthreads();
        for (int w = 128; w > 0; w >>= 1) {
            if (threadIdx.x < w) red[threadIdx.x] += red[threadIdx.x + w];
            __syncthreads();
        }
        float rms = sqrtf(red[0] / (float)TOTAL);
        float sc = 1.0f / (rms + 1e-8f);
        __nv_bfloat16* orow = g_Abf + (size_t)i * AW1;
#pragma unroll
        for (int gi = 0; gi < 2; gi++) {
            int g = threadIdx.x + gi * 256;
            if (g < NGRP) {
                int f0 = g * 8;
                float4 n0 = *(const float4*)&vn1[f0];
                float4 n1 = *(const float4*)&vn1[f0 + 4];
                float v[8] = { v0[gi].x * n0.x * sc, v0[gi].y * n0.y * sc,
                               v0[gi].z * n0.z * sc, v0[gi].w * n0.w * sc,
                               v1[gi].x * n1.x * sc, v1[gi].y * n1.y * sc,
                               v1[gi].z * n1.z * sc, v1[gi].w * n1.w * sc };
                uint32_t hi[4], lo[4];
#pragma unroll
                for (int j = 0; j < 4; j++) {
                    __nv_bfloat16 h0 = __float2bfloat16(v[2 * j]);
                    __nv_bfloat16 h1 = __float2bfloat16(v[2 * j + 1]);
                    __nv_bfloat16 l0 = __float2bfloat16(v[2 * j] - __bfloat162float(h0));
                    __nv_bfloat16 l1 = __float2bfloat16(v[2 * j + 1] - __bfloat162float(h1));
                    hi[j] = (uint32_t)(*(unsigned short*)&h0) | ((uint32_t)(*(unsigned short*)&h1) << 16);
                    lo[j] = (uint32_t)(*(unsigned short*)&l0) | ((uint32_t)(*(unsigned short*)&l1) << 16);
                }
                int blk = f0 >> 5, pos = f0 & 31;
                *(uint4*)(orow + blk * 64 + pos)      = make_uint4(hi[0], hi[1], hi[2], hi[3]);
                *(uint4*)(orow + blk * 64 + 32 + pos) = make_uint4(lo[0], lo[1], lo[2], lo[3]);
            }
        }
    } else if (bid < NPTS + CWBLK) {
        // -------- convW: permuted transpose + split vw1 -> g_WT --------
        int b2 = bid - NPTS;
        int n0 = (b2 % 152) * 32, k0 = (b2 / 152) * 32;
        int tx = threadIdx.x & 31, ty = threadIdx.x >> 5;   // 32 x 8
        int tile = n0 >> 8, half = (n0 >> 7) & 1;
        int f0 = tile * 128 + (n0 & 127);
#pragma unroll
        for (int ii = 0; ii < 4; ii++) {
            int r = ty + ii * 8;
            int k = k0 + r;
            int f = f0 + tx;
            float v = 0.f;
            if (f < TOTAL && k < TOTAL)
                v = vw1[(size_t)k * TWOTOTAL + half * TOTAL + f];
            sh[r][tx] = v;
        }
        __syncthreads();
#pragma unroll
        for (int ii = 0; ii < 4; ii++) {
            int r = ty + ii * 8;
            int n = n0 + r;
            float v = sh[tx][r];
            __nv_bfloat16 h = __float2bfloat16(v);
            float hf = __bfloat162float(h);
            __nv_bfloat16 l = __float2bfloat16(v - hf);
            size_t base = (size_t)n * WTS + (size_t)(k0 * 2);
            g_WT[base + tx] = h;
            g_WT[base + 32 + tx] = l;
        }
    } else {
        // -------- convW2: (vn2 * vw2)^T split -> g_WT2 --------
        int idx = (bid - NPTS - CWBLK) * 256 + threadIdx.x;
        if (idx < TOTAL * 64) {
            int k = idx >> 6, n = idx & 63;
            float v = vn2[k] * vw2[idx];
            __nv_bfloat16 h = __float2bfloat16(v);
            float hf = __bfloat162float(h);
            __nv_bfloat16 l = __float2bfloat16(v - hf);
            size_t base = (size_t)n * VW + (size_t)((k >> 5) * 64);
            g_WT2[base + (k & 31)] = h;
            g_WT2[base + 32 + (k & 31)] = l;
        }
    }
}

// ---------------- K3: warp-specialized GEMM1 + fused geglu epilogue -----------
#define SMEM1 (1024 + 3 * 65536)

__global__ void __launch_bounds__(256, 1) k3_gemm1(const __nv_bfloat16* __restrict__ Abf,
                                                   const __nv_bfloat16* __restrict__ WT,
                                                   __nv_bfloat16* __restrict__ Vbf,
                                                   float* __restrict__ sspart)
{
    extern __shared__ char smem[];
    uint32_t sbase = smem_u32(smem);
    int tid = threadIdx.x;
    int wid = tid >> 5, lid = tid & 31;
    int tile = blockIdx.x;
    int bm = blockIdx.y * 256;
    int bn = tile * 256;

#if defined(__CUDA_ARCH_FEAT_SM103_ALL)
    const uint32_t TSLOT = sbase;
    const uint32_t FUL0 = sbase + 16, FUL1 = sbase + 24, FUL2 = sbase + 32;
    const uint32_t EMP0 = sbase + 40, EMP1 = sbase + 48, EMP2 = sbase + 56;
    const uint32_t DONE = sbase + 64;
    const uint32_t SDATA = sbase + 1024;

    if (wid == 0) TC_ALLOC(TSLOT, 512);
    if (tid == 0) {
        MBARRIER_INIT(FUL0, 224); MBARRIER_INIT(FUL1, 224); MBARRIER_INIT(FUL2, 224);
        MBARRIER_INIT(EMP0, 1);   MBARRIER_INIT(EMP1, 1);   MBARRIER_INIT(EMP2, 1);
        MBARRIER_INIT(DONE, 1);
    }
    __syncthreads();
    uint32_t tmem;
    asm volatile("ld.shared.b32 %0, [%1];" : "=r"(tmem) : "r"(TSLOT));

    const uint32_t IDESC = (1u << 4) | (1u << 7) | (1u << 10) | (32u << 17) | (8u << 24);

    if (wid >= 1) {
        int ptid = tid - 32;
        int pe0 = 1, pe1 = 1, pe2 = 1;
        const __nv_bfloat16* Abase = Abf + (size_t)bm * AW1;
        const __nv_bfloat16* Wbase = WT + (size_t)bn * WTS;
        for (int s = 0; s < NST1; s++) {
            int b = s % 3;
            uint32_t emp = (b == 0) ? EMP0 : (b == 1) ? EMP1 : EMP2;
            uint32_t ful = (b == 0) ? FUL0 : (b == 1) ? FUL1 : FUL2;
            if (b == 0)      { MBARRIER_WAIT_PARITY(emp, pe0); pe0 ^= 1; }
            else if (b == 1) { MBARRIER_WAIT_PARITY(emp, pe1); pe1 ^= 1; }
            else             { MBARRIER_WAIT_PARITY(emp, pe2); pe2 ^= 1; }
            uint32_t ab = SDATA + b * 65536;
            int ks = s * 64;
            for (int idx = ptid; idx < 4096; idx += 224) {
                int half = idx >> 11;
                int r = (idx & 2047) >> 3, c = idx & 7;
                uint32_t off = (uint32_t)(r * 128 + c * 16);
                uint32_t sw = off ^ ((off >> 3) & 0x70);
                if (half == 0)
                    CP_ASYNC16(ab + sw, (const void*)(Abase + (size_t)r * AW1 + ks + c * 8));
                else
                    CP_ASYNC16(ab + 32768 + sw, (const void*)(Wbase + (size_t)r * WTS + ks + c * 8));
            }
            CPA_MBAR_ARRIVE_NOINC(ful);
        }
    } else if (elect_one()) {
        int pf0 = 0, pf1 = 0, pf2 = 0;
        for (int s = 0; s < NST1; s++) {
            int b = s % 3;
            uint32_t ful = (b == 0) ? FUL0 : (b == 1) ? FUL1 : FUL2;
            uint32_t emp = (b == 0) ? EMP0 : (b == 1) ? EMP1 : EMP2;
            if (b == 0)      { MBARRIER_WAIT_PARITY(ful, pf0); pf0 ^= 1; }
            else if (b == 1) { MBARRIER_WAIT_PARITY(ful, pf1); pf1 ^= 1; }
            else             { MBARRIER_WAIT_PARITY(ful, pf2); pf2 ^= 1; }
            FENCE_ASYNC_SH();
            uint32_t ab = SDATA + b * 65536;
            uint64_t bd = make_desc(ab + 32768);
#pragma unroll
            for (int half = 0; half < 2; half++) {
                uint64_t ad = make_desc(ab + half * 16384);
                uint32_t dt = tmem + half * 256;
                uint32_t en0 = (s > 0) ? 1u : 0u;
                mma_f16_ss(dt, ad + 0, bd + 0, IDESC, en0);
                mma_f16_ss(dt, ad + 2, bd + 2, IDESC, 1u);
                mma_f16_ss(dt, ad + 4, bd + 0, IDESC, 1u);
                mma_f16_ss(dt, ad + 6, bd + 2, IDESC, 1u);
                mma_f16_ss(dt, ad + 0, bd + 4, IDESC, 1u);
                mma_f16_ss(dt, ad + 2, bd + 6, IDESC, 1u);
            }
            TC_COMMIT(emp);
        }
        TC_COMMIT(DONE);
    }
    MBARRIER_WAIT_PARITY(DONE, 0);
    TC_FENCE_AFTER();

    {
        int m = bm + ((wid < 4) ? 0 : 128) + (wid & 3) * 32 + lid;
        uint32_t dbase = tmem + ((wid < 4) ? 0 : 256);
        float ssacc = 0.f;
#pragma unroll
        for (int cp = 0; cp < 4; cp++) {
            uint32_t ra[32], rg[32];
            TC_LD_X32(ra, dbase + cp * 32);
            TC_LD_X32(rg, dbase + 128 + cp * 32);
            TC_WAIT_LD();
            uint32_t o[32];
#pragma unroll
            for (int j = 0; j < 32; j += 2) {
                float a0 = __uint_as_float(ra[j]),     a1 = __uint_as_float(ra[j + 1]);
                float g0 = __uint_as_float(rg[j]),     g1 = __uint_as_float(rg[j + 1]);
                float v0 = a0 * gelu_tanh(g0), v1 = a1 * gelu_tanh(g1);
                ssacc += v0 * v0 + v1 * v1;
                __nv_bfloat16 h0 = __float2bfloat16(v0);
                __nv_bfloat16 h1 = __float2bfloat16(v1);
                __nv_bfloat16 l0 = __float2bfloat16(v0 - __bfloat162float(h0));
                __nv_bfloat16 l1 = __float2bfloat16(v1 - __bfloat162float(h1));
                unsigned short uh0 = *(unsigned short*)&h0, uh1 = *(unsigned short*)&h1;
                unsigned short ul0 = *(unsigned short*)&l0, ul1 = *(unsigned short*)&l1;
                o[j >> 1]        = (uint32_t)uh0 | ((uint32_t)uh1 << 16);
                o[16 + (j >> 1)] = (uint32_t)ul0 | ((uint32_t)ul1 << 16);
            }
            int fb = tile * 4 + cp;
            uint4* dst = (uint4*)(Vbf + (size_t)m * VW + fb * 64);
#pragma unroll
            for (int q = 0; q < 8; q++)
                dst[q] = make_uint4(o[4 * q], o[4 * q + 1], o[4 * q + 2], o[4 * q + 3]);
        }
        sspart[(size_t)m * NTILES + tile] = ssacc;
    }
    __syncthreads();
    if (wid == 0) {
        TC_RELINQ();
        TC_DEALLOC(tmem, 512);
    }
#else
    // ---- FFMA fallback (generic pass; never selected on sm_103a) ----
    float* Da   = (float*)smem;
    float* As   = Da + 128 * 128;
    float* Bs   = As + 16 * 128;
    float* ssrd = Bs + 16 * 128;
    int tx = tid % 16, ty = tid / 16;
    for (int pass = 0; pass < 2; pass++) {
        int pm = bm + pass * 128;
        for (int half = 0; half < 2; half++) {
            int pn = bn + half * 128;
            float acc[8][8];
#pragma unroll
            for (int a = 0; a < 8; a++)
#pragma unroll
                for (int b = 0; b < 8; b++) acc[a][b] = 0.f;
            for (int k0 = 0; k0 < KPAD1; k0 += 16) {
                __syncthreads();
                for (int idx = tid; idx < 2048; idx += 256) {
                    int row = idx >> 4, kk = idx & 15;
                    int k = k0 + kk;
                    size_t pb = (size_t)(k >> 5) * 64 + (k & 31);
                    const __nv_bfloat16* ar = Abf + (size_t)(pm + row) * AW1 + pb;
                    const __nv_bfloat16* wr = WT + (size_t)(pn + row) * WTS + pb;
                    As[kk * 128 + row] = __bfloat162float(ar[0]) + __bfloat162float(ar[32]);
                    Bs[kk * 128 + row] = __bfloat162float(wr[0]) + __bfloat162float(wr[32]);
                }
                __syncthreads();
#pragma unroll
                for (int k = 0; k < 16; k++) {
                    float af[8], bf[8];
#pragma unroll
                    for (int a = 0; a < 8; a++) af[a] = As[k * 128 + ty * 8 + a];
#pragma unroll
                    for (int b = 0; b < 8; b++) bf[b] = Bs[k * 128 + tx * 8 + b];
#pragma unroll
                    for (int a = 0; a < 8; a++)
#pragma unroll
                        for (int b = 0; b < 8; b++) acc[a][b] += af[a] * bf[b];
                }
            }
            __syncthreads();
            if (half == 0) {
#pragma unroll
                for (int a = 0; a < 8; a++)
#pragma unroll
                    for (int b = 0; b < 8; b++)
                        Da[(ty * 8 + a) * 128 + tx * 8 + b] = acc[a][b];
            } else {
#pragma unroll
                for (int a = 0; a < 8; a++) {
                    int row = ty * 8 + a;
                    float ssp = 0.f;
#pragma unroll
                    for (int b = 0; b < 8; b++) {
                        int col = tx * 8 + b;
                        float av = Da[row * 128 + col];
                        float v = av * gelu_tanh(acc[a][b]);
                        ssp += v * v;
                        __nv_bfloat16 h = __float2bfloat16(v);
                        __nv_bfloat16 l = __float2bfloat16(v - __bfloat162float(h));
                        int f = tile * 128 + col;
                        int fb = f >> 5, pos = f & 31;
                        Vbf[(size_t)(pm + row) * VW + fb * 64 + pos] = h;
                        Vbf[(size_t)(pm + row) * VW + fb * 64 + 32 + pos] = l;
                    }
                    ssrd[row * 16 + tx] = ssp;
                }
            }
            __syncthreads();
        }
        if (tid < 128) {
            float sm = 0.f;
            for (int j = 0; j < 16; j++) sm += ssrd[tid * 16 + j];
            sspart[(size_t)(pm + tid) * NTILES + tile] = sm;
        }
        __syncthreads();
    }
#endif
}

// ---------------- K5: GEMM2 + fused row-scale + final linear -> out -----------
#define SMEM5 (1024 + 3 * 24576)
__global__ void __launch_bounds__(256, 1) k5_gemm2(const __nv_bfloat16* __restrict__ Vbf,
                                                   const __nv_bfloat16* __restrict__ WT2,
                                                   const float* __restrict__ t,
                                                   const float* __restrict__ fw,
                                                   const float* __restrict__ fbias,
                                                   const float* __restrict__ sspart,
                                                   float* __restrict__ out)
{
    extern __shared__ char smem[];
    uint32_t sbase = smem_u32(smem);
    int tid = threadIdx.x;
    int wid = tid >> 5, lid = tid & 31;
    int bm = blockIdx.x * 128;

#if defined(__CUDA_ARCH_FEAT_SM103_ALL)
    const uint32_t TSLOT = sbase;
    const uint32_t MB0 = sbase + 16;
    const uint32_t MB1 = sbase + 24;
    const uint32_t MB2 = sbase + 32;
    const uint32_t SDATA = sbase + 1024;

    if (wid == 0) TC_ALLOC(TSLOT, 64);
    if (tid == 0) { MBARRIER_INIT(MB0, 1); MBARRIER_INIT(MB1, 1); MBARRIER_INIT(MB2, 1); }
    __syncthreads();
    uint32_t tmem;
    asm volatile("ld.shared.b32 %0, [%1];" : "=r"(tmem) : "r"(TSLOT));

    const uint32_t IDESC = (1u << 4) | (1u << 7) | (1u << 10) | (8u << 17) | (8u << 24);

    auto load_stage = [&](int s) {
        int buf = s % 3;
        int ks = s * 64;
        uint32_t ab = SDATA + buf * 24576;
        uint32_t wb = ab + 16384;
        const __nv_bfloat16* Asrc = Vbf + (size_t)bm * VW + ks;
        const __nv_bfloat16* Wsrc = WT2 + ks;
#pragma unroll
        for (int j = 0; j < 4; j++) {
            int idx = tid + j * 256;
            int row = idx >> 3, c = idx & 7;
            uint32_t off = (uint32_t)(row * 128 + c * 16);
            uint32_t sw = off ^ ((off >> 3) & 0x70);
            CP_ASYNC16(ab + sw, (const void*)(Asrc + (size_t)row * VW + c * 8));
        }
#pragma unroll
        for (int j = 0; j < 2; j++) {
            int idx = tid + j * 256;
            int row = idx >> 3, c = idx & 7;
            uint32_t off = (uint32_t)(row * 128 + c * 16);
            uint32_t sw = off ^ ((off >> 3) & 0x70);
            CP_ASYNC16(wb + sw, (const void*)(Wsrc + (size_t)row * VW + c * 8));
        }
        CP_COMMIT();
    };

    int ph0 = 0, ph1 = 0, ph2 = 0;
    load_stage(0);
    load_stage(1);
    for (int s = 0; s < NST2; s++) {
        if (s + 2 < NST2) {
            if (s >= 1) {
                int b = (s - 1) % 3;
                if (b == 0)      { MBARRIER_WAIT_PARITY(MB0, ph0); ph0 ^= 1; }
                else if (b == 1) { MBARRIER_WAIT_PARITY(MB1, ph1); ph1 ^= 1; }
                else             { MBARRIER_WAIT_PARITY(MB2, ph2); ph2 ^= 1; }
            }
            load_stage(s + 2);
        }
        if (s + 2 < NST2)      CP_WAIT2();
        else if (s + 1 < NST2) CP_WAIT1();
        else                   CP_WAIT0();
        __syncthreads();
        FENCE_ASYNC_SH();
        if (wid == 0) {
            if (elect_one()) {
                int buf = s % 3;
                uint32_t ab = SDATA + buf * 24576;
                uint64_t ad = make_desc(ab);
                uint64_t bd = make_desc(ab + 16384);
                uint32_t en0 = (s > 0) ? 1u : 0u;
                mma_f16_ss(tmem, ad + 0, bd + 0, IDESC, en0);
                mma_f16_ss(tmem, ad + 2, bd + 2, IDESC, 1u);
                mma_f16_ss(tmem, ad + 4, bd + 0, IDESC, 1u);
                mma_f16_ss(tmem, ad + 6, bd + 2, IDESC, 1u);
                mma_f16_ss(tmem, ad + 0, bd + 4, IDESC, 1u);
                mma_f16_ss(tmem, ad + 2, bd + 6, IDESC, 1u);
                if (buf == 0) TC_COMMIT(MB0);
                else if (buf == 1) TC_COMMIT(MB1);
                else TC_COMMIT(MB2);
            }
        }
    }
    {
        int b = (NST2 - 1) % 3;   // 75 % 3 = 0
        if (b == 0)      MBARRIER_WAIT_PARITY(MB0, ph0);
        else if (b == 1) MBARRIER_WAIT_PARITY(MB1, ph1);
        else             MBARRIER_WAIT_PARITY(MB2, ph2);
    }
    TC_FENCE_AFTER();

    if (wid < 4) {
        int m = bm + wid * 32 + lid;
        uint32_t r[32], r2[32];
        TC_LD_X32(r, tmem);
        TC_LD_X32(r2, tmem + 32);
        TC_WAIT_LD();

        // fused k6: deferred rmsnorm scale + final linear
        const float* sp = sspart + (size_t)m * NTILES;
        float ss = 0.f;
#pragma unroll
        for (int q = 0; q < NTILES; q++) ss += sp[q];
        float sc = 1.0f / (sqrtf(ss / (float)TOTAL) + 1e-8f);

        float o0 = 0.f, o1 = 0.f, o2 = 0.f, o3 = 0.f;
#pragma unroll
        for (int q = 0; q < 32; q++) {
            float a = __uint_as_float(r[q]);
            o0 += a * fw[q * 4 + 0]; o1 += a * fw[q * 4 + 1];
            o2 += a * fw[q * 4 + 2]; o3 += a * fw[q * 4 + 3];
        }
#pragma unroll
        for (int q = 0; q < 32; q++) {
            float a = __uint_as_float(r2[q]);
            o0 += a * fw[(32 + q) * 4 + 0]; o1 += a * fw[(32 + q) * 4 + 1];
            o2 += a * fw[(32 + q) * 4 + 2]; o3 += a * fw[(32 + q) * 4 + 3];
        }
        o0 *= sc; o1 *= sc; o2 *= sc; o3 *= sc;
        o0 += fbias[0]; o1 += fbias[1]; o2 += fbias[2]; o3 += fbias[3];
        float p0 = g_p[m * 3 + 0], p1 = g_p[m * 3 + 1], p2 = g_p[m * 3 + 2];
        float tv = t[m];
        o0 += p0 * fw[256 + 0] + p1 * fw[260 + 0] + p2 * fw[264 + 0] + tv * fw[268 + 0];
        o1 += p0 * fw[256 + 1] + p1 * fw[260 + 1] + p2 * fw[264 + 1] + tv * fw[268 + 1];
        o2 += p0 * fw[256 + 2] + p1 * fw[260 + 2] + p2 * fw[264 + 2] + tv * fw[268 + 2];
        o3 += p0 * fw[256 + 3] + p1 * fw[260 + 3] + p2 * fw[264 + 3] + tv * fw[268 + 3];
        *(float4*)(out + (size_t)m * 4) = make_float4(o0, o1, o2, o3);
    }
    __syncthreads();
    if (wid == 0) {
        TC_RELINQ();
        TC_DEALLOC(tmem, 64);
    }
#else
    // ---- FFMA fallback (256 threads) ----
    float* Ds = (float*)smem;            // 64 x 64 staging
    float* Bs = Ds + 64 * 64;            // [16][64]
    for (int m0 = 0; m0 < 128; m0 += 64) {
        int mrow = (tid >> 2);
        int m = bm + m0 + mrow;
        int nq = (tid & 3) * 16;
        float acc[16];
#pragma unroll
        for (int a = 0; a < 16; a++) acc[a] = 0.f;
        for (int k0 = 0; k0 < KPAD2; k0 += 16) {
            __syncthreads();
            for (int idx = tid; idx < 1024; idx += 256) {
                int kk = idx >> 6, n = idx & 63;
                int k = k0 + kk;
                const __nv_bfloat16* wr = WT2 + (size_t)n * VW + (size_t)(k >> 5) * 64 + (k & 31);
                Bs[kk * 64 + n] = __bfloat162float(wr[0]) + __bfloat162float(wr[32]);
            }
            __syncthreads();
#pragma unroll
            for (int kk = 0; kk < 16; kk++) {
                int k = k0 + kk;
                const __nv_bfloat16* ar = Vbf + (size_t)m * VW + (size_t)(k >> 5) * 64 + (k & 31);
                float av = __bfloat162float(ar[0]) + __bfloat162float(ar[32]);
#pragma unroll
                for (int a = 0; a < 16; a++) acc[a] += av * Bs[kk * 64 + nq + a];
            }
        }
        __syncthreads();
        for (int a = 0; a < 16; a++) Ds[mrow * 64 + nq + a] = acc[a];
        __syncthreads();
        if (tid < 64) {
            int m2 = bm + m0 + tid;
            const float* sp = sspart + (size_t)m2 * NTILES;
            float ss = 0.f;
            for (int q = 0; q < NTILES; q++) ss += sp[q];
            float sc = 1.0f / (sqrtf(ss / (float)TOTAL) + 1e-8f);
            float o0 = 0.f, o1 = 0.f, o2 = 0.f, o3 = 0.f;
            for (int q = 0; q < 64; q++) {
                float a = Ds[tid * 64 + q];
                o0 += a * fw[q * 4 + 0]; o1 += a * fw[q * 4 + 1];
                o2 += a * fw[q * 4 + 2]; o3 += a * fw[q * 4 + 3];
            }
            o0 *= sc; o1 *= sc; o2 *= sc; o3 *= sc;
            o0 += fbias[0]; o1 += fbias[1]; o2 += fbias[2]; o3 += fbias[3];
            float p0 = g_p[m2 * 3 + 0], p1 = g_p[m2 * 3 + 1], p2 = g_p[m2 * 3 + 2];
            float tv = t[m2];
            o0 += p0 * fw[256 + 0] + p1 * fw[260 + 0] + p2 * fw[264 + 0] + tv * fw[268 + 0];
            o1 += p0 * fw[256 + 1] + p1 * fw[260 + 1] + p2 * fw[264 + 1] + tv * fw[268 + 1];
            o2 += p0 * fw[256 + 2] + p1 * fw[260 + 2] + p2 * fw[264 + 2] + tv * fw[268 + 2];
            o3 += p0 * fw[256 + 3] + p1 * fw[260 + 3] + p2 * fw[264 + 3] + tv * fw[268 + 3];
            *(float4*)(out + (size_t)m2 * 4) = make_float4(o0, o1, o2, o3);
        }
        __syncthreads();
    }
#endif
}

// ---------------- launcher ----------------------------------------------------
extern "C" void kernel_launch(void* const* d_in, const int* in_sizes, int n_in,
                              void* d_out, int out_size)
{
    const float* pos      = (const float*)d_in[0];
    const float* t        = (const float*)d_in[2];
    const float* table0   = (const float*)d_in[3];
    const float* table1   = (const float*)d_in[4];
    const float* table2   = (const float*)d_in[5];
    const float* table3   = (const float*)d_in[6];
    const float* st1      = (const float*)d_in[7];
    const float* st2      = (const float*)d_in[8];
    const float* tf       = (const float*)d_in[9];
    const float* sph_proj = (const float*)d_in[10];
    const float* tb1      = (const float*)d_in[11];
    const float* tb2      = (const float*)d_in[12];
    const float* gn1      = (const float*)d_in[13];
    const float* gw1      = (const float*)d_in[14];
    const float* gn2      = (const float*)d_in[15];
    const float* gw2      = (const float*)d_in[16];
    const float* gn3      = (const float*)d_in[17];
    const float* gw3      = (const float*)d_in[18];
    const float* vn1      = (const float*)d_in[19];
    const float* vw1      = (const float*)d_in[20];
    const float* vn2      = (const float*)d_in[21];
    const float* vw2      = (const float*)d_in[22];
    const float* fw       = (const float*)d_in[23];
    const float* fb       = (const float*)d_in[24];
    float* out = (float*)d_out;

    cudaFuncSetAttribute(k3_gemm1, cudaFuncAttributeMaxDynamicSharedMemorySize, SMEM1);
    cudaFuncSetAttribute(k5_gemm2, cudaFuncAttributeMaxDynamicSharedMemorySize, SMEM5);

    k1_preamble<<<NPTS / 256, 256>>>(pos, t, sph_proj, tb1, tb2,
                                     gn1, gw1, gn2, gw2, gn3, gw3);

    k2m<<<NPTS + CWBLK + CW2BLK, 256>>>(t, table0, table1, table2, table3,
                                        st1, st2, tf, vn1, vw1, vw2, vn2);

    __nv_bfloat16* Abf; cudaGetSymbolAddress((void**)&Abf, g_Abf);
    __nv_bfloat16* Vbf; cudaGetSymbolAddress((void**)&Vbf, g_Vbf);
    __nv_bfloat16* WT;  cudaGetSymbolAddress((void**)&WT,  g_WT);
    __nv_bfloat16* WT2; cudaGetSymbolAddress((void**)&WT2, g_WT2);
    float* Sp;          cudaGetSymbolAddress((void**)&Sp,  g_sspart);

    dim3 g1(NTILES, NPTS / 256);          // (19, 128)
    k3_gemm1<<<g1, 256, SMEM1>>>(Abf, WT, Vbf, Sp);

    k5_gemm2<<<NPTS / 128, 256, SMEM5>>>(Vbf, WT2, t, fw, fb, Sp, out);
}

// round 12
// speedup vs baseline: 1.0726x; 1.0633x over previous
#include <cuda_runtime.h>
#include <cuda_bf16.h>
#include <cuda_fp16.h>
#include <math.h>
#include <stdint.h>

#define NPTS 32768
#define TOTAL 2336
#define KPAD1 2368         // GEMM1 K padded (74 blocks of 32; 37 stages of 64)
#define NST1 37            // stages of 64 logical k
#define KPAD2 2432         // GEMM2 K (76 blocks)
#define NST2 76
#define TWOTOTAL 4672
#define INNER 64
#define AW1 4736           // g_Abf row (fp16): 74 blocks x [hi32|lo32]
#define VW 4864            // g_Vbf / g_WT2 row (bf16): 76 blocks x [hi32|lo32]
#define WTS 2368           // g_WT row (fp16 single): plain k layout
#define WTROWS 4864        // permuted W1 rows (19 tiles x 256)
#define NTILES 19
#define NGRP 292           // TOTAL / 8
#define CWBLK (152 * 74)   // convW blocks (32x32 tiles over 4864 x 2368)
#define CW2BLK 584         // convW2 blocks

// ---------------- scratch (static device memory; zero-initialized) -----------
__device__ float g_p[NPTS * 3];
__device__ __align__(128) __half g_Abf[(size_t)NPTS * AW1];          // A fp16 hi/lo
__device__ __align__(128) __nv_bfloat16 g_Vbf[(size_t)NPTS * VW];    // V bf16 hi/lo
__device__ __align__(128) __half g_WT[(size_t)WTROWS * WTS];         // W1 fp16 single
__device__ __align__(128) __nv_bfloat16 g_WT2[(size_t)64 * VW];      // (vn2*vw2)^T bf16 split
__device__ float g_sspart[(size_t)NPTS * NTILES];
__device__ float g_down[NPTS * INNER];     // fallback only

// ---------------- common helpers ---------------------------------------------
__device__ __forceinline__ uint32_t smem_u32(const void* p) {
    uint32_t a;
    asm("{ .reg .u64 t; cvta.to.shared.u64 t, %1; cvt.u32.u64 %0, t; }" : "=r"(a) : "l"(p));
    return a;
}
__device__ __forceinline__ float sigmoidf_(float x) { return 1.0f / (1.0f + expf(-x)); }
__device__ __forceinline__ float gelu_tanh(float x) {
    float x3 = x * x * x;
    return 0.5f * x * (1.0f + tanhf(0.7978845608028654f * (x + 0.044715f * x3)));
}
__device__ __forceinline__ int wrapi(int v, int d) {
    if (v < 0) v += d; else if (v >= d) v -= d; return v;
}
__device__ const int FACE3[6][3] = {{1,0,0},{-1,0,0},{0,1,0},{0,-1,0},{0,0,1},{0,0,-1}};
__device__ const int ST8[8][4]   = {{1,0,0,0},{-1,0,0,0},{0,1,0,0},{0,-1,0,0},
                                    {0,0,1,0},{0,0,-1,0},{0,0,0,1},{0,0,0,-1}};

// cp.async helpers (baseline PTX)
#define CP_ASYNC16(smem, gmem) \
    asm volatile("cp.async.cg.shared.global [%0], [%1], 16;" :: "r"(smem), "l"(gmem) : "memory")
#define CP_COMMIT() asm volatile("cp.async.commit_group;" ::: "memory")
#define CP_WAIT2()  asm volatile("cp.async.wait_group 2;" ::: "memory")
#define CP_WAIT1()  asm volatile("cp.async.wait_group 1;" ::: "memory")
#define CP_WAIT0()  asm volatile("cp.async.wait_group 0;" ::: "memory")

#if defined(__CUDA_ARCH_FEAT_SM103_ALL)
// ---------------- tcgen05 helpers (sm_103a pass only) -------------------------
__device__ __forceinline__ uint32_t elect_one() {
    uint32_t p;
    asm volatile("{ .reg .pred p; elect.sync _|p, 0xFFFFFFFF; selp.b32 %0,1,0,p; }" : "=r"(p));
    return p;
}
#define MBARRIER_INIT(addr, cnt) \
    asm volatile("mbarrier.init.shared.b64 [%0], %1;" :: "r"(addr), "r"(cnt) : "memory")
#define MBARRIER_WAIT_PARITY(addr, parity) do { \
    uint32_t _m = (addr); uint32_t _p = (parity); uint32_t _d; \
    asm volatile("{ .reg .pred p; mbarrier.try_wait.parity.acquire.cta.shared::cta.b64 p, [%1], %2; selp.b32 %0,1,0,p; }" \
        : "=r"(_d) : "r"(_m), "r"(_p) : "memory"); \
    if (!_d) { \
        asm volatile("{ .reg .pred P1; WL_%=: mbarrier.try_wait.parity.acquire.cta.shared::cta.b64 P1, [%0], %1, 0x989680; @P1 bra.uni WD_%=; bra.uni WL_%=; WD_%=: }" \
            :: "r"(_m), "r"(_p) : "memory"); \
    } } while (0)
#define CPA_MBAR_ARRIVE_NOINC(mbar) \
    asm volatile("cp.async.mbarrier.arrive.noinc.shared::cta.b64 [%0];" :: "r"(mbar) : "memory")
#define TC_ALLOC(slot, n)  asm volatile("tcgen05.alloc.cta_group::1.sync.aligned.shared::cta.b32 [%0], %1;" :: "r"(slot), "r"(n) : "memory")
#define TC_DEALLOC(t, n)   asm volatile("tcgen05.dealloc.cta_group::1.sync.aligned.b32 %0, %1;" :: "r"(t), "r"(n))
#define TC_RELINQ()        asm volatile("tcgen05.relinquish_alloc_permit.cta_group::1.sync.aligned;")
#define TC_COMMIT(mbar)    asm volatile("tcgen05.commit.cta_group::1.mbarrier::arrive::one.shared::cluster.b64 [%0];" :: "r"(mbar) : "memory")
#define TC_WAIT_LD()       asm volatile("tcgen05.wait::ld.sync.aligned;" ::: "memory")
#define TC_FENCE_AFTER()   asm volatile("tcgen05.fence::after_thread_sync;" ::: "memory")
#define FENCE_ASYNC_SH()   asm volatile("fence.proxy.async.shared::cta;" ::: "memory")
#define TC_LD_X32(r, addr) \
    asm volatile("tcgen05.ld.sync.aligned.32x32b.x32.b32 " \
        "{%0,%1,%2,%3,%4,%5,%6,%7,%8,%9,%10,%11,%12,%13,%14,%15," \
        "%16,%17,%18,%19,%20,%21,%22,%23,%24,%25,%26,%27,%28,%29,%30,%31}, [%32];" \
        : "=r"((r)[0]),"=r"((r)[1]),"=r"((r)[2]),"=r"((r)[3]),"=r"((r)[4]),"=r"((r)[5]),"=r"((r)[6]),"=r"((r)[7]), \
          "=r"((r)[8]),"=r"((r)[9]),"=r"((r)[10]),"=r"((r)[11]),"=r"((r)[12]),"=r"((r)[13]),"=r"((r)[14]),"=r"((r)[15]), \
          "=r"((r)[16]),"=r"((r)[17]),"=r"((r)[18]),"=r"((r)[19]),"=r"((r)[20]),"=r"((r)[21]),"=r"((r)[22]),"=r"((r)[23]), \
          "=r"((r)[24]),"=r"((r)[25]),"=r"((r)[26]),"=r"((r)[27]),"=r"((r)[28]),"=r"((r)[29]),"=r"((r)[30]),"=r"((r)[31]) \
        : "r"(addr))
static constexpr uint64_t SMEM_DESC_BASE =
    (uint64_t(2) << 61) | (uint64_t(1) << 46) | (uint64_t(64) << 32) | (uint64_t(1) << 16);
__device__ __forceinline__ uint64_t make_desc(uint32_t addr) {
    return SMEM_DESC_BASE | ((uint64_t)(addr >> 4) & 0x3FFF);
}
__device__ __forceinline__ void mma_f16_ss(uint32_t d, uint64_t a, uint64_t b,
                                           uint32_t idesc, uint32_t en) {
    asm volatile("{ .reg .pred p; setp.ne.u32 p, %4, 0;"
                 "tcgen05.mma.cta_group::1.kind::f16 [%0], %1, %2, %3, {%5,%5,%5,%5}, p; }"
                 :: "r"(d), "l"(a), "l"(b), "r"(idesc), "r"(en), "r"(0u) : "memory");
}
#endif

// ---------------- K1: per-point preamble MLP -> p ----------------------------
__global__ void k1_preamble(const float* __restrict__ pos, const float* __restrict__ t,
                            const float* __restrict__ sph_proj,
                            const float* __restrict__ tb1, const float* __restrict__ tb2,
                            const float* __restrict__ gn1, const float* __restrict__ gw1,
                            const float* __restrict__ gn2, const float* __restrict__ gw2,
                            const float* __restrict__ gn3, const float* __restrict__ gw3)
{
    int i = blockIdx.x * blockDim.x + threadIdx.x;
    if (i >= NPTS) return;

    float x = pos[i * 3 + 0], y = pos[i * 3 + 1], z = pos[i * 3 + 2];
    float rho = sqrtf(x * x + y * y + z * z);
    float phi = atan2f(y, x);
    float cz = z / rho;
    cz = fminf(1.0f, fmaxf(-1.0f, cz));
    float theta = acosf(cz);

    float h[12];
#pragma unroll
    for (int j = 0; j < 8; j++)
        h[j] = rho * sph_proj[j] + phi * sph_proj[8 + j] + theta * sph_proj[16 + j];
    float tv = t[i];
    float ct = cosf(tv + tb1[0]);
    float st = sinf(tv + tb2[0]);
    h[8] = ct; h[9] = st;
    h[10] = ct * sigmoidf_(ct);
    h[11] = st * sigmoidf_(st);

    float ss = 0.f;
#pragma unroll
    for (int j = 0; j < 12; j++) ss += h[j] * h[j];
    float sc = 1.0f / (sqrtf(ss / 12.0f) + 1e-8f);
    float hn[12];
#pragma unroll
    for (int j = 0; j < 12; j++) hn[j] = gn1[j] * h[j] * sc;
    float y1[32];
#pragma unroll
    for (int j = 0; j < 32; j++) y1[j] = 0.f;
#pragma unroll
    for (int r = 0; r < 12; r++) {
        float a = hn[r];
#pragma unroll
        for (int j = 0; j < 32; j++) y1[j] += a * gw1[r * 32 + j];
    }
    float h2[16];
#pragma unroll
    for (int k = 0; k < 16; k++) h2[k] = y1[k] * gelu_tanh(y1[16 + k]);

    ss = 0.f;
#pragma unroll
    for (int j = 0; j < 16; j++) ss += h2[j] * h2[j];
    sc = 1.0f / (sqrtf(ss / 16.0f) + 1e-8f);
    float hn2[16];
#pragma unroll
    for (int j = 0; j < 16; j++) hn2[j] = gn2[j] * h2[j] * sc;
    float y2[32];
#pragma unroll
    for (int j = 0; j < 32; j++) y2[j] = 0.f;
#pragma unroll
    for (int r = 0; r < 16; r++) {
        float a = hn2[r];
#pragma unroll
        for (int j = 0; j < 32; j++) y2[j] += a * gw2[r * 32 + j];
    }
    float h3[16];
#pragma unroll
    for (int k = 0; k < 16; k++) h3[k] = y2[k] * gelu_tanh(y2[16 + k]);

    ss = 0.f;
#pragma unroll
    for (int j = 0; j < 16; j++) ss += h3[j] * h3[j];
    sc = 1.0f / (sqrtf(ss / 16.0f) + 1e-8f);
    float z3[3] = {0.f, 0.f, 0.f};
#pragma unroll
    for (int r = 0; r < 16; r++) {
        float a = gn3[r] * h3[r] * sc;
#pragma unroll
        for (int j = 0; j < 3; j++) z3[j] += a * gw3[r * 3 + j];
    }
    g_p[i * 3 + 0] = sigmoidf_(z3[0]);
    g_p[i * 3 + 1] = sigmoidf_(z3[1]);
    g_p[i * 3 + 2] = sigmoidf_(z3[2]);
}

// ---------------- K2m: fused gather + convW(fp16) + convW2 --------------------
__global__ void __launch_bounds__(256) k2m(const float* __restrict__ t,
                          const float* __restrict__ table0, const float* __restrict__ table1,
                          const float* __restrict__ table2, const float* __restrict__ table3,
                          const float* __restrict__ st1, const float* __restrict__ st2,
                          const float* __restrict__ tf, const float* __restrict__ vn1,
                          const float* __restrict__ vw1, const float* __restrict__ vw2,
                          const float* __restrict__ vn2)
{
    int bid = blockIdx.x;
    __shared__ const float* segp[47];
    __shared__ __align__(16) float red[256];
    __shared__ float sh[32][33];

    if (bid < NPTS) {
        int i = bid;
        float p0 = g_p[i * 3 + 0], p1 = g_p[i * 3 + 1], p2 = g_p[i * 3 + 2];
        float tt = t[i];

        int s = threadIdx.x;
        if (s < 47) {
            const float* base = nullptr;
            if (s < 28) {
                int tb = s / 7;
                int o = s % 7;
                int d, F; const float* T;
                if (tb == 0)      { d = 128; F = 16;  T = table0; }
                else if (tb == 1) { d = 64;  F = 32;  T = table1; }
                else if (tb == 2) { d = 32;  F = 64;  T = table2; }
                else              { d = 16;  F = 128; T = table3; }
                int ix = (int)(p0 * (float)(d - 1));
                int iy = (int)(p1 * (float)(d - 1));
                int iz = (int)(p2 * (float)(d - 1));
                if (o > 0) {
                    ix = wrapi(ix + FACE3[o - 1][0], d);
                    iy = wrapi(iy + FACE3[o - 1][1], d);
                    iz = wrapi(iz + FACE3[o - 1][2], d);
                }
                base = T + (size_t)((ix * d + iy) * d + iz) * F;
            } else if (s < 46) {
                int grp = (s - 28) / 9;
                int o = (s - 28) % 9;
                if (grp == 0) {
                    int a = (int)(p0 * 15.0f), b = (int)(p1 * 15.0f),
                        c = (int)(p2 * 15.0f), e = (int)(tt * 63.0f);
                    if (o > 0) {
                        a = wrapi(a + ST8[o - 1][0], 16);
                        b = wrapi(b + ST8[o - 1][1], 16);
                        c = wrapi(c + ST8[o - 1][2], 16);
                        e = wrapi(e + ST8[o - 1][3], 64);
                    }
                    base = st1 + (size_t)(((a * 16 + b) * 16 + c) * 64 + e) * 64;
                } else {
                    int a = (int)(p0 * 63.0f), b = (int)(p1 * 63.0f),
                        c = (int)(p2 * 31.0f), e = (int)(tt * 15.0f);
                    if (o > 0) {
                        a = wrapi(a + ST8[o - 1][0], 64);
                        b = wrapi(b + ST8[o - 1][1], 64);
                        c = wrapi(c + ST8[o - 1][2], 32);
                        e = wrapi(e + ST8[o - 1][3], 16);
                    }
                    base = st2 + (size_t)(((a * 64 + b) * 32 + c) * 16 + e) * 8;
                }
            } else {
                int a = (int)(p0 * 3.0f), b = (int)(p1 * 3.0f),
                    c = (int)(p2 * 3.0f), e = (int)(tt * 65535.0f);
                base = tf + (size_t)(((a * 4 + b) * 4 + c) * 65536 + e) * 8;
            }
            segp[s] = base;
        }
        __syncthreads();

        float4 v0[2], v1[2];
        float ss = 0.f;
#pragma unroll
        for (int gi = 0; gi < 2; gi++) {
            int g = threadIdx.x + gi * 256;
            if (g < NGRP) {
                int f0 = g * 8;
                int seg, off;
                if (f0 < 112)       { seg = f0 >> 4;                 off = f0 & 15; }
                else if (f0 < 336)  { int q = f0 - 112;  seg = 7  + (q >> 5); off = q & 31; }
                else if (f0 < 784)  { int q = f0 - 336;  seg = 14 + (q >> 6); off = q & 63; }
                else if (f0 < 1680) { int q = f0 - 784;  seg = 21 + (q >> 7); off = q & 127; }
                else if (f0 < 2256) { int q = f0 - 1680; seg = 28 + (q >> 6); off = q & 63; }
                else if (f0 < 2328) { int q = f0 - 2256; seg = 37 + (q >> 3); off = q & 7; }
                else                { seg = 46;                      off = f0 - 2328; }
                const float* sp = segp[seg] + off;
                float4 a = *(const float4*)sp;
                float4 b = *(const float4*)(sp + 4);
                v0[gi] = a; v1[gi] = b;
                ss += a.x * a.x + a.y * a.y + a.z * a.z + a.w * a.w
                    + b.x * b.x + b.y * b.y + b.z * b.z + b.w * b.w;
            }
        }
        red[threadIdx.x] = ss;
        __syncthreads();
        for (int w = 128; w > 0; w >>= 1) {
            if (threadIdx.x < w) red[threadIdx.x] += red[threadIdx.x + w];
            __syncthreads();
        }
        float rms = sqrtf(red[0] / (float)TOTAL);
        float sc = 1.0f / (rms + 1e-8f);
        __half* orow = g_Abf + (size_t)i * AW1;
#pragma unroll
        for (int gi = 0; gi < 2; gi++) {
            int g = threadIdx.x + gi * 256;
            if (g < NGRP) {
                int f0 = g * 8;
                float4 n0 = *(const float4*)&vn1[f0];
                float4 n1 = *(const float4*)&vn1[f0 + 4];
                float v[8] = { v0[gi].x * n0.x * sc, v0[gi].y * n0.y * sc,
                               v0[gi].z * n0.z * sc, v0[gi].w * n0.w * sc,
                               v1[gi].x * n1.x * sc, v1[gi].y * n1.y * sc,
                               v1[gi].z * n1.z * sc, v1[gi].w * n1.w * sc };
                uint32_t hi[4], lo[4];
#pragma unroll
                for (int j = 0; j < 4; j++) {
                    __half h0 = __float2half(v[2 * j]);
                    __half h1 = __float2half(v[2 * j + 1]);
                    __half l0 = __float2half(v[2 * j] - __half2float(h0));
                    __half l1 = __float2half(v[2 * j + 1] - __half2float(h1));
                    hi[j] = (uint32_t)(*(unsigned short*)&h0) | ((uint32_t)(*(unsigned short*)&h1) << 16);
                    lo[j] = (uint32_t)(*(unsigned short*)&l0) | ((uint32_t)(*(unsigned short*)&l1) << 16);
                }
                int blk = f0 >> 5, pos = f0 & 31;
                *(uint4*)(orow + blk * 64 + pos)      = make_uint4(hi[0], hi[1], hi[2], hi[3]);
                *(uint4*)(orow + blk * 64 + 32 + pos) = make_uint4(lo[0], lo[1], lo[2], lo[3]);
            }
        }
    } else if (bid < NPTS + CWBLK) {
        // -------- convW: permuted transpose, single fp16 -> g_WT[n][k] --------
        int b2 = bid - NPTS;
        int n0 = (b2 % 152) * 32, k0 = (b2 / 152) * 32;
        int tx = threadIdx.x & 31, ty = threadIdx.x >> 5;   // 32 x 8
        int tile = n0 >> 8, half = (n0 >> 7) & 1;
        int f0 = tile * 128 + (n0 & 127);
#pragma unroll
        for (int ii = 0; ii < 4; ii++) {
            int r = ty + ii * 8;
            int k = k0 + r;
            int f = f0 + tx;
            float v = 0.f;
            if (f < TOTAL && k < TOTAL)
                v = vw1[(size_t)k * TWOTOTAL + half * TOTAL + f];
            sh[r][tx] = v;
        }
        __syncthreads();
#pragma unroll
        for (int ii = 0; ii < 4; ii++) {
            int r = ty + ii * 8;
            int n = n0 + r;
            g_WT[(size_t)n * WTS + (k0 + tx)] = __float2half(sh[tx][r]);
        }
    } else {
        // -------- convW2: (vn2 * vw2)^T bf16 split -> g_WT2 --------
        int idx = (bid - NPTS - CWBLK) * 256 + threadIdx.x;
        if (idx < TOTAL * 64) {
            int k = idx >> 6, n = idx & 63;
            float v = vn2[k] * vw2[idx];
            __nv_bfloat16 h = __float2bfloat16(v);
            float hf = __bfloat162float(h);
            __nv_bfloat16 l = __float2bfloat16(v - hf);
            size_t base = (size_t)n * VW + (size_t)((k >> 5) * 64);
            g_WT2[base + (k & 31)] = h;
            g_WT2[base + 32 + (k & 31)] = l;
        }
    }
}

// ---------------- K3: warp-specialized fp16 2-term GEMM1 + geglu epilogue -----
// Stage = 64 logical k: A blk(2s) 32KB + A blk(2s+1) 32KB + W 32KB; 2 buffers.
#define SMEM1 (1024 + 2 * 98304)

__global__ void __launch_bounds__(256, 1) k3_gemm1(const __half* __restrict__ Abf,
                                                   const __half* __restrict__ WT,
                                                   __nv_bfloat16* __restrict__ Vbf,
                                                   float* __restrict__ sspart)
{
    extern __shared__ char smem[];
    uint32_t sbase = smem_u32(smem);
    int tid = threadIdx.x;
    int wid = tid >> 5, lid = tid & 31;
    int tile = blockIdx.x;
    int bm = blockIdx.y * 256;
    int bn = tile * 256;

#if defined(__CUDA_ARCH_FEAT_SM103_ALL)
    const uint32_t TSLOT = sbase;
    const uint32_t FUL0 = sbase + 16, FUL1 = sbase + 24;
    const uint32_t EMP0 = sbase + 40, EMP1 = sbase + 48;
    const uint32_t DONE = sbase + 64;
    const uint32_t SDATA = sbase + 1024;

    if (wid == 0) TC_ALLOC(TSLOT, 512);
    if (tid == 0) {
        MBARRIER_INIT(FUL0, 224); MBARRIER_INIT(FUL1, 224);
        MBARRIER_INIT(EMP0, 1);   MBARRIER_INIT(EMP1, 1);
        MBARRIER_INIT(DONE, 1);
    }
    __syncthreads();
    uint32_t tmem;
    asm volatile("ld.shared.b32 %0, [%1];" : "=r"(tmem) : "r"(TSLOT));

    // fp16 inputs: atype=btype=F16=0; dtype F32; N=256; M=128
    const uint32_t IDESC = (1u << 4) | (32u << 17) | (8u << 24);

    if (wid >= 1) {
        // producers: warps 1-7 (224 threads)
        int ptid = tid - 32;
        int pe0 = 1, pe1 = 1;
        const __half* Abase = Abf + (size_t)bm * AW1;
        const __half* Wbase = WT + (size_t)bn * WTS;
        for (int s = 0; s < NST1; s++) {
            int b = s & 1;
            uint32_t emp = b ? EMP1 : EMP0;
            uint32_t ful = b ? FUL1 : FUL0;
            if (b == 0) { MBARRIER_WAIT_PARITY(emp, pe0); pe0 ^= 1; }
            else        { MBARRIER_WAIT_PARITY(emp, pe1); pe1 ^= 1; }
            uint32_t ab = SDATA + b * 98304;
            int ka = s * 128;          // A phys elem offset (2 blocks of 64)
            int kw = s * 64;           // W elem offset
            for (int idx = ptid; idx < 6144; idx += 224) {
                int part = idx >> 11;  // 0: A blk0, 1: A blk1, 2: W
                int r = (idx & 2047) >> 3, c = idx & 7;
                uint32_t off = (uint32_t)(r * 128 + c * 16);
                uint32_t sw = off ^ ((off >> 3) & 0x70);
                if (part == 0)
                    CP_ASYNC16(ab + sw, (const void*)(Abase + (size_t)r * AW1 + ka + c * 8));
                else if (part == 1)
                    CP_ASYNC16(ab + 32768 + sw, (const void*)(Abase + (size_t)r * AW1 + ka + 64 + c * 8));
                else
                    CP_ASYNC16(ab + 65536 + sw, (const void*)(Wbase + (size_t)r * WTS + kw + c * 8));
            }
            CPA_MBAR_ARRIVE_NOINC(ful);
        }
    } else if (elect_one()) {
        // consumer
        int pf0 = 0, pf1 = 0;
        for (int s = 0; s < NST1; s++) {
            int b = s & 1;
            uint32_t ful = b ? FUL1 : FUL0;
            uint32_t emp = b ? EMP1 : EMP0;
            if (b == 0) { MBARRIER_WAIT_PARITY(ful, pf0); pf0 ^= 1; }
            else        { MBARRIER_WAIT_PARITY(ful, pf1); pf1 ^= 1; }
            FENCE_ASYNC_SH();
            uint32_t ab = SDATA + b * 98304;
            uint64_t wd = make_desc(ab + 65536);
#pragma unroll
            for (int half = 0; half < 2; half++) {
                uint64_t a0 = make_desc(ab + half * 16384);
                uint64_t a1 = make_desc(ab + 32768 + half * 16384);
                uint32_t dt = tmem + half * 256;
                uint32_t en0 = (s > 0) ? 1u : 0u;
                // Ahi blk0/blk1 x W
                mma_f16_ss(dt, a0 + 0, wd + 0, IDESC, en0);
                mma_f16_ss(dt, a0 + 2, wd + 2, IDESC, 1u);
                mma_f16_ss(dt, a1 + 0, wd + 4, IDESC, 1u);
                mma_f16_ss(dt, a1 + 2, wd + 6, IDESC, 1u);
                // Alo blk0/blk1 x W
                mma_f16_ss(dt, a0 + 4, wd + 0, IDESC, 1u);
                mma_f16_ss(dt, a0 + 6, wd + 2, IDESC, 1u);
                mma_f16_ss(dt, a1 + 4, wd + 4, IDESC, 1u);
                mma_f16_ss(dt, a1 + 6, wd + 6, IDESC, 1u);
            }
            TC_COMMIT(emp);
        }
        TC_COMMIT(DONE);
    }
    MBARRIER_WAIT_PARITY(DONE, 0);
    TC_FENCE_AFTER();

    // fused epilogue: a = cols 0-127, g = cols 128-255 -> v = a*gelu(g)
    {
        int m = bm + ((wid < 4) ? 0 : 128) + (wid & 3) * 32 + lid;
        uint32_t dbase = tmem + ((wid < 4) ? 0 : 256);
        float ssacc = 0.f;
#pragma unroll
        for (int cp = 0; cp < 4; cp++) {
            uint32_t ra[32], rg[32];
            TC_LD_X32(ra, dbase + cp * 32);
            TC_LD_X32(rg, dbase + 128 + cp * 32);
            TC_WAIT_LD();
            uint32_t o[32];
#pragma unroll
            for (int j = 0; j < 32; j += 2) {
                float a0 = __uint_as_float(ra[j]),     a1 = __uint_as_float(ra[j + 1]);
                float g0 = __uint_as_float(rg[j]),     g1 = __uint_as_float(rg[j + 1]);
                float v0 = a0 * gelu_tanh(g0), v1 = a1 * gelu_tanh(g1);
                ssacc += v0 * v0 + v1 * v1;
                __nv_bfloat16 h0 = __float2bfloat16(v0);
                __nv_bfloat16 h1 = __float2bfloat16(v1);
                __nv_bfloat16 l0 = __float2bfloat16(v0 - __bfloat162float(h0));
                __nv_bfloat16 l1 = __float2bfloat16(v1 - __bfloat162float(h1));
                unsigned short uh0 = *(unsigned short*)&h0, uh1 = *(unsigned short*)&h1;
                unsigned short ul0 = *(unsigned short*)&l0, ul1 = *(unsigned short*)&l1;
                o[j >> 1]        = (uint32_t)uh0 | ((uint32_t)uh1 << 16);
                o[16 + (j >> 1)] = (uint32_t)ul0 | ((uint32_t)ul1 << 16);
            }
            int fb = tile * 4 + cp;
            uint4* dst = (uint4*)(Vbf + (size_t)m * VW + fb * 64);
#pragma unroll
            for (int q = 0; q < 8; q++)
                dst[q] = make_uint4(o[4 * q], o[4 * q + 1], o[4 * q + 2], o[4 * q + 3]);
        }
        sspart[(size_t)m * NTILES + tile] = ssacc;
    }
    __syncthreads();
    if (wid == 0) {
        TC_RELINQ();
        TC_DEALLOC(tmem, 512);
    }
#else
    // ---- FFMA fallback (generic pass; never selected on sm_103a) ----
    float* Da   = (float*)smem;
    float* As   = Da + 128 * 128;
    float* Bs   = As + 16 * 128;
    float* ssrd = Bs + 16 * 128;
    int tx = tid % 16, ty = tid / 16;
    for (int pass = 0; pass < 2; pass++) {
        int pm = bm + pass * 128;
        for (int half = 0; half < 2; half++) {
            int pn = bn + half * 128;
            float acc[8][8];
#pragma unroll
            for (int a = 0; a < 8; a++)
#pragma unroll
                for (int b = 0; b < 8; b++) acc[a][b] = 0.f;
            for (int k0 = 0; k0 < KPAD1; k0 += 16) {
                __syncthreads();
                for (int idx = tid; idx < 2048; idx += 256) {
                    int row = idx >> 4, kk = idx & 15;
                    int k = k0 + kk;
                    size_t pb = (size_t)(k >> 5) * 64 + (k & 31);
                    const __half* ar = Abf + (size_t)(pm + row) * AW1 + pb;
                    As[kk * 128 + row] = __half2float(ar[0]) + __half2float(ar[32]);
                    Bs[kk * 128 + row] = __half2float(WT[(size_t)(pn + row) * WTS + k]);
                }
                __syncthreads();
#pragma unroll
                for (int k = 0; k < 16; k++) {
                    float af[8], bf[8];
#pragma unroll
                    for (int a = 0; a < 8; a++) af[a] = As[k * 128 + ty * 8 + a];
#pragma unroll
                    for (int b = 0; b < 8; b++) bf[b] = Bs[k * 128 + tx * 8 + b];
#pragma unroll
                    for (int a = 0; a < 8; a++)
#pragma unroll
                        for (int b = 0; b < 8; b++) acc[a][b] += af[a] * bf[b];
                }
            }
            __syncthreads();
            if (half == 0) {
#pragma unroll
                for (int a = 0; a < 8; a++)
#pragma unroll
                    for (int b = 0; b < 8; b++)
                        Da[(ty * 8 + a) * 128 + tx * 8 + b] = acc[a][b];
            } else {
#pragma unroll
                for (int a = 0; a < 8; a++) {
                    int row = ty * 8 + a;
                    float ssp = 0.f;
#pragma unroll
                    for (int b = 0; b < 8; b++) {
                        int col = tx * 8 + b;
                        float av = Da[row * 128 + col];
                        float v = av * gelu_tanh(acc[a][b]);
                        ssp += v * v;
                        __nv_bfloat16 h = __float2bfloat16(v);
                        __nv_bfloat16 l = __float2bfloat16(v - __bfloat162float(h));
                        int f = tile * 128 + col;
                        int fb = f >> 5, pos = f & 31;
                        Vbf[(size_t)(pm + row) * VW + fb * 64 + pos] = h;
                        Vbf[(size_t)(pm + row) * VW + fb * 64 + 32 + pos] = l;
                    }
                    ssrd[row * 16 + tx] = ssp;
                }
            }
            __syncthreads();
        }
        if (tid < 128) {
            float sm = 0.f;
            for (int j = 0; j < 16; j++) sm += ssrd[tid * 16 + j];
            sspart[(size_t)(pm + tid) * NTILES + tile] = sm;
        }
        __syncthreads();
    }
#endif
}

// ---------------- K5: GEMM2 (bf16 3-term) + fused row-scale + final linear ----
#define SMEM5 (1024 + 3 * 24576)
__global__ void __launch_bounds__(256, 1) k5_gemm2(const __nv_bfloat16* __restrict__ Vbf,
                                                   const __nv_bfloat16* __restrict__ WT2,
                                                   const float* __restrict__ t,
                                                   const float* __restrict__ fw,
                                                   const float* __restrict__ fbias,
                                                   const float* __restrict__ sspart,
                                                   float* __restrict__ out)
{
    extern __shared__ char smem[];
    uint32_t sbase = smem_u32(smem);
    int tid = threadIdx.x;
    int wid = tid >> 5, lid = tid & 31;
    int bm = blockIdx.x * 128;

#if defined(__CUDA_ARCH_FEAT_SM103_ALL)
    const uint32_t TSLOT = sbase;
    const uint32_t MB0 = sbase + 16;
    const uint32_t MB1 = sbase + 24;
    const uint32_t MB2 = sbase + 32;
    const uint32_t SDATA = sbase + 1024;

    if (wid == 0) TC_ALLOC(TSLOT, 64);
    if (tid == 0) { MBARRIER_INIT(MB0, 1); MBARRIER_INIT(MB1, 1); MBARRIER_INIT(MB2, 1); }
    __syncthreads();
    uint32_t tmem;
    asm volatile("ld.shared.b32 %0, [%1];" : "=r"(tmem) : "r"(TSLOT));

    const uint32_t IDESC = (1u << 4) | (1u << 7) | (1u << 10) | (8u << 17) | (8u << 24);

    auto load_stage = [&](int s) {
        int buf = s % 3;
        int ks = s * 64;
        uint32_t ab = SDATA + buf * 24576;
        uint32_t wb = ab + 16384;
        const __nv_bfloat16* Asrc = Vbf + (size_t)bm * VW + ks;
        const __nv_bfloat16* Wsrc = WT2 + ks;
#pragma unroll
        for (int j = 0; j < 4; j++) {
            int idx = tid + j * 256;
            int row = idx >> 3, c = idx & 7;
            uint32_t off = (uint32_t)(row * 128 + c * 16);
            uint32_t sw = off ^ ((off >> 3) & 0x70);
            CP_ASYNC16(ab + sw, (const void*)(Asrc + (size_t)row * VW + c * 8));
        }
#pragma unroll
        for (int j = 0; j < 2; j++) {
            int idx = tid + j * 256;
            int row = idx >> 3, c = idx & 7;
            uint32_t off = (uint32_t)(row * 128 + c * 16);
            uint32_t sw = off ^ ((off >> 3) & 0x70);
            CP_ASYNC16(wb + sw, (const void*)(Wsrc + (size_t)row * VW + c * 8));
        }
        CP_COMMIT();
    };

    int ph0 = 0, ph1 = 0, ph2 = 0;
    load_stage(0);
    load_stage(1);
    for (int s = 0; s < NST2; s++) {
        if (s + 2 < NST2) {
            if (s >= 1) {
                int b = (s - 1) % 3;
                if (b == 0)      { MBARRIER_WAIT_PARITY(MB0, ph0); ph0 ^= 1; }
                else if (b == 1) { MBARRIER_WAIT_PARITY(MB1, ph1); ph1 ^= 1; }
                else             { MBARRIER_WAIT_PARITY(MB2, ph2); ph2 ^= 1; }
            }
            load_stage(s + 2);
        }
        if (s + 2 < NST2)      CP_WAIT2();
        else if (s + 1 < NST2) CP_WAIT1();
        else                   CP_WAIT0();
        __syncthreads();
        FENCE_ASYNC_SH();
        if (wid == 0) {
            if (elect_one()) {
                int buf = s % 3;
                uint32_t ab = SDATA + buf * 24576;
                uint64_t ad = make_desc(ab);
                uint64_t bd = make_desc(ab + 16384);
                uint32_t en0 = (s > 0) ? 1u : 0u;
                mma_f16_ss(tmem, ad + 0, bd + 0, IDESC, en0);
                mma_f16_ss(tmem, ad + 2, bd + 2, IDESC, 1u);
                mma_f16_ss(tmem, ad + 4, bd + 0, IDESC, 1u);
                mma_f16_ss(tmem, ad + 6, bd + 2, IDESC, 1u);
                mma_f16_ss(tmem, ad + 0, bd + 4, IDESC, 1u);
                mma_f16_ss(tmem, ad + 2, bd + 6, IDESC, 1u);
                if (buf == 0) TC_COMMIT(MB0);
                else if (buf == 1) TC_COMMIT(MB1);
                else TC_COMMIT(MB2);
            }
        }
    }
    {
        int b = (NST2 - 1) % 3;   // 75 % 3 = 0
        if (b == 0)      MBARRIER_WAIT_PARITY(MB0, ph0);
        else if (b == 1) MBARRIER_WAIT_PARITY(MB1, ph1);
        else             MBARRIER_WAIT_PARITY(MB2, ph2);
    }
    TC_FENCE_AFTER();

    if (wid < 4) {
        int m = bm + wid * 32 + lid;
        uint32_t r[32], r2[32];
        TC_LD_X32(r, tmem);
        TC_LD_X32(r2, tmem + 32);
        TC_WAIT_LD();

        const float* sp = sspart + (size_t)m * NTILES;
        float ss = 0.f;
#pragma unroll
        for (int q = 0; q < NTILES; q++) ss += sp[q];
        float sc = 1.0f / (sqrtf(ss / (float)TOTAL) + 1e-8f);

        float o0 = 0.f, o1 = 0.f, o2 = 0.f, o3 = 0.f;
#pragma unroll
        for (int q = 0; q < 32; q++) {
            float a = __uint_as_float(r[q]);
            o0 += a * fw[q * 4 + 0]; o1 += a * fw[q * 4 + 1];
            o2 += a * fw[q * 4 + 2]; o3 += a * fw[q * 4 + 3];
        }
#pragma unroll
        for (int q = 0; q < 32; q++) {
            float a = __uint_as_float(r2[q]);
            o0 += a * fw[(32 + q) * 4 + 0]; o1 += a * fw[(32 + q) * 4 + 1];
            o2 += a * fw[(32 + q) * 4 + 2]; o3 += a * fw[(32 + q) * 4 + 3];
        }
        o0 *= sc; o1 *= sc; o2 *= sc; o3 *= sc;
        o0 += fbias[0]; o1 += fbias[1]; o2 += fbias[2]; o3 += fbias[3];
        float p0 = g_p[m * 3 + 0], p1 = g_p[m * 3 + 1], p2 = g_p[m * 3 + 2];
        float tv = t[m];
        o0 += p0 * fw[256 + 0] + p1 * fw[260 + 0] + p2 * fw[264 + 0] + tv * fw[268 + 0];
        o1 += p0 * fw[256 + 1] + p1 * fw[260 + 1] + p2 * fw[264 + 1] + tv * fw[268 + 1];
        o2 += p0 * fw[256 + 2] + p1 * fw[260 + 2] + p2 * fw[264 + 2] + tv * fw[268 + 2];
        o3 += p0 * fw[256 + 3] + p1 * fw[260 + 3] + p2 * fw[264 + 3] + tv * fw[268 + 3];
        *(float4*)(out + (size_t)m * 4) = make_float4(o0, o1, o2, o3);
    }
    __syncthreads();
    if (wid == 0) {
        TC_RELINQ();
        TC_DEALLOC(tmem, 64);
    }
#else
    // ---- FFMA fallback (256 threads) ----
    float* Ds = (float*)smem;
    float* Bs = Ds + 64 * 64;
    for (int m0 = 0; m0 < 128; m0 += 64) {
        int mrow = (tid >> 2);
        int m = bm + m0 + mrow;
        int nq = (tid & 3) * 16;
        float acc[16];
#pragma unroll
        for (int a = 0; a < 16; a++) acc[a] = 0.f;
        for (int k0 = 0; k0 < KPAD2; k0 += 16) {
            __syncthreads();
            for (int idx = tid; idx < 1024; idx += 256) {
                int kk = idx >> 6, n = idx & 63;
                int k = k0 + kk;
                const __nv_bfloat16* wr = WT2 + (size_t)n * VW + (size_t)(k >> 5) * 64 + (k & 31);
                Bs[kk * 64 + n] = __bfloat162float(wr[0]) + __bfloat162float(wr[32]);
            }
            __syncthreads();
#pragma unroll
            for (int kk = 0; kk < 16; kk++) {
                int k = k0 + kk;
                const __nv_bfloat16* ar = Vbf + (size_t)m * VW + (size_t)(k >> 5) * 64 + (k & 31);
                float av = __bfloat162float(ar[0]) + __bfloat162float(ar[32]);
#pragma unroll
                for (int a = 0; a < 16; a++) acc[a] += av * Bs[kk * 64 + nq + a];
            }
        }
        __syncthreads();
        for (int a = 0; a < 16; a++) Ds[mrow * 64 + nq + a] = acc[a];
        __syncthreads();
        if (tid < 64) {
            int m2 = bm + m0 + tid;
            const float* sp = sspart + (size_t)m2 * NTILES;
            float ss = 0.f;
            for (int q = 0; q < NTILES; q++) ss += sp[q];
            float sc = 1.0f / (sqrtf(ss / (float)TOTAL) + 1e-8f);
            float o0 = 0.f, o1 = 0.f, o2 = 0.f, o3 = 0.f;
            for (int q = 0; q < 64; q++) {
                float a = Ds[tid * 64 + q];
                o0 += a * fw[q * 4 + 0]; o1 += a * fw[q * 4 + 1];
                o2 += a * fw[q * 4 + 2]; o3 += a * fw[q * 4 + 3];
            }
            o0 *= sc; o1 *= sc; o2 *= sc; o3 *= sc;
            o0 += fbias[0]; o1 += fbias[1]; o2 += fbias[2]; o3 += fbias[3];
            float p0 = g_p[m2 * 3 + 0], p1 = g_p[m2 * 3 + 1], p2 = g_p[m2 * 3 + 2];
            float tv = t[m2];
            o0 += p0 * fw[256 + 0] + p1 * fw[260 + 0] + p2 * fw[264 + 0] + tv * fw[268 + 0];
            o1 += p0 * fw[256 + 1] + p1 * fw[260 + 1] + p2 * fw[264 + 1] + tv * fw[268 + 1];
            o2 += p0 * fw[256 + 2] + p1 * fw[260 + 2] + p2 * fw[264 + 2] + tv * fw[268 + 2];
            o3 += p0 * fw[256 + 3] + p1 * fw[260 + 3] + p2 * fw[264 + 3] + tv * fw[268 + 3];
            *(float4*)(out + (size_t)m2 * 4) = make_float4(o0, o1, o2, o3);
        }
        __syncthreads();
    }
#endif
}

// ---------------- launcher ----------------------------------------------------
extern "C" void kernel_launch(void* const* d_in, const int* in_sizes, int n_in,
                              void* d_out, int out_size)
{
    const float* pos      = (const float*)d_in[0];
    const float* t        = (const float*)d_in[2];
    const float* table0   = (const float*)d_in[3];
    const float* table1   = (const float*)d_in[4];
    const float* table2   = (const float*)d_in[5];
    const float* table3   = (const float*)d_in[6];
    const float* st1      = (const float*)d_in[7];
    const float* st2      = (const float*)d_in[8];
    const float* tf       = (const float*)d_in[9];
    const float* sph_proj = (const float*)d_in[10];
    const float* tb1      = (const float*)d_in[11];
    const float* tb2      = (const float*)d_in[12];
    const float* gn1      = (const float*)d_in[13];
    const float* gw1      = (const float*)d_in[14];
    const float* gn2      = (const float*)d_in[15];
    const float* gw2      = (const float*)d_in[16];
    const float* gn3      = (const float*)d_in[17];
    const float* gw3      = (const float*)d_in[18];
    const float* vn1      = (const float*)d_in[19];
    const float* vw1      = (const float*)d_in[20];
    const float* vn2      = (const float*)d_in[21];
    const float* vw2      = (const float*)d_in[22];
    const float* fw       = (const float*)d_in[23];
    const float* fb       = (const float*)d_in[24];
    float* out = (float*)d_out;

    cudaFuncSetAttribute(k3_gemm1, cudaFuncAttributeMaxDynamicSharedMemorySize, SMEM1);
    cudaFuncSetAttribute(k5_gemm2, cudaFuncAttributeMaxDynamicSharedMemorySize, SMEM5);

    k1_preamble<<<NPTS / 256, 256>>>(pos, t, sph_proj, tb1, tb2,
                                     gn1, gw1, gn2, gw2, gn3, gw3);

    k2m<<<NPTS + CWBLK + CW2BLK, 256>>>(t, table0, table1, table2, table3,
                                        st1, st2, tf, vn1, vw1, vw2, vn2);

    __half* Abf;        cudaGetSymbolAddress((void**)&Abf, g_Abf);
    __nv_bfloat16* Vbf; cudaGetSymbolAddress((void**)&Vbf, g_Vbf);
    __half* WT;         cudaGetSymbolAddress((void**)&WT,  g_WT);
    __nv_bfloat16* WT2; cudaGetSymbolAddress((void**)&WT2, g_WT2);
    float* Sp;          cudaGetSymbolAddress((void**)&Sp,  g_sspart);

    dim3 g1(NTILES, NPTS / 256);          // (19, 128)
    k3_gemm1<<<g1, 256, SMEM1>>>(Abf, WT, Vbf, Sp);

    k5_gemm2<<<NPTS / 128, 256, SMEM5>>>(Vbf, WT2, t, fw, fb, Sp, out);
}

// round 13
// speedup vs baseline: 1.1025x; 1.0278x over previous
#include <cuda_runtime.h>
#include <cuda_bf16.h>
#include <cuda_fp16.h>
#include <math.h>
#include <stdint.h>

#define NPTS 32768
#define TOTAL 2336
#define KPAD1 2368         // GEMM1 K padded (74 stages of 32 logical k)
#define NST1 74
#define KPAD2 2432         // GEMM2 K (76 blocks)
#define NST2 76
#define TWOTOTAL 4672
#define INNER 64
#define AW1 4736           // g_Abf row (fp16): 74 blocks x [hi32|lo32]
#define VW 4864            // g_Vbf / g_WT2 row (bf16): 76 blocks x [hi32|lo32]
#define WTS 2368           // g_WT row (fp16 single): plain k layout
#define WTROWS 4864        // permuted W1 rows (19 tiles x 256)
#define NTILES 19
#define NGRP 292           // TOTAL / 8
#define CWBLK (152 * 74)
#define CW2BLK 584

// ---------------- scratch (static device memory; zero-initialized) -----------
__device__ float g_p[NPTS * 3];
__device__ __align__(128) __half g_Abf[(size_t)NPTS * AW1];          // A fp16 hi/lo
__device__ __align__(128) __nv_bfloat16 g_Vbf[(size_t)NPTS * VW];    // V bf16 hi/lo
__device__ __align__(128) __half g_WT[(size_t)WTROWS * WTS];         // W1 fp16 single
__device__ __align__(128) __nv_bfloat16 g_WT2[(size_t)64 * VW];      // (vn2*vw2)^T bf16 split
__device__ float g_sspart[(size_t)NPTS * NTILES];
__device__ float g_down[NPTS * INNER];     // fallback only

// ---------------- common helpers ---------------------------------------------
__device__ __forceinline__ uint32_t smem_u32(const void* p) {
    uint32_t a;
    asm("{ .reg .u64 t; cvta.to.shared.u64 t, %1; cvt.u32.u64 %0, t; }" : "=r"(a) : "l"(p));
    return a;
}
__device__ __forceinline__ float sigmoidf_(float x) { return 1.0f / (1.0f + expf(-x)); }
__device__ __forceinline__ float gelu_tanh(float x) {
    float x3 = x * x * x;
    return 0.5f * x * (1.0f + tanhf(0.7978845608028654f * (x + 0.044715f * x3)));
}
__device__ __forceinline__ int wrapi(int v, int d) {
    if (v < 0) v += d; else if (v >= d) v -= d; return v;
}
__device__ const int FACE3[6][3] = {{1,0,0},{-1,0,0},{0,1,0},{0,-1,0},{0,0,1},{0,0,-1}};
__device__ const int ST8[8][4]   = {{1,0,0,0},{-1,0,0,0},{0,1,0,0},{0,-1,0,0},
                                    {0,0,1,0},{0,0,-1,0},{0,0,0,1},{0,0,0,-1}};

// cp.async helpers (baseline PTX)
#define CP_ASYNC16(smem, gmem) \
    asm volatile("cp.async.cg.shared.global [%0], [%1], 16;" :: "r"(smem), "l"(gmem) : "memory")
#define CP_COMMIT() asm volatile("cp.async.commit_group;" ::: "memory")
#define CP_WAIT2()  asm volatile("cp.async.wait_group 2;" ::: "memory")
#define CP_WAIT1()  asm volatile("cp.async.wait_group 1;" ::: "memory")
#define CP_WAIT0()  asm volatile("cp.async.wait_group 0;" ::: "memory")

#if defined(__CUDA_ARCH_FEAT_SM103_ALL)
// ---------------- tcgen05 helpers (sm_103a pass only) -------------------------
__device__ __forceinline__ uint32_t elect_one() {
    uint32_t p;
    asm volatile("{ .reg .pred p; elect.sync _|p, 0xFFFFFFFF; selp.b32 %0,1,0,p; }" : "=r"(p));
    return p;
}
#define MBARRIER_INIT(addr, cnt) \
    asm volatile("mbarrier.init.shared.b64 [%0], %1;" :: "r"(addr), "r"(cnt) : "memory")
#define MBARRIER_WAIT_PARITY(addr, parity) do { \
    uint32_t _m = (addr); uint32_t _p = (parity); uint32_t _d; \
    asm volatile("{ .reg .pred p; mbarrier.try_wait.parity.acquire.cta.shared::cta.b64 p, [%1], %2; selp.b32 %0,1,0,p; }" \
        : "=r"(_d) : "r"(_m), "r"(_p) : "memory"); \
    if (!_d) { \
        asm volatile("{ .reg .pred P1; WL_%=: mbarrier.try_wait.parity.acquire.cta.shared::cta.b64 P1, [%0], %1, 0x989680; @P1 bra.uni WD_%=; bra.uni WL_%=; WD_%=: }" \
            :: "r"(_m), "r"(_p) : "memory"); \
    } } while (0)
#define CPA_MBAR_ARRIVE_NOINC(mbar) \
    asm volatile("cp.async.mbarrier.arrive.noinc.shared::cta.b64 [%0];" :: "r"(mbar) : "memory")
#define TC_ALLOC(slot, n)  asm volatile("tcgen05.alloc.cta_group::1.sync.aligned.shared::cta.b32 [%0], %1;" :: "r"(slot), "r"(n) : "memory")
#define TC_DEALLOC(t, n)   asm volatile("tcgen05.dealloc.cta_group::1.sync.aligned.b32 %0, %1;" :: "r"(t), "r"(n))
#define TC_RELINQ()        asm volatile("tcgen05.relinquish_alloc_permit.cta_group::1.sync.aligned;")
#define TC_COMMIT(mbar)    asm volatile("tcgen05.commit.cta_group::1.mbarrier::arrive::one.shared::cluster.b64 [%0];" :: "r"(mbar) : "memory")
#define TC_WAIT_LD()       asm volatile("tcgen05.wait::ld.sync.aligned;" ::: "memory")
#define TC_FENCE_AFTER()   asm volatile("tcgen05.fence::after_thread_sync;" ::: "memory")
#define FENCE_ASYNC_SH()   asm volatile("fence.proxy.async.shared::cta;" ::: "memory")
#define TC_LD_X32(r, addr) \
    asm volatile("tcgen05.ld.sync.aligned.32x32b.x32.b32 " \
        "{%0,%1,%2,%3,%4,%5,%6,%7,%8,%9,%10,%11,%12,%13,%14,%15," \
        "%16,%17,%18,%19,%20,%21,%22,%23,%24,%25,%26,%27,%28,%29,%30,%31}, [%32];" \
        : "=r"((r)[0]),"=r"((r)[1]),"=r"((r)[2]),"=r"((r)[3]),"=r"((r)[4]),"=r"((r)[5]),"=r"((r)[6]),"=r"((r)[7]), \
          "=r"((r)[8]),"=r"((r)[9]),"=r"((r)[10]),"=r"((r)[11]),"=r"((r)[12]),"=r"((r)[13]),"=r"((r)[14]),"=r"((r)[15]), \
          "=r"((r)[16]),"=r"((r)[17]),"=r"((r)[18]),"=r"((r)[19]),"=r"((r)[20]),"=r"((r)[21]),"=r"((r)[22]),"=r"((r)[23]), \
          "=r"((r)[24]),"=r"((r)[25]),"=r"((r)[26]),"=r"((r)[27]),"=r"((r)[28]),"=r"((r)[29]),"=r"((r)[30]),"=r"((r)[31]) \
        : "r"(addr))
// SW128 K-major: layout=2, SBO=64, LBO=1
static constexpr uint64_t SMEM_DESC_SW128 =
    (uint64_t(2) << 61) | (uint64_t(1) << 46) | (uint64_t(64) << 32) | (uint64_t(1) << 16);
// SW64 K-major: layout=4, SBO=32, LBO=1 (atom = 8 rows x 64B)
static constexpr uint64_t SMEM_DESC_SW64 =
    (uint64_t(4) << 61) | (uint64_t(1) << 46) | (uint64_t(32) << 32) | (uint64_t(1) << 16);
__device__ __forceinline__ uint64_t make_desc(uint32_t addr) {
    return SMEM_DESC_SW128 | ((uint64_t)(addr >> 4) & 0x3FFF);
}
__device__ __forceinline__ uint64_t make_desc64(uint32_t addr) {
    return SMEM_DESC_SW64 | ((uint64_t)(addr >> 4) & 0x3FFF);
}
__device__ __forceinline__ void mma_f16_ss(uint32_t d, uint64_t a, uint64_t b,
                                           uint32_t idesc, uint32_t en) {
    asm volatile("{ .reg .pred p; setp.ne.u32 p, %4, 0;"
                 "tcgen05.mma.cta_group::1.kind::f16 [%0], %1, %2, %3, {%5,%5,%5,%5}, p; }"
                 :: "r"(d), "l"(a), "l"(b), "r"(idesc), "r"(en), "r"(0u) : "memory");
}
#endif

// ---------------- K1: per-point preamble MLP -> p ----------------------------
__global__ void k1_preamble(const float* __restrict__ pos, const float* __restrict__ t,
                            const float* __restrict__ sph_proj,
                            const float* __restrict__ tb1, const float* __restrict__ tb2,
                            const float* __restrict__ gn1, const float* __restrict__ gw1,
                            const float* __restrict__ gn2, const float* __restrict__ gw2,
                            const float* __restrict__ gn3, const float* __restrict__ gw3)
{
    int i = blockIdx.x * blockDim.x + threadIdx.x;
    if (i >= NPTS) return;

    float x = pos[i * 3 + 0], y = pos[i * 3 + 1], z = pos[i * 3 + 2];
    float rho = sqrtf(x * x + y * y + z * z);
    float phi = atan2f(y, x);
    float cz = z / rho;
    cz = fminf(1.0f, fmaxf(-1.0f, cz));
    float theta = acosf(cz);

    float h[12];
#pragma unroll
    for (int j = 0; j < 8; j++)
        h[j] = rho * sph_proj[j] + phi * sph_proj[8 + j] + theta * sph_proj[16 + j];
    float tv = t[i];
    float ct = cosf(tv + tb1[0]);
    float st = sinf(tv + tb2[0]);
    h[8] = ct; h[9] = st;
    h[10] = ct * sigmoidf_(ct);
    h[11] = st * sigmoidf_(st);

    float ss = 0.f;
#pragma unroll
    for (int j = 0; j < 12; j++) ss += h[j] * h[j];
    float sc = 1.0f / (sqrtf(ss / 12.0f) + 1e-8f);
    float hn[12];
#pragma unroll
    for (int j = 0; j < 12; j++) hn[j] = gn1[j] * h[j] * sc;
    float y1[32];
#pragma unroll
    for (int j = 0; j < 32; j++) y1[j] = 0.f;
#pragma unroll
    for (int r = 0; r < 12; r++) {
        float a = hn[r];
#pragma unroll
        for (int j = 0; j < 32; j++) y1[j] += a * gw1[r * 32 + j];
    }
    float h2[16];
#pragma unroll
    for (int k = 0; k < 16; k++) h2[k] = y1[k] * gelu_tanh(y1[16 + k]);

    ss = 0.f;
#pragma unroll
    for (int j = 0; j < 16; j++) ss += h2[j] * h2[j];
    sc = 1.0f / (sqrtf(ss / 16.0f) + 1e-8f);
    float hn2[16];
#pragma unroll
    for (int j = 0; j < 16; j++) hn2[j] = gn2[j] * h2[j] * sc;
    float y2[32];
#pragma unroll
    for (int j = 0; j < 32; j++) y2[j] = 0.f;
#pragma unroll
    for (int r = 0; r < 16; r++) {
        float a = hn2[r];
#pragma unroll
        for (int j = 0; j < 32; j++) y2[j] += a * gw2[r * 32 + j];
    }
    float h3[16];
#pragma unroll
    for (int k = 0; k < 16; k++) h3[k] = y2[k] * gelu_tanh(y2[16 + k]);

    ss = 0.f;
#pragma unroll
    for (int j = 0; j < 16; j++) ss += h3[j] * h3[j];
    sc = 1.0f / (sqrtf(ss / 16.0f) + 1e-8f);
    float z3[3] = {0.f, 0.f, 0.f};
#pragma unroll
    for (int r = 0; r < 16; r++) {
        float a = gn3[r] * h3[r] * sc;
#pragma unroll
        for (int j = 0; j < 3; j++) z3[j] += a * gw3[r * 3 + j];
    }
    g_p[i * 3 + 0] = sigmoidf_(z3[0]);
    g_p[i * 3 + 1] = sigmoidf_(z3[1]);
    g_p[i * 3 + 2] = sigmoidf_(z3[2]);
}

// ---------------- K2m: fused gather + convW(fp16) + convW2 --------------------
__global__ void __launch_bounds__(256) k2m(const float* __restrict__ t,
                          const float* __restrict__ table0, const float* __restrict__ table1,
                          const float* __restrict__ table2, const float* __restrict__ table3,
                          const float* __restrict__ st1, const float* __restrict__ st2,
                          const float* __restrict__ tf, const float* __restrict__ vn1,
                          const float* __restrict__ vw1, const float* __restrict__ vw2,
                          const float* __restrict__ vn2)
{
    int bid = blockIdx.x;
    __shared__ const float* segp[47];
    __shared__ __align__(16) float red[256];
    __shared__ float sh[32][33];

    if (bid < NPTS) {
        int i = bid;
        float p0 = g_p[i * 3 + 0], p1 = g_p[i * 3 + 1], p2 = g_p[i * 3 + 2];
        float tt = t[i];

        int s = threadIdx.x;
        if (s < 47) {
            const float* base = nullptr;
            if (s < 28) {
                int tb = s / 7;
                int o = s % 7;
                int d, F; const float* T;
                if (tb == 0)      { d = 128; F = 16;  T = table0; }
                else if (tb == 1) { d = 64;  F = 32;  T = table1; }
                else if (tb == 2) { d = 32;  F = 64;  T = table2; }
                else              { d = 16;  F = 128; T = table3; }
                int ix = (int)(p0 * (float)(d - 1));
                int iy = (int)(p1 * (float)(d - 1));
                int iz = (int)(p2 * (float)(d - 1));
                if (o > 0) {
                    ix = wrapi(ix + FACE3[o - 1][0], d);
                    iy = wrapi(iy + FACE3[o - 1][1], d);
                    iz = wrapi(iz + FACE3[o - 1][2], d);
                }
                base = T + (size_t)((ix * d + iy) * d + iz) * F;
            } else if (s < 46) {
                int grp = (s - 28) / 9;
                int o = (s - 28) % 9;
                if (grp == 0) {
                    int a = (int)(p0 * 15.0f), b = (int)(p1 * 15.0f),
                        c = (int)(p2 * 15.0f), e = (int)(tt * 63.0f);
                    if (o > 0) {
                        a = wrapi(a + ST8[o - 1][0], 16);
                        b = wrapi(b + ST8[o - 1][1], 16);
                        c = wrapi(c + ST8[o - 1][2], 16);
                        e = wrapi(e + ST8[o - 1][3], 64);
                    }
                    base = st1 + (size_t)(((a * 16 + b) * 16 + c) * 64 + e) * 64;
                } else {
                    int a = (int)(p0 * 63.0f), b = (int)(p1 * 63.0f),
                        c = (int)(p2 * 31.0f), e = (int)(tt * 15.0f);
                    if (o > 0) {
                        a = wrapi(a + ST8[o - 1][0], 64);
                        b = wrapi(b + ST8[o - 1][1], 64);
                        c = wrapi(c + ST8[o - 1][2], 32);
                        e = wrapi(e + ST8[o - 1][3], 16);
                    }
                    base = st2 + (size_t)(((a * 64 + b) * 32 + c) * 16 + e) * 8;
                }
            } else {
                int a = (int)(p0 * 3.0f), b = (int)(p1 * 3.0f),
                    c = (int)(p2 * 3.0f), e = (int)(tt * 65535.0f);
                base = tf + (size_t)(((a * 4 + b) * 4 + c) * 65536 + e) * 8;
            }
            segp[s] = base;
        }
        __syncthreads();

        float4 v0[2], v1[2];
        float ss = 0.f;
#pragma unroll
        for (int gi = 0; gi < 2; gi++) {
            int g = threadIdx.x + gi * 256;
            if (g < NGRP) {
                int f0 = g * 8;
                int seg, off;
                if (f0 < 112)       { seg = f0 >> 4;                 off = f0 & 15; }
                else if (f0 < 336)  { int q = f0 - 112;  seg = 7  + (q >> 5); off = q & 31; }
                else if (f0 < 784)  { int q = f0 - 336;  seg = 14 + (q >> 6); off = q & 63; }
                else if (f0 < 1680) { int q = f0 - 784;  seg = 21 + (q >> 7); off = q & 127; }
                else if (f0 < 2256) { int q = f0 - 1680; seg = 28 + (q >> 6); off = q & 63; }
                else if (f0 < 2328) { int q = f0 - 2256; seg = 37 + (q >> 3); off = q & 7; }
                else                { seg = 46;                      off = f0 - 2328; }
                const float* sp = segp[seg] + off;
                float4 a = *(const float4*)sp;
                float4 b = *(const float4*)(sp + 4);
                v0[gi] = a; v1[gi] = b;
                ss += a.x * a.x + a.y * a.y + a.z * a.z + a.w * a.w
                    + b.x * b.x + b.y * b.y + b.z * b.z + b.w * b.w;
            }
        }
        red[threadIdx.x] = ss;
        __syncthreads();
        for (int w = 128; w > 0; w >>= 1) {
            if (threadIdx.x < w) red[threadIdx.x] += red[threadIdx.x + w];
            __syncthreads();
        }
        float rms = sqrtf(red[0] / (float)TOTAL);
        float sc = 1.0f / (rms + 1e-8f);
        __half* orow = g_Abf + (size_t)i * AW1;
#pragma unroll
        for (int gi = 0; gi < 2; gi++) {
            int g = threadIdx.x + gi * 256;
            if (g < NGRP) {
                int f0 = g * 8;
                float4 n0 = *(const float4*)&vn1[f0];
                float4 n1 = *(const float4*)&vn1[f0 + 4];
                float v[8] = { v0[gi].x * n0.x * sc, v0[gi].y * n0.y * sc,
                               v0[gi].z * n0.z * sc, v0[gi].w * n0.w * sc,
                               v1[gi].x * n1.x * sc, v1[gi].y * n1.y * sc,
                               v1[gi].z * n1.z * sc, v1[gi].w * n1.w * sc };
                uint32_t hi[4], lo[4];
#pragma unroll
                for (int j = 0; j < 4; j++) {
                    __half h0 = __float2half(v[2 * j]);
                    __half h1 = __float2half(v[2 * j + 1]);
                    __half l0 = __float2half(v[2 * j] - __half2float(h0));
                    __half l1 = __float2half(v[2 * j + 1] - __half2float(h1));
                    hi[j] = (uint32_t)(*(unsigned short*)&h0) | ((uint32_t)(*(unsigned short*)&h1) << 16);
                    lo[j] = (uint32_t)(*(unsigned short*)&l0) | ((uint32_t)(*(unsigned short*)&l1) << 16);
                }
                int blk = f0 >> 5, pos = f0 & 31;
                *(uint4*)(orow + blk * 64 + pos)      = make_uint4(hi[0], hi[1], hi[2], hi[3]);
                *(uint4*)(orow + blk * 64 + 32 + pos) = make_uint4(lo[0], lo[1], lo[2], lo[3]);
            }
        }
    } else if (bid < NPTS + CWBLK) {
        int b2 = bid - NPTS;
        int n0 = (b2 % 152) * 32, k0 = (b2 / 152) * 32;
        int tx = threadIdx.x & 31, ty = threadIdx.x >> 5;
        int tile = n0 >> 8, half = (n0 >> 7) & 1;
        int f0 = tile * 128 + (n0 & 127);
#pragma unroll
        for (int ii = 0; ii < 4; ii++) {
            int r = ty + ii * 8;
            int k = k0 + r;
            int f = f0 + tx;
            float v = 0.f;
            if (f < TOTAL && k < TOTAL)
                v = vw1[(size_t)k * TWOTOTAL + half * TOTAL + f];
            sh[r][tx] = v;
        }
        __syncthreads();
#pragma unroll
        for (int ii = 0; ii < 4; ii++) {
            int r = ty + ii * 8;
            int n = n0 + r;
            g_WT[(size_t)n * WTS + (k0 + tx)] = __float2half(sh[tx][r]);
        }
    } else {
        int idx = (bid - NPTS - CWBLK) * 256 + threadIdx.x;
        if (idx < TOTAL * 64) {
            int k = idx >> 6, n = idx & 63;
            float v = vn2[k] * vw2[idx];
            __nv_bfloat16 h = __float2bfloat16(v);
            float hf = __bfloat162float(h);
            __nv_bfloat16 l = __float2bfloat16(v - hf);
            size_t base = (size_t)n * VW + (size_t)((k >> 5) * 64);
            g_WT2[base + (k & 31)] = h;
            g_WT2[base + 32 + (k & 31)] = l;
        }
    }
}

// ---------------- K3: warp-specialized fp16 GEMM1, 3-buffer, SW64 W -----------
// Stage = 32 logical k: A 32KB (SW128 [hi|lo] rows) + W 16KB (SW64 64B rows).
#define STG1 49152
#define SMEM1 (1024 + 3 * STG1)

__global__ void __launch_bounds__(256, 1) k3_gemm1(const __half* __restrict__ Abf,
                                                   const __half* __restrict__ WT,
                                                   __nv_bfloat16* __restrict__ Vbf,
                                                   float* __restrict__ sspart)
{
    extern __shared__ char smem[];
    uint32_t sbase = smem_u32(smem);
    int tid = threadIdx.x;
    int wid = tid >> 5, lid = tid & 31;
    int tile = blockIdx.x;
    int bm = blockIdx.y * 256;
    int bn = tile * 256;

#if defined(__CUDA_ARCH_FEAT_SM103_ALL)
    const uint32_t TSLOT = sbase;
    const uint32_t FUL0 = sbase + 16, FUL1 = sbase + 24, FUL2 = sbase + 32;
    const uint32_t EMP0 = sbase + 40, EMP1 = sbase + 48, EMP2 = sbase + 56;
    const uint32_t DONE = sbase + 64;
    const uint32_t SDATA = sbase + 1024;

    if (wid == 0) TC_ALLOC(TSLOT, 512);
    if (tid == 0) {
        MBARRIER_INIT(FUL0, 224); MBARRIER_INIT(FUL1, 224); MBARRIER_INIT(FUL2, 224);
        MBARRIER_INIT(EMP0, 1);   MBARRIER_INIT(EMP1, 1);   MBARRIER_INIT(EMP2, 1);
        MBARRIER_INIT(DONE, 1);
    }
    __syncthreads();
    uint32_t tmem;
    asm volatile("ld.shared.b32 %0, [%1];" : "=r"(tmem) : "r"(TSLOT));

    // fp16 inputs: atype=btype=F16=0; dtype F32; N=256; M=128
    const uint32_t IDESC = (1u << 4) | (32u << 17) | (8u << 24);

    if (wid >= 1) {
        // producers: warps 1-7 (224 threads); 3072 copies/stage
        int ptid = tid - 32;
        int pe0 = 1, pe1 = 1, pe2 = 1;
        const __half* Abase = Abf + (size_t)bm * AW1;
        const __half* Wbase = WT + (size_t)bn * WTS;
        for (int s = 0; s < NST1; s++) {
            int b = s % 3;
            uint32_t emp = (b == 0) ? EMP0 : (b == 1) ? EMP1 : EMP2;
            uint32_t ful = (b == 0) ? FUL0 : (b == 1) ? FUL1 : FUL2;
            if (b == 0)      { MBARRIER_WAIT_PARITY(emp, pe0); pe0 ^= 1; }
            else if (b == 1) { MBARRIER_WAIT_PARITY(emp, pe1); pe1 ^= 1; }
            else             { MBARRIER_WAIT_PARITY(emp, pe2); pe2 ^= 1; }
            uint32_t ab = SDATA + b * STG1;
            int ka = s * 64;           // A phys elems per stage: one [hi|lo] block
            int kw = s * 32;           // W elems per stage
            for (int idx = ptid; idx < 3072; idx += 224) {
                if (idx < 2048) {
                    // A: 256 rows x 8 vec16 (128B rows, SW128)
                    int r = idx >> 3, c = idx & 7;
                    uint32_t off = (uint32_t)(r * 128 + c * 16);
                    uint32_t sw = off ^ ((off >> 3) & 0x70);
                    CP_ASYNC16(ab + sw, (const void*)(Abase + (size_t)r * AW1 + ka + c * 8));
                } else {
                    // W: 256 rows x 4 vec16 (64B rows, SW64)
                    int q = idx - 2048;
                    int r = q >> 2, c = q & 3;
                    uint32_t off = (uint32_t)(r * 64 + c * 16);
                    uint32_t sw = off ^ ((off >> 3) & 0x30);
                    CP_ASYNC16(ab + 32768 + sw, (const void*)(Wbase + (size_t)r * WTS + kw + c * 8));
                }
            }
            CPA_MBAR_ARRIVE_NOINC(ful);
        }
    } else if (elect_one()) {
        // consumer
        int pf0 = 0, pf1 = 0, pf2 = 0;
        for (int s = 0; s < NST1; s++) {
            int b = s % 3;
            uint32_t ful = (b == 0) ? FUL0 : (b == 1) ? FUL1 : FUL2;
            uint32_t emp = (b == 0) ? EMP0 : (b == 1) ? EMP1 : EMP2;
            if (b == 0)      { MBARRIER_WAIT_PARITY(ful, pf0); pf0 ^= 1; }
            else if (b == 1) { MBARRIER_WAIT_PARITY(ful, pf1); pf1 ^= 1; }
            else             { MBARRIER_WAIT_PARITY(ful, pf2); pf2 ^= 1; }
            FENCE_ASYNC_SH();
            uint32_t ab = SDATA + b * STG1;
            uint64_t wd = make_desc64(ab + 32768);
#pragma unroll
            for (int half = 0; half < 2; half++) {
                uint64_t ad = make_desc(ab + half * 16384);
                uint32_t dt = tmem + half * 256;
                uint32_t en0 = (s > 0) ? 1u : 0u;
                // hi x W (k 0-15, 16-31), then lo x W
                mma_f16_ss(dt, ad + 0, wd + 0, IDESC, en0);
                mma_f16_ss(dt, ad + 2, wd + 2, IDESC, 1u);
                mma_f16_ss(dt, ad + 4, wd + 0, IDESC, 1u);
                mma_f16_ss(dt, ad + 6, wd + 2, IDESC, 1u);
            }
            TC_COMMIT(emp);
        }
        TC_COMMIT(DONE);
    }
    MBARRIER_WAIT_PARITY(DONE, 0);
    TC_FENCE_AFTER();

    // fused epilogue: a = cols 0-127, g = cols 128-255 -> v = a*gelu(g)
    {
        int m = bm + ((wid < 4) ? 0 : 128) + (wid & 3) * 32 + lid;
        uint32_t dbase = tmem + ((wid < 4) ? 0 : 256);
        float ssacc = 0.f;
#pragma unroll
        for (int cp = 0; cp < 4; cp++) {
            uint32_t ra[32], rg[32];
            TC_LD_X32(ra, dbase + cp * 32);
            TC_LD_X32(rg, dbase + 128 + cp * 32);
            TC_WAIT_LD();
            uint32_t o[32];
#pragma unroll
            for (int j = 0; j < 32; j += 2) {
                float a0 = __uint_as_float(ra[j]),     a1 = __uint_as_float(ra[j + 1]);
                float g0 = __uint_as_float(rg[j]),     g1 = __uint_as_float(rg[j + 1]);
                float v0 = a0 * gelu_tanh(g0), v1 = a1 * gelu_tanh(g1);
                ssacc += v0 * v0 + v1 * v1;
                __nv_bfloat16 h0 = __float2bfloat16(v0);
                __nv_bfloat16 h1 = __float2bfloat16(v1);
                __nv_bfloat16 l0 = __float2bfloat16(v0 - __bfloat162float(h0));
                __nv_bfloat16 l1 = __float2bfloat16(v1 - __bfloat162float(h1));
                unsigned short uh0 = *(unsigned short*)&h0, uh1 = *(unsigned short*)&h1;
                unsigned short ul0 = *(unsigned short*)&l0, ul1 = *(unsigned short*)&l1;
                o[j >> 1]        = (uint32_t)uh0 | ((uint32_t)uh1 << 16);
                o[16 + (j >> 1)] = (uint32_t)ul0 | ((uint32_t)ul1 << 16);
            }
            int fb = tile * 4 + cp;
            uint4* dst = (uint4*)(Vbf + (size_t)m * VW + fb * 64);
#pragma unroll
            for (int q = 0; q < 8; q++)
                dst[q] = make_uint4(o[4 * q], o[4 * q + 1], o[4 * q + 2], o[4 * q + 3]);
        }
        sspart[(size_t)m * NTILES + tile] = ssacc;
    }
    __syncthreads();
    if (wid == 0) {
        TC_RELINQ();
        TC_DEALLOC(tmem, 512);
    }
#else
    // ---- FFMA fallback (generic pass; never selected on sm_103a) ----
    float* Da   = (float*)smem;
    float* As   = Da + 128 * 128;
    float* Bs   = As + 16 * 128;
    float* ssrd = Bs + 16 * 128;
    int tx = tid % 16, ty = tid / 16;
    for (int pass = 0; pass < 2; pass++) {
        int pm = bm + pass * 128;
        for (int half = 0; half < 2; half++) {
            int pn = bn + half * 128;
            float acc[8][8];
#pragma unroll
            for (int a = 0; a < 8; a++)
#pragma unroll
                for (int b = 0; b < 8; b++) acc[a][b] = 0.f;
            for (int k0 = 0; k0 < KPAD1; k0 += 16) {
                __syncthreads();
                for (int idx = tid; idx < 2048; idx += 256) {
                    int row = idx >> 4, kk = idx & 15;
                    int k = k0 + kk;
                    size_t pb = (size_t)(k >> 5) * 64 + (k & 31);
                    const __half* ar = Abf + (size_t)(pm + row) * AW1 + pb;
                    As[kk * 128 + row] = __half2float(ar[0]) + __half2float(ar[32]);
                    Bs[kk * 128 + row] = __half2float(WT[(size_t)(pn + row) * WTS + k]);
                }
                __syncthreads();
#pragma unroll
                for (int k = 0; k < 16; k++) {
                    float af[8], bf[8];
#pragma unroll
                    for (int a = 0; a < 8; a++) af[a] = As[k * 128 + ty * 8 + a];
#pragma unroll
                    for (int b = 0; b < 8; b++) bf[b] = Bs[k * 128 + tx * 8 + b];
#pragma unroll
                    for (int a = 0; a < 8; a++)
#pragma unroll
                        for (int b = 0; b < 8; b++) acc[a][b] += af[a] * bf[b];
                }
            }
            __syncthreads();
            if (half == 0) {
#pragma unroll
                for (int a = 0; a < 8; a++)
#pragma unroll
                    for (int b = 0; b < 8; b++)
                        Da[(ty * 8 + a) * 128 + tx * 8 + b] = acc[a][b];
            } else {
#pragma unroll
                for (int a = 0; a < 8; a++) {
                    int row = ty * 8 + a;
                    float ssp = 0.f;
#pragma unroll
                    for (int b = 0; b < 8; b++) {
                        int col = tx * 8 + b;
                        float av = Da[row * 128 + col];
                        float v = av * gelu_tanh(acc[a][b]);
                        ssp += v * v;
                        __nv_bfloat16 h = __float2bfloat16(v);
                        __nv_bfloat16 l = __float2bfloat16(v - __bfloat162float(h));
                        int f = tile * 128 + col;
                        int fb = f >> 5, pos = f & 31;
                        Vbf[(size_t)(pm + row) * VW + fb * 64 + pos] = h;
                        Vbf[(size_t)(pm + row) * VW + fb * 64 + 32 + pos] = l;
                    }
                    ssrd[row * 16 + tx] = ssp;
                }
            }
            __syncthreads();
        }
        if (tid < 128) {
            float sm = 0.f;
            for (int j = 0; j < 16; j++) sm += ssrd[tid * 16 + j];
            sspart[(size_t)(pm + tid) * NTILES + tile] = sm;
        }
        __syncthreads();
    }
#endif
}

// ---------------- K5: GEMM2 (bf16 3-term) + fused row-scale + final linear ----
#define SMEM5 (1024 + 3 * 24576)
__global__ void __launch_bounds__(256, 2) k5_gemm2(const __nv_bfloat16* __restrict__ Vbf,
                                                   const __nv_bfloat16* __restrict__ WT2,
                                                   const float* __restrict__ t,
                                                   const float* __restrict__ fw,
                                                   const float* __restrict__ fbias,
                                                   const float* __restrict__ sspart,
                                                   float* __restrict__ out)
{
    extern __shared__ char smem[];
    uint32_t sbase = smem_u32(smem);
    int tid = threadIdx.x;
    int wid = tid >> 5, lid = tid & 31;
    int bm = blockIdx.x * 128;

#if defined(__CUDA_ARCH_FEAT_SM103_ALL)
    const uint32_t TSLOT = sbase;
    const uint32_t MB0 = sbase + 16;
    const uint32_t MB1 = sbase + 24;
    const uint32_t MB2 = sbase + 32;
    const uint32_t SDATA = sbase + 1024;

    if (wid == 0) TC_ALLOC(TSLOT, 64);
    if (tid == 0) { MBARRIER_INIT(MB0, 1); MBARRIER_INIT(MB1, 1); MBARRIER_INIT(MB2, 1); }
    __syncthreads();
    uint32_t tmem;
    asm volatile("ld.shared.b32 %0, [%1];" : "=r"(tmem) : "r"(TSLOT));

    const uint32_t IDESC = (1u << 4) | (1u << 7) | (1u << 10) | (8u << 17) | (8u << 24);

    auto load_stage = [&](int s) {
        int buf = s % 3;
        int ks = s * 64;
        uint32_t ab = SDATA + buf * 24576;
        uint32_t wb = ab + 16384;
        const __nv_bfloat16* Asrc = Vbf + (size_t)bm * VW + ks;
        const __nv_bfloat16* Wsrc = WT2 + ks;
#pragma unroll
        for (int j = 0; j < 4; j++) {
            int idx = tid + j * 256;
            int row = idx >> 3, c = idx & 7;
            uint32_t off = (uint32_t)(row * 128 + c * 16);
            uint32_t sw = off ^ ((off >> 3) & 0x70);
            CP_ASYNC16(ab + sw, (const void*)(Asrc + (size_t)row * VW + c * 8));
        }
#pragma unroll
        for (int j = 0; j < 2; j++) {
            int idx = tid + j * 256;
            int row = idx >> 3, c = idx & 7;
            uint32_t off = (uint32_t)(row * 128 + c * 16);
            uint32_t sw = off ^ ((off >> 3) & 0x70);
            CP_ASYNC16(wb + sw, (const void*)(Wsrc + (size_t)row * VW + c * 8));
        }
        CP_COMMIT();
    };

    int ph0 = 0, ph1 = 0, ph2 = 0;
    load_stage(0);
    load_stage(1);
    for (int s = 0; s < NST2; s++) {
        if (s + 2 < NST2) {
            if (s >= 1) {
                int b = (s - 1) % 3;
                if (b == 0)      { MBARRIER_WAIT_PARITY(MB0, ph0); ph0 ^= 1; }
                else if (b == 1) { MBARRIER_WAIT_PARITY(MB1, ph1); ph1 ^= 1; }
                else             { MBARRIER_WAIT_PARITY(MB2, ph2); ph2 ^= 1; }
            }
            load_stage(s + 2);
        }
        if (s + 2 < NST2)      CP_WAIT2();
        else if (s + 1 < NST2) CP_WAIT1();
        else                   CP_WAIT0();
        __syncthreads();
        FENCE_ASYNC_SH();
        if (wid == 0) {
            if (elect_one()) {
                int buf = s % 3;
                uint32_t ab = SDATA + buf * 24576;
                uint64_t ad = make_desc(ab);
                uint64_t bd = make_desc(ab + 16384);
                uint32_t en0 = (s > 0) ? 1u : 0u;
                mma_f16_ss(tmem, ad + 0, bd + 0, IDESC, en0);
                mma_f16_ss(tmem, ad + 2, bd + 2, IDESC, 1u);
                mma_f16_ss(tmem, ad + 4, bd + 0, IDESC, 1u);
                mma_f16_ss(tmem, ad + 6, bd + 2, IDESC, 1u);
                mma_f16_ss(tmem, ad + 0, bd + 4, IDESC, 1u);
                mma_f16_ss(tmem, ad + 2, bd + 6, IDESC, 1u);
                if (buf == 0) TC_COMMIT(MB0);
                else if (buf == 1) TC_COMMIT(MB1);
                else TC_COMMIT(MB2);
            }
        }
    }
    {
        int b = (NST2 - 1) % 3;   // 75 % 3 = 0
        if (b == 0)      MBARRIER_WAIT_PARITY(MB0, ph0);
        else if (b == 1) MBARRIER_WAIT_PARITY(MB1, ph1);
        else             MBARRIER_WAIT_PARITY(MB2, ph2);
    }
    TC_FENCE_AFTER();

    if (wid < 4) {
        int m = bm + wid * 32 + lid;
        uint32_t r[32], r2[32];
        TC_LD_X32(r, tmem);
        TC_LD_X32(r2, tmem + 32);
        TC_WAIT_LD();

        const float* sp = sspart + (size_t)m * NTILES;
        float ss = 0.f;
#pragma unroll
        for (int q = 0; q < NTILES; q++) ss += sp[q];
        float sc = 1.0f / (sqrtf(ss / (float)TOTAL) + 1e-8f);

        float o0 = 0.f, o1 = 0.f, o2 = 0.f, o3 = 0.f;
#pragma unroll
        for (int q = 0; q < 32; q++) {
            float a = __uint_as_float(r[q]);
            o0 += a * fw[q * 4 + 0]; o1 += a * fw[q * 4 + 1];
            o2 += a * fw[q * 4 + 2]; o3 += a * fw[q * 4 + 3];
        }
#pragma unroll
        for (int q = 0; q < 32; q++) {
            float a = __uint_as_float(r2[q]);
            o0 += a * fw[(32 + q) * 4 + 0]; o1 += a * fw[(32 + q) * 4 + 1];
            o2 += a * fw[(32 + q) * 4 + 2]; o3 += a * fw[(32 + q) * 4 + 3];
        }
        o0 *= sc; o1 *= sc; o2 *= sc; o3 *= sc;
        o0 += fbias[0]; o1 += fbias[1]; o2 += fbias[2]; o3 += fbias[3];
        float p0 = g_p[m * 3 + 0], p1 = g_p[m * 3 + 1], p2 = g_p[m * 3 + 2];
        float tv = t[m];
        o0 += p0 * fw[256 + 0] + p1 * fw[260 + 0] + p2 * fw[264 + 0] + tv * fw[268 + 0];
        o1 += p0 * fw[256 + 1] + p1 * fw[260 + 1] + p2 * fw[264 + 1] + tv * fw[268 + 1];
        o2 += p0 * fw[256 + 2] + p1 * fw[260 + 2] + p2 * fw[264 + 2] + tv * fw[268 + 2];
        o3 += p0 * fw[256 + 3] + p1 * fw[260 + 3] + p2 * fw[264 + 3] + tv * fw[268 + 3];
        *(float4*)(out + (size_t)m * 4) = make_float4(o0, o1, o2, o3);
    }
    __syncthreads();
    if (wid == 0) {
        TC_RELINQ();
        TC_DEALLOC(tmem, 64);
    }
#else
    // ---- FFMA fallback (256 threads) ----
    float* Ds = (float*)smem;
    float* Bs = Ds + 64 * 64;
    for (int m0 = 0; m0 < 128; m0 += 64) {
        int mrow = (tid >> 2);
        int m = bm + m0 + mrow;
        int nq = (tid & 3) * 16;
        float acc[16];
#pragma unroll
        for (int a = 0; a < 16; a++) acc[a] = 0.f;
        for (int k0 = 0; k0 < KPAD2; k0 += 16) {
            __syncthreads();
            for (int idx = tid; idx < 1024; idx += 256) {
                int kk = idx >> 6, n = idx & 63;
                int k = k0 + kk;
                const __nv_bfloat16* wr = WT2 + (size_t)n * VW + (size_t)(k >> 5) * 64 + (k & 31);
                Bs[kk * 64 + n] = __bfloat162float(wr[0]) + __bfloat162float(wr[32]);
            }
            __syncthreads();
#pragma unroll
            for (int kk = 0; kk < 16; kk++) {
                int k = k0 + kk;
                const __nv_bfloat16* ar = Vbf + (size_t)m * VW + (size_t)(k >> 5) * 64 + (k & 31);
                float av = __bfloat162float(ar[0]) + __bfloat162float(ar[32]);
#pragma unroll
                for (int a = 0; a < 16; a++) acc[a] += av * Bs[kk * 64 + nq + a];
            }
        }
        __syncthreads();
        for (int a = 0; a < 16; a++) Ds[mrow * 64 + nq + a] = acc[a];
        __syncthreads();
        if (tid < 64) {
            int m2 = bm + m0 + tid;
            const float* sp = sspart + (size_t)m2 * NTILES;
            float ss = 0.f;
            for (int q = 0; q < NTILES; q++) ss += sp[q];
            float sc = 1.0f / (sqrtf(ss / (float)TOTAL) + 1e-8f);
            float o0 = 0.f, o1 = 0.f, o2 = 0.f, o3 = 0.f;
            for (int q = 0; q < 64; q++) {
                float a = Ds[tid * 64 + q];
                o0 += a * fw[q * 4 + 0]; o1 += a * fw[q * 4 + 1];
                o2 += a * fw[q * 4 + 2]; o3 += a * fw[q * 4 + 3];
            }
            o0 *= sc; o1 *= sc; o2 *= sc; o3 *= sc;
            o0 += fbias[0]; o1 += fbias[1]; o2 += fbias[2]; o3 += fbias[3];
            float p0 = g_p[m2 * 3 + 0], p1 = g_p[m2 * 3 + 1], p2 = g_p[m2 * 3 + 2];
            float tv = t[m2];
            o0 += p0 * fw[256 + 0] + p1 * fw[260 + 0] + p2 * fw[264 + 0] + tv * fw[268 + 0];
            o1 += p0 * fw[256 + 1] + p1 * fw[260 + 1] + p2 * fw[264 + 1] + tv * fw[268 + 1];
            o2 += p0 * fw[256 + 2] + p1 * fw[260 + 2] + p2 * fw[264 + 2] + tv * fw[268 + 2];
            o3 += p0 * fw[256 + 3] + p1 * fw[260 + 3] + p2 * fw[264 + 3] + tv * fw[268 + 3];
            *(float4*)(out + (size_t)m2 * 4) = make_float4(o0, o1, o2, o3);
        }
        __syncthreads();
    }
#endif
}

// ---------------- launcher ----------------------------------------------------
extern "C" void kernel_launch(void* const* d_in, const int* in_sizes, int n_in,
                              void* d_out, int out_size)
{
    const float* pos      = (const float*)d_in[0];
    const float* t        = (const float*)d_in[2];
    const float* table0   = (const float*)d_in[3];
    const float* table1   = (const float*)d_in[4];
    const float* table2   = (const float*)d_in[5];
    const float* table3   = (const float*)d_in[6];
    const float* st1      = (const float*)d_in[7];
    const float* st2      = (const float*)d_in[8];
    const float* tf       = (const float*)d_in[9];
    const float* sph_proj = (const float*)d_in[10];
    const float* tb1      = (const float*)d_in[11];
    const float* tb2      = (const float*)d_in[12];
    const float* gn1      = (const float*)d_in[13];
    const float* gw1      = (const float*)d_in[14];
    const float* gn2      = (const float*)d_in[15];
    const float* gw2      = (const float*)d_in[16];
    const float* gn3      = (const float*)d_in[17];
    const float* gw3      = (const float*)d_in[18];
    const float* vn1      = (const float*)d_in[19];
    const float* vw1      = (const float*)d_in[20];
    const float* vn2      = (const float*)d_in[21];
    const float* vw2      = (const float*)d_in[22];
    const float* fw       = (const float*)d_in[23];
    const float* fb       = (const float*)d_in[24];
    float* out = (float*)d_out;

    cudaFuncSetAttribute(k3_gemm1, cudaFuncAttributeMaxDynamicSharedMemorySize, SMEM1);
    cudaFuncSetAttribute(k5_gemm2, cudaFuncAttributeMaxDynamicSharedMemorySize, SMEM5);

    k1_preamble<<<NPTS / 256, 256>>>(pos, t, sph_proj, tb1, tb2,
                                     gn1, gw1, gn2, gw2, gn3, gw3);

    k2m<<<NPTS + CWBLK + CW2BLK, 256>>>(t, table0, table1, table2, table3,
                                        st1, st2, tf, vn1, vw1, vw2, vn2);

    __half* Abf;        cudaGetSymbolAddress((void**)&Abf, g_Abf);
    __nv_bfloat16* Vbf; cudaGetSymbolAddress((void**)&Vbf, g_Vbf);
    __half* WT;         cudaGetSymbolAddress((void**)&WT,  g_WT);
    __nv_bfloat16* WT2; cudaGetSymbolAddress((void**)&WT2, g_WT2);
    float* Sp;          cudaGetSymbolAddress((void**)&Sp,  g_sspart);

    dim3 g1(NTILES, NPTS / 256);          // (19, 128)
    k3_gemm1<<<g1, 256, SMEM1>>>(Abf, WT, Vbf, Sp);

    k5_gemm2<<<NPTS / 128, 256, SMEM5>>>(Vbf, WT2, t, fw, fb, Sp, out);
}

// round 14
// speedup vs baseline: 1.1244x; 1.0198x over previous
#include <cuda_runtime.h>
#include <cuda_bf16.h>
#include <cuda_fp16.h>
#include <math.h>
#include <stdint.h>

#define NPTS 32768
#define TOTAL 2336
#define KPAD1 2368         // GEMM1 K padded (74 stages of 32 logical k)
#define NST1 74
#define KPAD2 2432         // GEMM2 K (76 blocks)
#define NST2 76
#define TWOTOTAL 4672
#define INNER 64
#define AW1 4736           // g_Abf row (fp16): 74 blocks x [hi32|lo32]
#define VW 4864            // g_Vbf / g_WT2 row (bf16): 76 blocks x [hi32|lo32]
#define WTS 2368           // g_WT row (fp16 single): plain k layout
#define WTROWS 4864        // permuted W1 rows (19 tiles x 256)
#define NTILES 19
#define NGRP 292           // TOTAL / 8
#define CWBLK (152 * 74)
#define CW2BLK 584

// ---------------- scratch (static device memory; zero-initialized) -----------
__device__ float g_p[NPTS * 3];
__device__ __align__(128) __half g_Abf[(size_t)NPTS * AW1];          // A fp16 hi/lo
__device__ __align__(128) __nv_bfloat16 g_Vbf[(size_t)NPTS * VW];    // V bf16 hi/lo
__device__ __align__(128) __half g_WT[(size_t)WTROWS * WTS];         // W1 fp16 single
__device__ __align__(128) __nv_bfloat16 g_WT2[(size_t)64 * VW];      // (vn2*vw2)^T bf16 split
__device__ float g_sspart[(size_t)NPTS * NTILES];
__device__ float g_down[NPTS * INNER];     // fallback only

// ---------------- common helpers ---------------------------------------------
__device__ __forceinline__ uint32_t smem_u32(const void* p) {
    uint32_t a;
    asm("{ .reg .u64 t; cvta.to.shared.u64 t, %1; cvt.u32.u64 %0, t; }" : "=r"(a) : "l"(p));
    return a;
}
__device__ __forceinline__ float sigmoidf_(float x) { return 1.0f / (1.0f + expf(-x)); }
// exact gelu (used in k1, feeds index thresholds -> keep precise)
__device__ __forceinline__ float gelu_tanh(float x) {
    float x3 = x * x * x;
    return 0.5f * x * (1.0f + tanhf(0.7978845608028654f * (x + 0.044715f * x3)));
}
// fast gelu (k3 epilogue only; tanh.approx is a single MUFU op, ~1e-5 rel err)
__device__ __forceinline__ float gelu_fast(float x) {
    float x3 = x * x * x;
    float arg = 0.7978845608028654f * (x + 0.044715f * x3);
    float th;
    asm("tanh.approx.f32 %0, %1;" : "=f"(th) : "f"(arg));
    return 0.5f * x * (1.0f + th);
}
__device__ __forceinline__ int wrapi(int v, int d) {
    if (v < 0) v += d; else if (v >= d) v -= d; return v;
}
__device__ const int FACE3[6][3] = {{1,0,0},{-1,0,0},{0,1,0},{0,-1,0},{0,0,1},{0,0,-1}};
__device__ const int ST8[8][4]   = {{1,0,0,0},{-1,0,0,0},{0,1,0,0},{0,-1,0,0},
                                    {0,0,1,0},{0,0,-1,0},{0,0,0,1},{0,0,0,-1}};

// cp.async helpers (baseline PTX)
#define CP_ASYNC16(smem, gmem) \
    asm volatile("cp.async.cg.shared.global [%0], [%1], 16;" :: "r"(smem), "l"(gmem) : "memory")
#define CP_COMMIT() asm volatile("cp.async.commit_group;" ::: "memory")
#define CP_WAIT3()  asm volatile("cp.async.wait_group 3;" ::: "memory")
#define CP_WAIT2()  asm volatile("cp.async.wait_group 2;" ::: "memory")
#define CP_WAIT1()  asm volatile("cp.async.wait_group 1;" ::: "memory")
#define CP_WAIT0()  asm volatile("cp.async.wait_group 0;" ::: "memory")

#if defined(__CUDA_ARCH_FEAT_SM103_ALL)
// ---------------- tcgen05 helpers (sm_103a pass only) -------------------------
__device__ __forceinline__ uint32_t elect_one() {
    uint32_t p;
    asm volatile("{ .reg .pred p; elect.sync _|p, 0xFFFFFFFF; selp.b32 %0,1,0,p; }" : "=r"(p));
    return p;
}
#define MBARRIER_INIT(addr, cnt) \
    asm volatile("mbarrier.init.shared.b64 [%0], %1;" :: "r"(addr), "r"(cnt) : "memory")
#define MBARRIER_WAIT_PARITY(addr, parity) do { \
    uint32_t _m = (addr); uint32_t _p = (parity); uint32_t _d; \
    asm volatile("{ .reg .pred p; mbarrier.try_wait.parity.acquire.cta.shared::cta.b64 p, [%1], %2; selp.b32 %0,1,0,p; }" \
        : "=r"(_d) : "r"(_m), "r"(_p) : "memory"); \
    if (!_d) { \
        asm volatile("{ .reg .pred P1; WL_%=: mbarrier.try_wait.parity.acquire.cta.shared::cta.b64 P1, [%0], %1, 0x989680; @P1 bra.uni WD_%=; bra.uni WL_%=; WD_%=: }" \
            :: "r"(_m), "r"(_p) : "memory"); \
    } } while (0)
#define CPA_MBAR_ARRIVE_NOINC(mbar) \
    asm volatile("cp.async.mbarrier.arrive.noinc.shared::cta.b64 [%0];" :: "r"(mbar) : "memory")
#define TC_ALLOC(slot, n)  asm volatile("tcgen05.alloc.cta_group::1.sync.aligned.shared::cta.b32 [%0], %1;" :: "r"(slot), "r"(n) : "memory")
#define TC_DEALLOC(t, n)   asm volatile("tcgen05.dealloc.cta_group::1.sync.aligned.b32 %0, %1;" :: "r"(t), "r"(n))
#define TC_RELINQ()        asm volatile("tcgen05.relinquish_alloc_permit.cta_group::1.sync.aligned;")
#define TC_COMMIT(mbar)    asm volatile("tcgen05.commit.cta_group::1.mbarrier::arrive::one.shared::cluster.b64 [%0];" :: "r"(mbar) : "memory")
#define TC_WAIT_LD()       asm volatile("tcgen05.wait::ld.sync.aligned;" ::: "memory")
#define TC_FENCE_AFTER()   asm volatile("tcgen05.fence::after_thread_sync;" ::: "memory")
#define FENCE_ASYNC_SH()   asm volatile("fence.proxy.async.shared::cta;" ::: "memory")
#define TC_LD_X32(r, addr) \
    asm volatile("tcgen05.ld.sync.aligned.32x32b.x32.b32 " \
        "{%0,%1,%2,%3,%4,%5,%6,%7,%8,%9,%10,%11,%12,%13,%14,%15," \
        "%16,%17,%18,%19,%20,%21,%22,%23,%24,%25,%26,%27,%28,%29,%30,%31}, [%32];" \
        : "=r"((r)[0]),"=r"((r)[1]),"=r"((r)[2]),"=r"((r)[3]),"=r"((r)[4]),"=r"((r)[5]),"=r"((r)[6]),"=r"((r)[7]), \
          "=r"((r)[8]),"=r"((r)[9]),"=r"((r)[10]),"=r"((r)[11]),"=r"((r)[12]),"=r"((r)[13]),"=r"((r)[14]),"=r"((r)[15]), \
          "=r"((r)[16]),"=r"((r)[17]),"=r"((r)[18]),"=r"((r)[19]),"=r"((r)[20]),"=r"((r)[21]),"=r"((r)[22]),"=r"((r)[23]), \
          "=r"((r)[24]),"=r"((r)[25]),"=r"((r)[26]),"=r"((r)[27]),"=r"((r)[28]),"=r"((r)[29]),"=r"((r)[30]),"=r"((r)[31]) \
        : "r"(addr))
// SW128 K-major: layout=2, SBO=64, LBO=1
static constexpr uint64_t SMEM_DESC_SW128 =
    (uint64_t(2) << 61) | (uint64_t(1) << 46) | (uint64_t(64) << 32) | (uint64_t(1) << 16);
// SW64 K-major: layout=4, SBO=32, LBO=1 (atom = 8 rows x 64B)
static constexpr uint64_t SMEM_DESC_SW64 =
    (uint64_t(4) << 61) | (uint64_t(1) << 46) | (uint64_t(32) << 32) | (uint64_t(1) << 16);
__device__ __forceinline__ uint64_t make_desc(uint32_t addr) {
    return SMEM_DESC_SW128 | ((uint64_t)(addr >> 4) & 0x3FFF);
}
__device__ __forceinline__ uint64_t make_desc64(uint32_t addr) {
    return SMEM_DESC_SW64 | ((uint64_t)(addr >> 4) & 0x3FFF);
}
__device__ __forceinline__ void mma_f16_ss(uint32_t d, uint64_t a, uint64_t b,
                                           uint32_t idesc, uint32_t en) {
    asm volatile("{ .reg .pred p; setp.ne.u32 p, %4, 0;"
                 "tcgen05.mma.cta_group::1.kind::f16 [%0], %1, %2, %3, {%5,%5,%5,%5}, p; }"
                 :: "r"(d), "l"(a), "l"(b), "r"(idesc), "r"(en), "r"(0u) : "memory");
}
#endif

// ---------------- K1: per-point preamble MLP -> p ----------------------------
__global__ void k1_preamble(const float* __restrict__ pos, const float* __restrict__ t,
                            const float* __restrict__ sph_proj,
                            const float* __restrict__ tb1, const float* __restrict__ tb2,
                            const float* __restrict__ gn1, const float* __restrict__ gw1,
                            const float* __restrict__ gn2, const float* __restrict__ gw2,
                            const float* __restrict__ gn3, const float* __restrict__ gw3)
{
    int i = blockIdx.x * blockDim.x + threadIdx.x;
    if (i >= NPTS) return;

    float x = pos[i * 3 + 0], y = pos[i * 3 + 1], z = pos[i * 3 + 2];
    float rho = sqrtf(x * x + y * y + z * z);
    float phi = atan2f(y, x);
    float cz = z / rho;
    cz = fminf(1.0f, fmaxf(-1.0f, cz));
    float theta = acosf(cz);

    float h[12];
#pragma unroll
    for (int j = 0; j < 8; j++)
        h[j] = rho * sph_proj[j] + phi * sph_proj[8 + j] + theta * sph_proj[16 + j];
    float tv = t[i];
    float ct = cosf(tv + tb1[0]);
    float st = sinf(tv + tb2[0]);
    h[8] = ct; h[9] = st;
    h[10] = ct * sigmoidf_(ct);
    h[11] = st * sigmoidf_(st);

    float ss = 0.f;
#pragma unroll
    for (int j = 0; j < 12; j++) ss += h[j] * h[j];
    float sc = 1.0f / (sqrtf(ss / 12.0f) + 1e-8f);
    float hn[12];
#pragma unroll
    for (int j = 0; j < 12; j++) hn[j] = gn1[j] * h[j] * sc;
    float y1[32];
#pragma unroll
    for (int j = 0; j < 32; j++) y1[j] = 0.f;
#pragma unroll
    for (int r = 0; r < 12; r++) {
        float a = hn[r];
#pragma unroll
        for (int j = 0; j < 32; j++) y1[j] += a * gw1[r * 32 + j];
    }
    float h2[16];
#pragma unroll
    for (int k = 0; k < 16; k++) h2[k] = y1[k] * gelu_tanh(y1[16 + k]);

    ss = 0.f;
#pragma unroll
    for (int j = 0; j < 16; j++) ss += h2[j] * h2[j];
    sc = 1.0f / (sqrtf(ss / 16.0f) + 1e-8f);
    float hn2[16];
#pragma unroll
    for (int j = 0; j < 16; j++) hn2[j] = gn2[j] * h2[j] * sc;
    float y2[32];
#pragma unroll
    for (int j = 0; j < 32; j++) y2[j] = 0.f;
#pragma unroll
    for (int r = 0; r < 16; r++) {
        float a = hn2[r];
#pragma unroll
        for (int j = 0; j < 32; j++) y2[j] += a * gw2[r * 32 + j];
    }
    float h3[16];
#pragma unroll
    for (int k = 0; k < 16; k++) h3[k] = y2[k] * gelu_tanh(y2[16 + k]);

    ss = 0.f;
#pragma unroll
    for (int j = 0; j < 16; j++) ss += h3[j] * h3[j];
    sc = 1.0f / (sqrtf(ss / 16.0f) + 1e-8f);
    float z3[3] = {0.f, 0.f, 0.f};
#pragma unroll
    for (int r = 0; r < 16; r++) {
        float a = gn3[r] * h3[r] * sc;
#pragma unroll
        for (int j = 0; j < 3; j++) z3[j] += a * gw3[r * 3 + j];
    }
    g_p[i * 3 + 0] = sigmoidf_(z3[0]);
    g_p[i * 3 + 1] = sigmoidf_(z3[1]);
    g_p[i * 3 + 2] = sigmoidf_(z3[2]);
}

// ---------------- K2m: fused gather + convW(fp16) + convW2 --------------------
__global__ void __launch_bounds__(256) k2m(const float* __restrict__ t,
                          const float* __restrict__ table0, const float* __restrict__ table1,
                          const float* __restrict__ table2, const float* __restrict__ table3,
                          const float* __restrict__ st1, const float* __restrict__ st2,
                          const float* __restrict__ tf, const float* __restrict__ vn1,
                          const float* __restrict__ vw1, const float* __restrict__ vw2,
                          const float* __restrict__ vn2)
{
    int bid = blockIdx.x;
    __shared__ const float* segp[47];
    __shared__ __align__(16) float red[256];
    __shared__ float sh[32][33];

    if (bid < NPTS) {
        int i = bid;
        float p0 = g_p[i * 3 + 0], p1 = g_p[i * 3 + 1], p2 = g_p[i * 3 + 2];
        float tt = t[i];

        int s = threadIdx.x;
        if (s < 47) {
            const float* base = nullptr;
            if (s < 28) {
                int tb = s / 7;
                int o = s % 7;
                int d, F; const float* T;
                if (tb == 0)      { d = 128; F = 16;  T = table0; }
                else if (tb == 1) { d = 64;  F = 32;  T = table1; }
                else if (tb == 2) { d = 32;  F = 64;  T = table2; }
                else              { d = 16;  F = 128; T = table3; }
                int ix = (int)(p0 * (float)(d - 1));
                int iy = (int)(p1 * (float)(d - 1));
                int iz = (int)(p2 * (float)(d - 1));
                if (o > 0) {
                    ix = wrapi(ix + FACE3[o - 1][0], d);
                    iy = wrapi(iy + FACE3[o - 1][1], d);
                    iz = wrapi(iz + FACE3[o - 1][2], d);
                }
                base = T + (size_t)((ix * d + iy) * d + iz) * F;
            } else if (s < 46) {
                int grp = (s - 28) / 9;
                int o = (s - 28) % 9;
                if (grp == 0) {
                    int a = (int)(p0 * 15.0f), b = (int)(p1 * 15.0f),
                        c = (int)(p2 * 15.0f), e = (int)(tt * 63.0f);
                    if (o > 0) {
                        a = wrapi(a + ST8[o - 1][0], 16);
                        b = wrapi(b + ST8[o - 1][1], 16);
                        c = wrapi(c + ST8[o - 1][2], 16);
                        e = wrapi(e + ST8[o - 1][3], 64);
                    }
                    base = st1 + (size_t)(((a * 16 + b) * 16 + c) * 64 + e) * 64;
                } else {
                    int a = (int)(p0 * 63.0f), b = (int)(p1 * 63.0f),
                        c = (int)(p2 * 31.0f), e = (int)(tt * 15.0f);
                    if (o > 0) {
                        a = wrapi(a + ST8[o - 1][0], 64);
                        b = wrapi(b + ST8[o - 1][1], 64);
                        c = wrapi(c + ST8[o - 1][2], 32);
                        e = wrapi(e + ST8[o - 1][3], 16);
                    }
                    base = st2 + (size_t)(((a * 64 + b) * 32 + c) * 16 + e) * 8;
                }
            } else {
                int a = (int)(p0 * 3.0f), b = (int)(p1 * 3.0f),
                    c = (int)(p2 * 3.0f), e = (int)(tt * 65535.0f);
                base = tf + (size_t)(((a * 4 + b) * 4 + c) * 65536 + e) * 8;
            }
            segp[s] = base;
        }
        __syncthreads();

        float4 v0[2], v1[2];
        float ss = 0.f;
#pragma unroll
        for (int gi = 0; gi < 2; gi++) {
            int g = threadIdx.x + gi * 256;
            if (g < NGRP) {
                int f0 = g * 8;
                int seg, off;
                if (f0 < 112)       { seg = f0 >> 4;                 off = f0 & 15; }
                else if (f0 < 336)  { int q = f0 - 112;  seg = 7  + (q >> 5); off = q & 31; }
                else if (f0 < 784)  { int q = f0 - 336;  seg = 14 + (q >> 6); off = q & 63; }
                else if (f0 < 1680) { int q = f0 - 784;  seg = 21 + (q >> 7); off = q & 127; }
                else if (f0 < 2256) { int q = f0 - 1680; seg = 28 + (q >> 6); off = q & 63; }
                else if (f0 < 2328) { int q = f0 - 2256; seg = 37 + (q >> 3); off = q & 7; }
                else                { seg = 46;                      off = f0 - 2328; }
                const float* sp = segp[seg] + off;
                float4 a = *(const float4*)sp;
                float4 b = *(const float4*)(sp + 4);
                v0[gi] = a; v1[gi] = b;
                ss += a.x * a.x + a.y * a.y + a.z * a.z + a.w * a.w
                    + b.x * b.x + b.y * b.y + b.z * b.z + b.w * b.w;
            }
        }
        red[threadIdx.x] = ss;
        __syncthreads();
        for (int w = 128; w > 0; w >>= 1) {
            if (threadIdx.x < w) red[threadIdx.x] += red[threadIdx.x + w];
            __syncthreads();
        }
        float rms = sqrtf(red[0] / (float)TOTAL);
        float sc = 1.0f / (rms + 1e-8f);
        __half* orow = g_Abf + (size_t)i * AW1;
#pragma unroll
        for (int gi = 0; gi < 2; gi++) {
            int g = threadIdx.x + gi * 256;
            if (g < NGRP) {
                int f0 = g * 8;
                float4 n0 = *(const float4*)&vn1[f0];
                float4 n1 = *(const float4*)&vn1[f0 + 4];
                float v[8] = { v0[gi].x * n0.x * sc, v0[gi].y * n0.y * sc,
                               v0[gi].z * n0.z * sc, v0[gi].w * n0.w * sc,
                               v1[gi].x * n1.x * sc, v1[gi].y * n1.y * sc,
                               v1[gi].z * n1.z * sc, v1[gi].w * n1.w * sc };
                uint32_t hi[4], lo[4];
#pragma unroll
                for (int j = 0; j < 4; j++) {
                    __half h0 = __float2half(v[2 * j]);
                    __half h1 = __float2half(v[2 * j + 1]);
                    __half l0 = __float2half(v[2 * j] - __half2float(h0));
                    __half l1 = __float2half(v[2 * j + 1] - __half2float(h1));
                    hi[j] = (uint32_t)(*(unsigned short*)&h0) | ((uint32_t)(*(unsigned short*)&h1) << 16);
                    lo[j] = (uint32_t)(*(unsigned short*)&l0) | ((uint32_t)(*(unsigned short*)&l1) << 16);
                }
                int blk = f0 >> 5, pos = f0 & 31;
                *(uint4*)(orow + blk * 64 + pos)      = make_uint4(hi[0], hi[1], hi[2], hi[3]);
                *(uint4*)(orow + blk * 64 + 32 + pos) = make_uint4(lo[0], lo[1], lo[2], lo[3]);
            }
        }
    } else if (bid < NPTS + CWBLK) {
        int b2 = bid - NPTS;
        int n0 = (b2 % 152) * 32, k0 = (b2 / 152) * 32;
        int tx = threadIdx.x & 31, ty = threadIdx.x >> 5;
        int tile = n0 >> 8, half = (n0 >> 7) & 1;
        int f0 = tile * 128 + (n0 & 127);
#pragma unroll
        for (int ii = 0; ii < 4; ii++) {
            int r = ty + ii * 8;
            int k = k0 + r;
            int f = f0 + tx;
            float v = 0.f;
            if (f < TOTAL && k < TOTAL)
                v = vw1[(size_t)k * TWOTOTAL + half * TOTAL + f];
            sh[r][tx] = v;
        }
        __syncthreads();
#pragma unroll
        for (int ii = 0; ii < 4; ii++) {
            int r = ty + ii * 8;
            int n = n0 + r;
            g_WT[(size_t)n * WTS + (k0 + tx)] = __float2half(sh[tx][r]);
        }
    } else {
        int idx = (bid - NPTS - CWBLK) * 256 + threadIdx.x;
        if (idx < TOTAL * 64) {
            int k = idx >> 6, n = idx & 63;
            float v = vn2[k] * vw2[idx];
            __nv_bfloat16 h = __float2bfloat16(v);
            float hf = __bfloat162float(h);
            __nv_bfloat16 l = __float2bfloat16(v - hf);
            size_t base = (size_t)n * VW + (size_t)((k >> 5) * 64);
            g_WT2[base + (k & 31)] = h;
            g_WT2[base + 32 + (k & 31)] = l;
        }
    }
}

// ---------------- K3: warp-specialized fp16 GEMM1, 3-buffer, SW64 W -----------
#define STG1 49152
#define SMEM1 (1024 + 3 * STG1)

__global__ void __launch_bounds__(256, 1) k3_gemm1(const __half* __restrict__ Abf,
                                                   const __half* __restrict__ WT,
                                                   __nv_bfloat16* __restrict__ Vbf,
                                                   float* __restrict__ sspart)
{
    extern __shared__ char smem[];
    uint32_t sbase = smem_u32(smem);
    int tid = threadIdx.x;
    int wid = tid >> 5, lid = tid & 31;
    int tile = blockIdx.x;
    int bm = blockIdx.y * 256;
    int bn = tile * 256;

#if defined(__CUDA_ARCH_FEAT_SM103_ALL)
    const uint32_t TSLOT = sbase;
    const uint32_t FUL0 = sbase + 16, FUL1 = sbase + 24, FUL2 = sbase + 32;
    const uint32_t EMP0 = sbase + 40, EMP1 = sbase + 48, EMP2 = sbase + 56;
    const uint32_t DONE = sbase + 64;
    const uint32_t SDATA = sbase + 1024;

    if (wid == 0) TC_ALLOC(TSLOT, 512);
    if (tid == 0) {
        MBARRIER_INIT(FUL0, 224); MBARRIER_INIT(FUL1, 224); MBARRIER_INIT(FUL2, 224);
        MBARRIER_INIT(EMP0, 1);   MBARRIER_INIT(EMP1, 1);   MBARRIER_INIT(EMP2, 1);
        MBARRIER_INIT(DONE, 1);
    }
    __syncthreads();
    uint32_t tmem;
    asm volatile("ld.shared.b32 %0, [%1];" : "=r"(tmem) : "r"(TSLOT));

    const uint32_t IDESC = (1u << 4) | (32u << 17) | (8u << 24);

    if (wid >= 1) {
        int ptid = tid - 32;
        int pe0 = 1, pe1 = 1, pe2 = 1;
        const __half* Abase = Abf + (size_t)bm * AW1;
        const __half* Wbase = WT + (size_t)bn * WTS;
        for (int s = 0; s < NST1; s++) {
            int b = s % 3;
            uint32_t emp = (b == 0) ? EMP0 : (b == 1) ? EMP1 : EMP2;
            uint32_t ful = (b == 0) ? FUL0 : (b == 1) ? FUL1 : FUL2;
            if (b == 0)      { MBARRIER_WAIT_PARITY(emp, pe0); pe0 ^= 1; }
            else if (b == 1) { MBARRIER_WAIT_PARITY(emp, pe1); pe1 ^= 1; }
            else             { MBARRIER_WAIT_PARITY(emp, pe2); pe2 ^= 1; }
            uint32_t ab = SDATA + b * STG1;
            int ka = s * 64;
            int kw = s * 32;
            for (int idx = ptid; idx < 3072; idx += 224) {
                if (idx < 2048) {
                    int r = idx >> 3, c = idx & 7;
                    uint32_t off = (uint32_t)(r * 128 + c * 16);
                    uint32_t sw = off ^ ((off >> 3) & 0x70);
                    CP_ASYNC16(ab + sw, (const void*)(Abase + (size_t)r * AW1 + ka + c * 8));
                } else {
                    int q = idx - 2048;
                    int r = q >> 2, c = q & 3;
                    uint32_t off = (uint32_t)(r * 64 + c * 16);
                    uint32_t sw = off ^ ((off >> 3) & 0x30);
                    CP_ASYNC16(ab + 32768 + sw, (const void*)(Wbase + (size_t)r * WTS + kw + c * 8));
                }
            }
            CPA_MBAR_ARRIVE_NOINC(ful);
        }
    } else if (elect_one()) {
        int pf0 = 0, pf1 = 0, pf2 = 0;
        for (int s = 0; s < NST1; s++) {
            int b = s % 3;
            uint32_t ful = (b == 0) ? FUL0 : (b == 1) ? FUL1 : FUL2;
            uint32_t emp = (b == 0) ? EMP0 : (b == 1) ? EMP1 : EMP2;
            if (b == 0)      { MBARRIER_WAIT_PARITY(ful, pf0); pf0 ^= 1; }
            else if (b == 1) { MBARRIER_WAIT_PARITY(ful, pf1); pf1 ^= 1; }
            else             { MBARRIER_WAIT_PARITY(ful, pf2); pf2 ^= 1; }
            FENCE_ASYNC_SH();
            uint32_t ab = SDATA + b * STG1;
            uint64_t wd = make_desc64(ab + 32768);
#pragma unroll
            for (int half = 0; half < 2; half++) {
                uint64_t ad = make_desc(ab + half * 16384);
                uint32_t dt = tmem + half * 256;
                uint32_t en0 = (s > 0) ? 1u : 0u;
                mma_f16_ss(dt, ad + 0, wd + 0, IDESC, en0);
                mma_f16_ss(dt, ad + 2, wd + 2, IDESC, 1u);
                mma_f16_ss(dt, ad + 4, wd + 0, IDESC, 1u);
                mma_f16_ss(dt, ad + 6, wd + 2, IDESC, 1u);
            }
            TC_COMMIT(emp);
        }
        TC_COMMIT(DONE);
    }
    MBARRIER_WAIT_PARITY(DONE, 0);
    TC_FENCE_AFTER();

    // fused epilogue: a = cols 0-127, g = cols 128-255 -> v = a*gelu(g)
    {
        int m = bm + ((wid < 4) ? 0 : 128) + (wid & 3) * 32 + lid;
        uint32_t dbase = tmem + ((wid < 4) ? 0 : 256);
        float ssacc = 0.f;
#pragma unroll
        for (int cp = 0; cp < 4; cp++) {
            uint32_t ra[32], rg[32];
            TC_LD_X32(ra, dbase + cp * 32);
            TC_LD_X32(rg, dbase + 128 + cp * 32);
            TC_WAIT_LD();
            uint32_t o[32];
#pragma unroll
            for (int j = 0; j < 32; j += 2) {
                float a0 = __uint_as_float(ra[j]),     a1 = __uint_as_float(ra[j + 1]);
                float g0 = __uint_as_float(rg[j]),     g1 = __uint_as_float(rg[j + 1]);
                float v0 = a0 * gelu_fast(g0), v1 = a1 * gelu_fast(g1);
                ssacc += v0 * v0 + v1 * v1;
                __nv_bfloat16 h0 = __float2bfloat16(v0);
                __nv_bfloat16 h1 = __float2bfloat16(v1);
                __nv_bfloat16 l0 = __float2bfloat16(v0 - __bfloat162float(h0));
                __nv_bfloat16 l1 = __float2bfloat16(v1 - __bfloat162float(h1));
                unsigned short uh0 = *(unsigned short*)&h0, uh1 = *(unsigned short*)&h1;
                unsigned short ul0 = *(unsigned short*)&l0, ul1 = *(unsigned short*)&l1;
                o[j >> 1]        = (uint32_t)uh0 | ((uint32_t)uh1 << 16);
                o[16 + (j >> 1)] = (uint32_t)ul0 | ((uint32_t)ul1 << 16);
            }
            int fb = tile * 4 + cp;
            uint4* dst = (uint4*)(Vbf + (size_t)m * VW + fb * 64);
#pragma unroll
            for (int q = 0; q < 8; q++)
                dst[q] = make_uint4(o[4 * q], o[4 * q + 1], o[4 * q + 2], o[4 * q + 3]);
        }
        sspart[(size_t)m * NTILES + tile] = ssacc;
    }
    __syncthreads();
    if (wid == 0) {
        TC_RELINQ();
        TC_DEALLOC(tmem, 512);
    }
#else
    // ---- FFMA fallback (generic pass; never selected on sm_103a) ----
    float* Da   = (float*)smem;
    float* As   = Da + 128 * 128;
    float* Bs   = As + 16 * 128;
    float* ssrd = Bs + 16 * 128;
    int tx = tid % 16, ty = tid / 16;
    for (int pass = 0; pass < 2; pass++) {
        int pm = bm + pass * 128;
        for (int half = 0; half < 2; half++) {
            int pn = bn + half * 128;
            float acc[8][8];
#pragma unroll
            for (int a = 0; a < 8; a++)
#pragma unroll
                for (int b = 0; b < 8; b++) acc[a][b] = 0.f;
            for (int k0 = 0; k0 < KPAD1; k0 += 16) {
                __syncthreads();
                for (int idx = tid; idx < 2048; idx += 256) {
                    int row = idx >> 4, kk = idx & 15;
                    int k = k0 + kk;
                    size_t pb = (size_t)(k >> 5) * 64 + (k & 31);
                    const __half* ar = Abf + (size_t)(pm + row) * AW1 + pb;
                    As[kk * 128 + row] = __half2float(ar[0]) + __half2float(ar[32]);
                    Bs[kk * 128 + row] = __half2float(WT[(size_t)(pn + row) * WTS + k]);
                }
                __syncthreads();
#pragma unroll
                for (int k = 0; k < 16; k++) {
                    float af[8], bf[8];
#pragma unroll
                    for (int a = 0; a < 8; a++) af[a] = As[k * 128 + ty * 8 + a];
#pragma unroll
                    for (int b = 0; b < 8; b++) bf[b] = Bs[k * 128 + tx * 8 + b];
#pragma unroll
                    for (int a = 0; a < 8; a++)
#pragma unroll
                        for (int b = 0; b < 8; b++) acc[a][b] += af[a] * bf[b];
                }
            }
            __syncthreads();
            if (half == 0) {
#pragma unroll
                for (int a = 0; a < 8; a++)
#pragma unroll
                    for (int b = 0; b < 8; b++)
                        Da[(ty * 8 + a) * 128 + tx * 8 + b] = acc[a][b];
            } else {
#pragma unroll
                for (int a = 0; a < 8; a++) {
                    int row = ty * 8 + a;
                    float ssp = 0.f;
#pragma unroll
                    for (int b = 0; b < 8; b++) {
                        int col = tx * 8 + b;
                        float av = Da[row * 128 + col];
                        float v = av * gelu_tanh(acc[a][b]);
                        ssp += v * v;
                        __nv_bfloat16 h = __float2bfloat16(v);
                        __nv_bfloat16 l = __float2bfloat16(v - __bfloat162float(h));
                        int f = tile * 128 + col;
                        int fb = f >> 5, pos = f & 31;
                        Vbf[(size_t)(pm + row) * VW + fb * 64 + pos] = h;
                        Vbf[(size_t)(pm + row) * VW + fb * 64 + 32 + pos] = l;
                    }
                    ssrd[row * 16 + tx] = ssp;
                }
            }
            __syncthreads();
        }
        if (tid < 128) {
            float sm = 0.f;
            for (int j = 0; j < 16; j++) sm += ssrd[tid * 16 + j];
            sspart[(size_t)(pm + tid) * NTILES + tile] = sm;
        }
        __syncthreads();
    }
#endif
}

// ---------------- K5: GEMM2 (bf16 3-term), 4-buffer, + fused final linear -----
#define SMEM5 (1024 + 4 * 24576)
__global__ void __launch_bounds__(256, 1) k5_gemm2(const __nv_bfloat16* __restrict__ Vbf,
                                                   const __nv_bfloat16* __restrict__ WT2,
                                                   const float* __restrict__ t,
                                                   const float* __restrict__ fw,
                                                   const float* __restrict__ fbias,
                                                   const float* __restrict__ sspart,
                                                   float* __restrict__ out)
{
    extern __shared__ char smem[];
    uint32_t sbase = smem_u32(smem);
    int tid = threadIdx.x;
    int wid = tid >> 5, lid = tid & 31;
    int bm = blockIdx.x * 128;

#if defined(__CUDA_ARCH_FEAT_SM103_ALL)
    const uint32_t TSLOT = sbase;
    const uint32_t MB0 = sbase + 16;
    const uint32_t MB1 = sbase + 24;
    const uint32_t MB2 = sbase + 32;
    const uint32_t MB3 = sbase + 40;
    const uint32_t SDATA = sbase + 1024;

    if (wid == 0) TC_ALLOC(TSLOT, 64);
    if (tid == 0) {
        MBARRIER_INIT(MB0, 1); MBARRIER_INIT(MB1, 1);
        MBARRIER_INIT(MB2, 1); MBARRIER_INIT(MB3, 1);
    }
    __syncthreads();
    uint32_t tmem;
    asm volatile("ld.shared.b32 %0, [%1];" : "=r"(tmem) : "r"(TSLOT));

    const uint32_t IDESC = (1u << 4) | (1u << 7) | (1u << 10) | (8u << 17) | (8u << 24);

    auto load_stage = [&](int s) {
        int buf = s & 3;
        int ks = s * 64;
        uint32_t ab = SDATA + buf * 24576;
        uint32_t wb = ab + 16384;
        const __nv_bfloat16* Asrc = Vbf + (size_t)bm * VW + ks;
        const __nv_bfloat16* Wsrc = WT2 + ks;
#pragma unroll
        for (int j = 0; j < 4; j++) {
            int idx = tid + j * 256;
            int row = idx >> 3, c = idx & 7;
            uint32_t off = (uint32_t)(row * 128 + c * 16);
            uint32_t sw = off ^ ((off >> 3) & 0x70);
            CP_ASYNC16(ab + sw, (const void*)(Asrc + (size_t)row * VW + c * 8));
        }
#pragma unroll
        for (int j = 0; j < 2; j++) {
            int idx = tid + j * 256;
            int row = idx >> 3, c = idx & 7;
            uint32_t off = (uint32_t)(row * 128 + c * 16);
            uint32_t sw = off ^ ((off >> 3) & 0x70);
            CP_ASYNC16(wb + sw, (const void*)(Wsrc + (size_t)row * VW + c * 8));
        }
        CP_COMMIT();
    };

    int ph0 = 0, ph1 = 0, ph2 = 0, ph3 = 0;
    load_stage(0);
    load_stage(1);
    load_stage(2);
    for (int s = 0; s < NST2; s++) {
        if (s + 3 < NST2) {
            if (s >= 1) {
                int b = (s - 1) & 3;     // buffer (s+3)&3 == (s-1)&3 must be free
                if (b == 0)      { MBARRIER_WAIT_PARITY(MB0, ph0); ph0 ^= 1; }
                else if (b == 1) { MBARRIER_WAIT_PARITY(MB1, ph1); ph1 ^= 1; }
                else if (b == 2) { MBARRIER_WAIT_PARITY(MB2, ph2); ph2 ^= 1; }
                else             { MBARRIER_WAIT_PARITY(MB3, ph3); ph3 ^= 1; }
            }
            load_stage(s + 3);
        }
        if (s + 3 < NST2)      CP_WAIT3();
        else if (s + 2 < NST2) CP_WAIT2();
        else if (s + 1 < NST2) CP_WAIT1();
        else                   CP_WAIT0();
        __syncthreads();
        FENCE_ASYNC_SH();
        if (wid == 0) {
            if (elect_one()) {
                int buf = s & 3;
                uint32_t ab = SDATA + buf * 24576;
                uint64_t ad = make_desc(ab);
                uint64_t bd = make_desc(ab + 16384);
                uint32_t en0 = (s > 0) ? 1u : 0u;
                mma_f16_ss(tmem, ad + 0, bd + 0, IDESC, en0);
                mma_f16_ss(tmem, ad + 2, bd + 2, IDESC, 1u);
                mma_f16_ss(tmem, ad + 4, bd + 0, IDESC, 1u);
                mma_f16_ss(tmem, ad + 6, bd + 2, IDESC, 1u);
                mma_f16_ss(tmem, ad + 0, bd + 4, IDESC, 1u);
                mma_f16_ss(tmem, ad + 2, bd + 6, IDESC, 1u);
                if (buf == 0)      TC_COMMIT(MB0);
                else if (buf == 1) TC_COMMIT(MB1);
                else if (buf == 2) TC_COMMIT(MB2);
                else               TC_COMMIT(MB3);
            }
        }
    }
    {
        int b = (NST2 - 1) & 3;   // 75 & 3 = 3
        if (b == 0)      MBARRIER_WAIT_PARITY(MB0, ph0);
        else if (b == 1) MBARRIER_WAIT_PARITY(MB1, ph1);
        else if (b == 2) MBARRIER_WAIT_PARITY(MB2, ph2);
        else             MBARRIER_WAIT_PARITY(MB3, ph3);
    }
    TC_FENCE_AFTER();

    if (wid < 4) {
        int m = bm + wid * 32 + lid;
        uint32_t r[32], r2[32];
        TC_LD_X32(r, tmem);
        TC_LD_X32(r2, tmem + 32);
        TC_WAIT_LD();

        const float* sp = sspart + (size_t)m * NTILES;
        float ss = 0.f;
#pragma unroll
        for (int q = 0; q < NTILES; q++) ss += sp[q];
        float sc = 1.0f / (sqrtf(ss / (float)TOTAL) + 1e-8f);

        float o0 = 0.f, o1 = 0.f, o2 = 0.f, o3 = 0.f;
#pragma unroll
        for (int q = 0; q < 32; q++) {
            float a = __uint_as_float(r[q]);
            o0 += a * fw[q * 4 + 0]; o1 += a * fw[q * 4 + 1];
            o2 += a * fw[q * 4 + 2]; o3 += a * fw[q * 4 + 3];
        }
#pragma unroll
        for (int q = 0; q < 32; q++) {
            float a = __uint_as_float(r2[q]);
            o0 += a * fw[(32 + q) * 4 + 0]; o1 += a * fw[(32 + q) * 4 + 1];
            o2 += a * fw[(32 + q) * 4 + 2]; o3 += a * fw[(32 + q) * 4 + 3];
        }
        o0 *= sc; o1 *= sc; o2 *= sc; o3 *= sc;
        o0 += fbias[0]; o1 += fbias[1]; o2 += fbias[2]; o3 += fbias[3];
        float p0 = g_p[m * 3 + 0], p1 = g_p[m * 3 + 1], p2 = g_p[m * 3 + 2];
        float tv = t[m];
        o0 += p0 * fw[256 + 0] + p1 * fw[260 + 0] + p2 * fw[264 + 0] + tv * fw[268 + 0];
        o1 += p0 * fw[256 + 1] + p1 * fw[260 + 1] + p2 * fw[264 + 1] + tv * fw[268 + 1];
        o2 += p0 * fw[256 + 2] + p1 * fw[260 + 2] + p2 * fw[264 + 2] + tv * fw[268 + 2];
        o3 += p0 * fw[256 + 3] + p1 * fw[260 + 3] + p2 * fw[264 + 3] + tv * fw[268 + 3];
        *(float4*)(out + (size_t)m * 4) = make_float4(o0, o1, o2, o3);
    }
    __syncthreads();
    if (wid == 0) {
        TC_RELINQ();
        TC_DEALLOC(tmem, 64);
    }
#else
    // ---- FFMA fallback (256 threads) ----
    float* Ds = (float*)smem;
    float* Bs = Ds + 64 * 64;
    for (int m0 = 0; m0 < 128; m0 += 64) {
        int mrow = (tid >> 2);
        int m = bm + m0 + mrow;
        int nq = (tid & 3) * 16;
        float acc[16];
#pragma unroll
        for (int a = 0; a < 16; a++) acc[a] = 0.f;
        for (int k0 = 0; k0 < KPAD2; k0 += 16) {
            __syncthreads();
            for (int idx = tid; idx < 1024; idx += 256) {
                int kk = idx >> 6, n = idx & 63;
                int k = k0 + kk;
                const __nv_bfloat16* wr = WT2 + (size_t)n * VW + (size_t)(k >> 5) * 64 + (k & 31);
                Bs[kk * 64 + n] = __bfloat162float(wr[0]) + __bfloat162float(wr[32]);
            }
            __syncthreads();
#pragma unroll
            for (int kk = 0; kk < 16; kk++) {
                int k = k0 + kk;
                const __nv_bfloat16* ar = Vbf + (size_t)m * VW + (size_t)(k >> 5) * 64 + (k & 31);
                float av = __bfloat162float(ar[0]) + __bfloat162float(ar[32]);
#pragma unroll
                for (int a = 0; a < 16; a++) acc[a] += av * Bs[kk * 64 + nq + a];
            }
        }
        __syncthreads();
        for (int a = 0; a < 16; a++) Ds[mrow * 64 + nq + a] = acc[a];
        __syncthreads();
        if (tid < 64) {
            int m2 = bm + m0 + tid;
            const float* sp = sspart + (size_t)m2 * NTILES;
            float ss = 0.f;
            for (int q = 0; q < NTILES; q++) ss += sp[q];
            float sc = 1.0f / (sqrtf(ss / (float)TOTAL) + 1e-8f);
            float o0 = 0.f, o1 = 0.f, o2 = 0.f, o3 = 0.f;
            for (int q = 0; q < 64; q++) {
                float a = Ds[tid * 64 + q];
                o0 += a * fw[q * 4 + 0]; o1 += a * fw[q * 4 + 1];
                o2 += a * fw[q * 4 + 2]; o3 += a * fw[q * 4 + 3];
            }
            o0 *= sc; o1 *= sc; o2 *= sc; o3 *= sc;
            o0 += fbias[0]; o1 += fbias[1]; o2 += fbias[2]; o3 += fbias[3];
            float p0 = g_p[m2 * 3 + 0], p1 = g_p[m2 * 3 + 1], p2 = g_p[m2 * 3 + 2];
            float tv = t[m2];
            o0 += p0 * fw[256 + 0] + p1 * fw[260 + 0] + p2 * fw[264 + 0] + tv * fw[268 + 0];
            o1 += p0 * fw[256 + 1] + p1 * fw[260 + 1] + p2 * fw[264 + 1] + tv * fw[268 + 1];
            o2 += p0 * fw[256 + 2] + p1 * fw[260 + 2] + p2 * fw[264 + 2] + tv * fw[268 + 2];
            o3 += p0 * fw[256 + 3] + p1 * fw[260 + 3] + p2 * fw[264 + 3] + tv * fw[268 + 3];
            *(float4*)(out + (size_t)m2 * 4) = make_float4(o0, o1, o2, o3);
        }
        __syncthreads();
    }
#endif
}

// ---------------- launcher ----------------------------------------------------
extern "C" void kernel_launch(void* const* d_in, const int* in_sizes, int n_in,
                              void* d_out, int out_size)
{
    const float* pos      = (const float*)d_in[0];
    const float* t        = (const float*)d_in[2];
    const float* table0   = (const float*)d_in[3];
    const float* table1   = (const float*)d_in[4];
    const float* table2   = (const float*)d_in[5];
    const float* table3   = (const float*)d_in[6];
    const float* st1      = (const float*)d_in[7];
    const float* st2      = (const float*)d_in[8];
    const float* tf       = (const float*)d_in[9];
    const float* sph_proj = (const float*)d_in[10];
    const float* tb1      = (const float*)d_in[11];
    const float* tb2      = (const float*)d_in[12];
    const float* gn1      = (const float*)d_in[13];
    const float* gw1      = (const float*)d_in[14];
    const float* gn2      = (const float*)d_in[15];
    const float* gw2      = (const float*)d_in[16];
    const float* gn3      = (const float*)d_in[17];
    const float* gw3      = (const float*)d_in[18];
    const float* vn1      = (const float*)d_in[19];
    const float* vw1      = (const float*)d_in[20];
    const float* vn2      = (const float*)d_in[21];
    const float* vw2      = (const float*)d_in[22];
    const float* fw       = (const float*)d_in[23];
    const float* fb       = (const float*)d_in[24];
    float* out = (float*)d_out;

    cudaFuncSetAttribute(k3_gemm1, cudaFuncAttributeMaxDynamicSharedMemorySize, SMEM1);
    cudaFuncSetAttribute(k5_gemm2, cudaFuncAttributeMaxDynamicSharedMemorySize, SMEM5);

    k1_preamble<<<NPTS / 256, 256>>>(pos, t, sph_proj, tb1, tb2,
                                     gn1, gw1, gn2, gw2, gn3, gw3);

    k2m<<<NPTS + CWBLK + CW2BLK, 256>>>(t, table0, table1, table2, table3,
                                        st1, st2, tf, vn1, vw1, vw2, vn2);

    __half* Abf;        cudaGetSymbolAddress((void**)&Abf, g_Abf);
    __nv_bfloat16* Vbf; cudaGetSymbolAddress((void**)&Vbf, g_Vbf);
    __half* WT;         cudaGetSymbolAddress((void**)&WT,  g_WT);
    __nv_bfloat16* WT2; cudaGetSymbolAddress((void**)&WT2, g_WT2);
    float* Sp;          cudaGetSymbolAddress((void**)&Sp,  g_sspart);

    dim3 g1(NTILES, NPTS / 256);          // (19, 128)
    k3_gemm1<<<g1, 256, SMEM1>>>(Abf, WT, Vbf, Sp);

    k5_gemm2<<<NPTS / 128, 256, SMEM5>>>(Vbf, WT2, t, fw, fb, Sp, out);
}

// round 15
// speedup vs baseline: 1.6643x; 1.4802x over previous
#include <cuda_runtime.h>
#include <cuda_bf16.h>
#include <cuda_fp16.h>
#include <math.h>
#include <stdint.h>

#define NPTS 32768
#define TOTAL 2336
#define KPAD1 2368         // GEMM1 K padded (74 stages of 32 logical k)
#define NST1 74
#define KPAD2 2432         // GEMM2 K (76 blocks)
#define NST2 76
#define TWOTOTAL 4672
#define INNER 64
#define AW1 2368           // g_Abf row (fp16 single): plain k layout
#define VW 4864            // g_Vbf / g_WT2 row (bf16): 76 blocks x [hi32|lo32]
#define WTS 2368           // g_WT row (fp16 single): plain k layout
#define WTROWS 4864        // permuted W1 rows (19 tiles x 256)
#define NTILES 19
#define NGRP 292           // TOTAL / 8
#define CWBLK (152 * 74)
#define CW2BLK 584

// ---------------- scratch (static device memory; zero-initialized) -----------
__device__ float g_p[NPTS * 3];
__device__ __align__(128) __half g_Abf[(size_t)NPTS * AW1];          // A fp16 single
__device__ __align__(128) __nv_bfloat16 g_Vbf[(size_t)NPTS * VW];    // V bf16 hi/lo
__device__ __align__(128) __half g_WT[(size_t)WTROWS * WTS];         // W1 fp16 single
__device__ __align__(128) __nv_bfloat16 g_WT2[(size_t)64 * VW];      // (vn2*vw2)^T bf16 split
__device__ float g_sspart[(size_t)NPTS * NTILES];
__device__ float g_down[NPTS * INNER];     // fallback only

// ---------------- common helpers ---------------------------------------------
__device__ __forceinline__ uint32_t smem_u32(const void* p) {
    uint32_t a;
    asm("{ .reg .u64 t; cvta.to.shared.u64 t, %1; cvt.u32.u64 %0, t; }" : "=r"(a) : "l"(p));
    return a;
}
__device__ __forceinline__ float sigmoidf_(float x) { return 1.0f / (1.0f + expf(-x)); }
// exact gelu (used in k1, feeds index thresholds -> keep precise)
__device__ __forceinline__ float gelu_tanh(float x) {
    float x3 = x * x * x;
    return 0.5f * x * (1.0f + tanhf(0.7978845608028654f * (x + 0.044715f * x3)));
}
// fast gelu (k3 epilogue only)
__device__ __forceinline__ float gelu_fast(float x) {
    float x3 = x * x * x;
    float arg = 0.7978845608028654f * (x + 0.044715f * x3);
    float th;
    asm("tanh.approx.f32 %0, %1;" : "=f"(th) : "f"(arg));
    return 0.5f * x * (1.0f + th);
}
__device__ __forceinline__ int wrapi(int v, int d) {
    if (v < 0) v += d; else if (v >= d) v -= d; return v;
}
__device__ const int FACE3[6][3] = {{1,0,0},{-1,0,0},{0,1,0},{0,-1,0},{0,0,1},{0,0,-1}};
__device__ const int ST8[8][4]   = {{1,0,0,0},{-1,0,0,0},{0,1,0,0},{0,-1,0,0},
                                    {0,0,1,0},{0,0,-1,0},{0,0,0,1},{0,0,0,-1}};

// cp.async helpers (baseline PTX)
#define CP_ASYNC16(smem, gmem) \
    asm volatile("cp.async.cg.shared.global [%0], [%1], 16;" :: "r"(smem), "l"(gmem) : "memory")
#define CP_COMMIT() asm volatile("cp.async.commit_group;" ::: "memory")
#define CP_WAIT3()  asm volatile("cp.async.wait_group 3;" ::: "memory")
#define CP_WAIT2()  asm volatile("cp.async.wait_group 2;" ::: "memory")
#define CP_WAIT1()  asm volatile("cp.async.wait_group 1;" ::: "memory")
#define CP_WAIT0()  asm volatile("cp.async.wait_group 0;" ::: "memory")

#if defined(__CUDA_ARCH_FEAT_SM103_ALL)
// ---------------- tcgen05 helpers (sm_103a pass only) -------------------------
__device__ __forceinline__ uint32_t elect_one() {
    uint32_t p;
    asm volatile("{ .reg .pred p; elect.sync _|p, 0xFFFFFFFF; selp.b32 %0,1,0,p; }" : "=r"(p));
    return p;
}
#define MBARRIER_INIT(addr, cnt) \
    asm volatile("mbarrier.init.shared.b64 [%0], %1;" :: "r"(addr), "r"(cnt) : "memory")
#define MBARRIER_WAIT_PARITY(addr, parity) do { \
    uint32_t _m = (addr); uint32_t _p = (parity); uint32_t _d; \
    asm volatile("{ .reg .pred p; mbarrier.try_wait.parity.acquire.cta.shared::cta.b64 p, [%1], %2; selp.b32 %0,1,0,p; }" \
        : "=r"(_d) : "r"(_m), "r"(_p) : "memory"); \
    if (!_d) { \
        asm volatile("{ .reg .pred P1; WL_%=: mbarrier.try_wait.parity.acquire.cta.shared::cta.b64 P1, [%0], %1, 0x989680; @P1 bra.uni WD_%=; bra.uni WL_%=; WD_%=: }" \
            :: "r"(_m), "r"(_p) : "memory"); \
    } } while (0)
#define CPA_MBAR_ARRIVE_NOINC(mbar) \
    asm volatile("cp.async.mbarrier.arrive.noinc.shared::cta.b64 [%0];" :: "r"(mbar) : "memory")
#define TC_ALLOC(slot, n)  asm volatile("tcgen05.alloc.cta_group::1.sync.aligned.shared::cta.b32 [%0], %1;" :: "r"(slot), "r"(n) : "memory")
#define TC_DEALLOC(t, n)   asm volatile("tcgen05.dealloc.cta_group::1.sync.aligned.b32 %0, %1;" :: "r"(t), "r"(n))
#define TC_RELINQ()        asm volatile("tcgen05.relinquish_alloc_permit.cta_group::1.sync.aligned;")
#define TC_COMMIT(mbar)    asm volatile("tcgen05.commit.cta_group::1.mbarrier::arrive::one.shared::cluster.b64 [%0];" :: "r"(mbar) : "memory")
#define TC_WAIT_LD()       asm volatile("tcgen05.wait::ld.sync.aligned;" ::: "memory")
#define TC_FENCE_AFTER()   asm volatile("tcgen05.fence::after_thread_sync;" ::: "memory")
#define FENCE_ASYNC_SH()   asm volatile("fence.proxy.async.shared::cta;" ::: "memory")
#define TC_LD_X32(r, addr) \
    asm volatile("tcgen05.ld.sync.aligned.32x32b.x32.b32 " \
        "{%0,%1,%2,%3,%4,%5,%6,%7,%8,%9,%10,%11,%12,%13,%14,%15," \
        "%16,%17,%18,%19,%20,%21,%22,%23,%24,%25,%26,%27,%28,%29,%30,%31}, [%32];" \
        : "=r"((r)[0]),"=r"((r)[1]),"=r"((r)[2]),"=r"((r)[3]),"=r"((r)[4]),"=r"((r)[5]),"=r"((r)[6]),"=r"((r)[7]), \
          "=r"((r)[8]),"=r"((r)[9]),"=r"((r)[10]),"=r"((r)[11]),"=r"((r)[12]),"=r"((r)[13]),"=r"((r)[14]),"=r"((r)[15]), \
          "=r"((r)[16]),"=r"((r)[17]),"=r"((r)[18]),"=r"((r)[19]),"=r"((r)[20]),"=r"((r)[21]),"=r"((r)[22]),"=r"((r)[23]), \
          "=r"((r)[24]),"=r"((r)[25]),"=r"((r)[26]),"=r"((r)[27]),"=r"((r)[28]),"=r"((r)[29]),"=r"((r)[30]),"=r"((r)[31]) \
        : "r"(addr))
// SW128 K-major: layout=2, SBO=64, LBO=1
static constexpr uint64_t SMEM_DESC_SW128 =
    (uint64_t(2) << 61) | (uint64_t(1) << 46) | (uint64_t(64) << 32) | (uint64_t(1) << 16);
// SW64 K-major: layout=4, SBO=32, LBO=1 (atom = 8 rows x 64B)
static constexpr uint64_t SMEM_DESC_SW64 =
    (uint64_t(4) << 61) | (uint64_t(1) << 46) | (uint64_t(32) << 32) | (uint64_t(1) << 16);
__device__ __forceinline__ uint64_t make_desc(uint32_t addr) {
    return SMEM_DESC_SW128 | ((uint64_t)(addr >> 4) & 0x3FFF);
}
__device__ __forceinline__ uint64_t make_desc64(uint32_t addr) {
    return SMEM_DESC_SW64 | ((uint64_t)(addr >> 4) & 0x3FFF);
}
__device__ __forceinline__ void mma_f16_ss(uint32_t d, uint64_t a, uint64_t b,
                                           uint32_t idesc, uint32_t en) {
    asm volatile("{ .reg .pred p; setp.ne.u32 p, %4, 0;"
                 "tcgen05.mma.cta_group::1.kind::f16 [%0], %1, %2, %3, {%5,%5,%5,%5}, p; }"
                 :: "r"(d), "l"(a), "l"(b), "r"(idesc), "r"(en), "r"(0u) : "memory");
}
#endif

// ---------------- K1: per-point preamble MLP -> p ----------------------------
__global__ void k1_preamble(const float* __restrict__ pos, const float* __restrict__ t,
                            const float* __restrict__ sph_proj,
                            const float* __restrict__ tb1, const float* __restrict__ tb2,
                            const float* __restrict__ gn1, const float* __restrict__ gw1,
                            const float* __restrict__ gn2, const float* __restrict__ gw2,
                            const float* __restrict__ gn3, const float* __restrict__ gw3)
{
    int i = blockIdx.x * blockDim.x + threadIdx.x;
    if (i >= NPTS) return;

    float x = pos[i * 3 + 0], y = pos[i * 3 + 1], z = pos[i * 3 + 2];
    float rho = sqrtf(x * x + y * y + z * z);
    float phi = atan2f(y, x);
    float cz = z / rho;
    cz = fminf(1.0f, fmaxf(-1.0f, cz));
    float theta = acosf(cz);

    float h[12];
#pragma unroll
    for (int j = 0; j < 8; j++)
        h[j] = rho * sph_proj[j] + phi * sph_proj[8 + j] + theta * sph_proj[16 + j];
    float tv = t[i];
    float ct = cosf(tv + tb1[0]);
    float st = sinf(tv + tb2[0]);
    h[8] = ct; h[9] = st;
    h[10] = ct * sigmoidf_(ct);
    h[11] = st * sigmoidf_(st);

    float ss = 0.f;
#pragma unroll
    for (int j = 0; j < 12; j++) ss += h[j] * h[j];
    float sc = 1.0f / (sqrtf(ss / 12.0f) + 1e-8f);
    float hn[12];
#pragma unroll
    for (int j = 0; j < 12; j++) hn[j] = gn1[j] * h[j] * sc;
    float y1[32];
#pragma unroll
    for (int j = 0; j < 32; j++) y1[j] = 0.f;
#pragma unroll
    for (int r = 0; r < 12; r++) {
        float a = hn[r];
#pragma unroll
        for (int j = 0; j < 32; j++) y1[j] += a * gw1[r * 32 + j];
    }
    float h2[16];
#pragma unroll
    for (int k = 0; k < 16; k++) h2[k] = y1[k] * gelu_tanh(y1[16 + k]);

    ss = 0.f;
#pragma unroll
    for (int j = 0; j < 16; j++) ss += h2[j] * h2[j];
    sc = 1.0f / (sqrtf(ss / 16.0f) + 1e-8f);
    float hn2[16];
#pragma unroll
    for (int j = 0; j < 16; j++) hn2[j] = gn2[j] * h2[j] * sc;
    float y2[32];
#pragma unroll
    for (int j = 0; j < 32; j++) y2[j] = 0.f;
#pragma unroll
    for (int r = 0; r < 16; r++) {
        float a = hn2[r];
#pragma unroll
        for (int j = 0; j < 32; j++) y2[j] += a * gw2[r * 32 + j];
    }
    float h3[16];
#pragma unroll
    for (int k = 0; k < 16; k++) h3[k] = y2[k] * gelu_tanh(y2[16 + k]);

    ss = 0.f;
#pragma unroll
    for (int j = 0; j < 16; j++) ss += h3[j] * h3[j];
    sc = 1.0f / (sqrtf(ss / 16.0f) + 1e-8f);
    float z3[3] = {0.f, 0.f, 0.f};
#pragma unroll
    for (int r = 0; r < 16; r++) {
        float a = gn3[r] * h3[r] * sc;
#pragma unroll
        for (int j = 0; j < 3; j++) z3[j] += a * gw3[r * 3 + j];
    }
    g_p[i * 3 + 0] = sigmoidf_(z3[0]);
    g_p[i * 3 + 1] = sigmoidf_(z3[1]);
    g_p[i * 3 + 2] = sigmoidf_(z3[2]);
}

// ---------------- K2m: fused gather + convW(fp16) + convW2 --------------------
__global__ void __launch_bounds__(256) k2m(const float* __restrict__ t,
                          const float* __restrict__ table0, const float* __restrict__ table1,
                          const float* __restrict__ table2, const float* __restrict__ table3,
                          const float* __restrict__ st1, const float* __restrict__ st2,
                          const float* __restrict__ tf, const float* __restrict__ vn1,
                          const float* __restrict__ vw1, const float* __restrict__ vw2,
                          const float* __restrict__ vn2)
{
    int bid = blockIdx.x;
    __shared__ const float* segp[47];
    __shared__ __align__(16) float red[256];
    __shared__ float sh[32][33];

    if (bid < NPTS) {
        int i = bid;
        float p0 = g_p[i * 3 + 0], p1 = g_p[i * 3 + 1], p2 = g_p[i * 3 + 2];
        float tt = t[i];

        int s = threadIdx.x;
        if (s < 47) {
            const float* base = nullptr;
            if (s < 28) {
                int tb = s / 7;
                int o = s % 7;
                int d, F; const float* T;
                if (tb == 0)      { d = 128; F = 16;  T = table0; }
                else if (tb == 1) { d = 64;  F = 32;  T = table1; }
                else if (tb == 2) { d = 32;  F = 64;  T = table2; }
                else              { d = 16;  F = 128; T = table3; }
                int ix = (int)(p0 * (float)(d - 1));
                int iy = (int)(p1 * (float)(d - 1));
                int iz = (int)(p2 * (float)(d - 1));
                if (o > 0) {
                    ix = wrapi(ix + FACE3[o - 1][0], d);
                    iy = wrapi(iy + FACE3[o - 1][1], d);
                    iz = wrapi(iz + FACE3[o - 1][2], d);
                }
                base = T + (size_t)((ix * d + iy) * d + iz) * F;
            } else if (s < 46) {
                int grp = (s - 28) / 9;
                int o = (s - 28) % 9;
                if (grp == 0) {
                    int a = (int)(p0 * 15.0f), b = (int)(p1 * 15.0f),
                        c = (int)(p2 * 15.0f), e = (int)(tt * 63.0f);
                    if (o > 0) {
                        a = wrapi(a + ST8[o - 1][0], 16);
                        b = wrapi(b + ST8[o - 1][1], 16);
                        c = wrapi(c + ST8[o - 1][2], 16);
                        e = wrapi(e + ST8[o - 1][3], 64);
                    }
                    base = st1 + (size_t)(((a * 16 + b) * 16 + c) * 64 + e) * 64;
                } else {
                    int a = (int)(p0 * 63.0f), b = (int)(p1 * 63.0f),
                        c = (int)(p2 * 31.0f), e = (int)(tt * 15.0f);
                    if (o > 0) {
                        a = wrapi(a + ST8[o - 1][0], 64);
                        b = wrapi(b + ST8[o - 1][1], 64);
                        c = wrapi(c + ST8[o - 1][2], 32);
                        e = wrapi(e + ST8[o - 1][3], 16);
                    }
                    base = st2 + (size_t)(((a * 64 + b) * 32 + c) * 16 + e) * 8;
                }
            } else {
                int a = (int)(p0 * 3.0f), b = (int)(p1 * 3.0f),
                    c = (int)(p2 * 3.0f), e = (int)(tt * 65535.0f);
                base = tf + (size_t)(((a * 4 + b) * 4 + c) * 65536 + e) * 8;
            }
            segp[s] = base;
        }
        __syncthreads();

        float4 v0[2], v1[2];
        float ss = 0.f;
#pragma unroll
        for (int gi = 0; gi < 2; gi++) {
            int g = threadIdx.x + gi * 256;
            if (g < NGRP) {
                int f0 = g * 8;
                int seg, off;
                if (f0 < 112)       { seg = f0 >> 4;                 off = f0 & 15; }
                else if (f0 < 336)  { int q = f0 - 112;  seg = 7  + (q >> 5); off = q & 31; }
                else if (f0 < 784)  { int q = f0 - 336;  seg = 14 + (q >> 6); off = q & 63; }
                else if (f0 < 1680) { int q = f0 - 784;  seg = 21 + (q >> 7); off = q & 127; }
                else if (f0 < 2256) { int q = f0 - 1680; seg = 28 + (q >> 6); off = q & 63; }
                else if (f0 < 2328) { int q = f0 - 2256; seg = 37 + (q >> 3); off = q & 7; }
                else                { seg = 46;                      off = f0 - 2328; }
                const float* sp = segp[seg] + off;
                float4 a = *(const float4*)sp;
                float4 b = *(const float4*)(sp + 4);
                v0[gi] = a; v1[gi] = b;
                ss += a.x * a.x + a.y * a.y + a.z * a.z + a.w * a.w
                    + b.x * b.x + b.y * b.y + b.z * b.z + b.w * b.w;
            }
        }
        red[threadIdx.x] = ss;
        __syncthreads();
        for (int w = 128; w > 0; w >>= 1) {
            if (threadIdx.x < w) red[threadIdx.x] += red[threadIdx.x + w];
            __syncthreads();
        }
        float rms = sqrtf(red[0] / (float)TOTAL);
        float sc = 1.0f / (rms + 1e-8f);
        __half* orow = g_Abf + (size_t)i * AW1;
#pragma unroll
        for (int gi = 0; gi < 2; gi++) {
            int g = threadIdx.x + gi * 256;
            if (g < NGRP) {
                int f0 = g * 8;
                float4 n0 = *(const float4*)&vn1[f0];
                float4 n1 = *(const float4*)&vn1[f0 + 4];
                float v[8] = { v0[gi].x * n0.x * sc, v0[gi].y * n0.y * sc,
                               v0[gi].z * n0.z * sc, v0[gi].w * n0.w * sc,
                               v1[gi].x * n1.x * sc, v1[gi].y * n1.y * sc,
                               v1[gi].z * n1.z * sc, v1[gi].w * n1.w * sc };
                uint32_t hw[4];
#pragma unroll
                for (int j = 0; j < 4; j++) {
                    __half h0 = __float2half(v[2 * j]);
                    __half h1 = __float2half(v[2 * j + 1]);
                    hw[j] = (uint32_t)(*(unsigned short*)&h0) | ((uint32_t)(*(unsigned short*)&h1) << 16);
                }
                *(uint4*)(orow + f0) = make_uint4(hw[0], hw[1], hw[2], hw[3]);
            }
        }
    } else if (bid < NPTS + CWBLK) {
        int b2 = bid - NPTS;
        int n0 = (b2 % 152) * 32, k0 = (b2 / 152) * 32;
        int tx = threadIdx.x & 31, ty = threadIdx.x >> 5;
        int tile = n0 >> 8, half = (n0 >> 7) & 1;
        int f0 = tile * 128 + (n0 & 127);
#pragma unroll
        for (int ii = 0; ii < 4; ii++) {
            int r = ty + ii * 8;
            int k = k0 + r;
            int f = f0 + tx;
            float v = 0.f;
            if (f < TOTAL && k < TOTAL)
                v = vw1[(size_t)k * TWOTOTAL + half * TOTAL + f];
            sh[r][tx] = v;
        }
        __syncthreads();
#pragma unroll
        for (int ii = 0; ii < 4; ii++) {
            int r = ty + ii * 8;
            int n = n0 + r;
            g_WT[(size_t)n * WTS + (k0 + tx)] = __float2half(sh[tx][r]);
        }
    } else {
        int idx = (bid - NPTS - CWBLK) * 256 + threadIdx.x;
        if (idx < TOTAL * 64) {
            int k = idx >> 6, n = idx & 63;
            float v = vn2[k] * vw2[idx];
            __nv_bfloat16 h = __float2bfloat16(v);
            float hf = __bfloat162float(h);
            __nv_bfloat16 l = __float2bfloat16(v - hf);
            size_t base = (size_t)n * VW + (size_t)((k >> 5) * 64);
            g_WT2[base + (k & 31)] = h;
            g_WT2[base + 32 + (k & 31)] = l;
        }
    }
}

// ---------------- K3: warp-specialized single-fp16 GEMM1, 3-buffer, SW64 ------
// Stage = 32 logical k: A 16KB (256 rows x 64B, SW64) + W 16KB (SW64).
#define STG1 32768
#define SMEM1 (1024 + 3 * STG1)

__global__ void __launch_bounds__(256, 1) k3_gemm1(const __half* __restrict__ Abf,
                                                   const __half* __restrict__ WT,
                                                   __nv_bfloat16* __restrict__ Vbf,
                                                   float* __restrict__ sspart)
{
    extern __shared__ char smem[];
    uint32_t sbase = smem_u32(smem);
    int tid = threadIdx.x;
    int wid = tid >> 5, lid = tid & 31;
    int tile = blockIdx.x;
    int bm = blockIdx.y * 256;
    int bn = tile * 256;

#if defined(__CUDA_ARCH_FEAT_SM103_ALL)
    const uint32_t TSLOT = sbase;
    const uint32_t FUL0 = sbase + 16, FUL1 = sbase + 24, FUL2 = sbase + 32;
    const uint32_t EMP0 = sbase + 40, EMP1 = sbase + 48, EMP2 = sbase + 56;
    const uint32_t DONE = sbase + 64;
    const uint32_t SDATA = sbase + 1024;

    if (wid == 0) TC_ALLOC(TSLOT, 512);
    if (tid == 0) {
        MBARRIER_INIT(FUL0, 224); MBARRIER_INIT(FUL1, 224); MBARRIER_INIT(FUL2, 224);
        MBARRIER_INIT(EMP0, 1);   MBARRIER_INIT(EMP1, 1);   MBARRIER_INIT(EMP2, 1);
        MBARRIER_INIT(DONE, 1);
    }
    __syncthreads();
    uint32_t tmem;
    asm volatile("ld.shared.b32 %0, [%1];" : "=r"(tmem) : "r"(TSLOT));

    const uint32_t IDESC = (1u << 4) | (32u << 17) | (8u << 24);

    if (wid >= 1) {
        // producers: warps 1-7 (224 threads); 2048 copies/stage
        int ptid = tid - 32;
        int pe0 = 1, pe1 = 1, pe2 = 1;
        const __half* Abase = Abf + (size_t)bm * AW1;
        const __half* Wbase = WT + (size_t)bn * WTS;
        for (int s = 0; s < NST1; s++) {
            int b = s % 3;
            uint32_t emp = (b == 0) ? EMP0 : (b == 1) ? EMP1 : EMP2;
            uint32_t ful = (b == 0) ? FUL0 : (b == 1) ? FUL1 : FUL2;
            if (b == 0)      { MBARRIER_WAIT_PARITY(emp, pe0); pe0 ^= 1; }
            else if (b == 1) { MBARRIER_WAIT_PARITY(emp, pe1); pe1 ^= 1; }
            else             { MBARRIER_WAIT_PARITY(emp, pe2); pe2 ^= 1; }
            uint32_t ab = SDATA + b * STG1;
            int ks = s * 32;           // 32 elems per row per stage
            for (int idx = ptid; idx < 2048; idx += 224) {
                int r = (idx & 1023) >> 2, c = idx & 3;
                uint32_t off = (uint32_t)(r * 64 + c * 16);
                uint32_t sw = off ^ ((off >> 3) & 0x30);
                if (idx < 1024)
                    CP_ASYNC16(ab + sw, (const void*)(Abase + (size_t)r * AW1 + ks + c * 8));
                else
                    CP_ASYNC16(ab + 16384 + sw, (const void*)(Wbase + (size_t)r * WTS + ks + c * 8));
            }
            CPA_MBAR_ARRIVE_NOINC(ful);
        }
    } else if (elect_one()) {
        // consumer
        int pf0 = 0, pf1 = 0, pf2 = 0;
        for (int s = 0; s < NST1; s++) {
            int b = s % 3;
            uint32_t ful = (b == 0) ? FUL0 : (b == 1) ? FUL1 : FUL2;
            uint32_t emp = (b == 0) ? EMP0 : (b == 1) ? EMP1 : EMP2;
            if (b == 0)      { MBARRIER_WAIT_PARITY(ful, pf0); pf0 ^= 1; }
            else if (b == 1) { MBARRIER_WAIT_PARITY(ful, pf1); pf1 ^= 1; }
            else             { MBARRIER_WAIT_PARITY(ful, pf2); pf2 ^= 1; }
            FENCE_ASYNC_SH();
            uint32_t ab = SDATA + b * STG1;
            uint64_t wd = make_desc64(ab + 16384);
#pragma unroll
            for (int half = 0; half < 2; half++) {
                // A rows [half*128, half*128+128): offset half * 128 rows * 64B
                uint64_t ad = make_desc64(ab + half * 8192);
                uint32_t dt = tmem + half * 256;
                uint32_t en0 = (s > 0) ? 1u : 0u;
                mma_f16_ss(dt, ad + 0, wd + 0, IDESC, en0);
                mma_f16_ss(dt, ad + 2, wd + 2, IDESC, 1u);
            }
            TC_COMMIT(emp);
        }
        TC_COMMIT(DONE);
    }
    MBARRIER_WAIT_PARITY(DONE, 0);
    TC_FENCE_AFTER();

    // fused epilogue: a = cols 0-127, g = cols 128-255 -> v = a*gelu(g)
    {
        int m = bm + ((wid < 4) ? 0 : 128) + (wid & 3) * 32 + lid;
        uint32_t dbase = tmem + ((wid < 4) ? 0 : 256);
        float ssacc = 0.f;
#pragma unroll
        for (int cp = 0; cp < 4; cp++) {
            uint32_t ra[32], rg[32];
            TC_LD_X32(ra, dbase + cp * 32);
            TC_LD_X32(rg, dbase + 128 + cp * 32);
            TC_WAIT_LD();
            uint32_t o[32];
#pragma unroll
            for (int j = 0; j < 32; j += 2) {
                float a0 = __uint_as_float(ra[j]),     a1 = __uint_as_float(ra[j + 1]);
                float g0 = __uint_as_float(rg[j]),     g1 = __uint_as_float(rg[j + 1]);
                float v0 = a0 * gelu_fast(g0), v1 = a1 * gelu_fast(g1);
                ssacc += v0 * v0 + v1 * v1;
                __nv_bfloat16 h0 = __float2bfloat16(v0);
                __nv_bfloat16 h1 = __float2bfloat16(v1);
                __nv_bfloat16 l0 = __float2bfloat16(v0 - __bfloat162float(h0));
                __nv_bfloat16 l1 = __float2bfloat16(v1 - __bfloat162float(h1));
                unsigned short uh0 = *(unsigned short*)&h0, uh1 = *(unsigned short*)&h1;
                unsigned short ul0 = *(unsigned short*)&l0, ul1 = *(unsigned short*)&l1;
                o[j >> 1]        = (uint32_t)uh0 | ((uint32_t)uh1 << 16);
                o[16 + (j >> 1)] = (uint32_t)ul0 | ((uint32_t)ul1 << 16);
            }
            int fb = tile * 4 + cp;
            uint4* dst = (uint4*)(Vbf + (size_t)m * VW + fb * 64);
#pragma unroll
            for (int q = 0; q < 8; q++)
                dst[q] = make_uint4(o[4 * q], o[4 * q + 1], o[4 * q + 2], o[4 * q + 3]);
        }
        sspart[(size_t)m * NTILES + tile] = ssacc;
    }
    __syncthreads();
    if (wid == 0) {
        TC_RELINQ();
        TC_DEALLOC(tmem, 512);
    }
#else
    // ---- FFMA fallback (generic pass; never selected on sm_103a) ----
    float* Da   = (float*)smem;
    float* As   = Da + 128 * 128;
    float* Bs   = As + 16 * 128;
    float* ssrd = Bs + 16 * 128;
    int tx = tid % 16, ty = tid / 16;
    for (int pass = 0; pass < 2; pass++) {
        int pm = bm + pass * 128;
        for (int half = 0; half < 2; half++) {
            int pn = bn + half * 128;
            float acc[8][8];
#pragma unroll
            for (int a = 0; a < 8; a++)
#pragma unroll
                for (int b = 0; b < 8; b++) acc[a][b] = 0.f;
            for (int k0 = 0; k0 < KPAD1; k0 += 16) {
                __syncthreads();
                for (int idx = tid; idx < 2048; idx += 256) {
                    int row = idx >> 4, kk = idx & 15;
                    int k = k0 + kk;
                    As[kk * 128 + row] = __half2float(Abf[(size_t)(pm + row) * AW1 + k]);
                    Bs[kk * 128 + row] = __half2float(WT[(size_t)(pn + row) * WTS + k]);
                }
                __syncthreads();
#pragma unroll
                for (int k = 0; k < 16; k++) {
                    float af[8], bf[8];
#pragma unroll
                    for (int a = 0; a < 8; a++) af[a] = As[k * 128 + ty * 8 + a];
#pragma unroll
                    for (int b = 0; b < 8; b++) bf[b] = Bs[k * 128 + tx * 8 + b];
#pragma unroll
                    for (int a = 0; a < 8; a++)
#pragma unroll
                        for (int b = 0; b < 8; b++) acc[a][b] += af[a] * bf[b];
                }
            }
            __syncthreads();
            if (half == 0) {
#pragma unroll
                for (int a = 0; a < 8; a++)
#pragma unroll
                    for (int b = 0; b < 8; b++)
                        Da[(ty * 8 + a) * 128 + tx * 8 + b] = acc[a][b];
            } else {
#pragma unroll
                for (int a = 0; a < 8; a++) {
                    int row = ty * 8 + a;
                    float ssp = 0.f;
#pragma unroll
                    for (int b = 0; b < 8; b++) {
                        int col = tx * 8 + b;
                        float av = Da[row * 128 + col];
                        float v = av * gelu_tanh(acc[a][b]);
                        ssp += v * v;
                        __nv_bfloat16 h = __float2bfloat16(v);
                        __nv_bfloat16 l = __float2bfloat16(v - __bfloat162float(h));
                        int f = tile * 128 + col;
                        int fb = f >> 5, pos = f & 31;
                        Vbf[(size_t)(pm + row) * VW + fb * 64 + pos] = h;
                        Vbf[(size_t)(pm + row) * VW + fb * 64 + 32 + pos] = l;
                    }
                    ssrd[row * 16 + tx] = ssp;
                }
            }
            __syncthreads();
        }
        if (tid < 128) {
            float sm = 0.f;
            for (int j = 0; j < 16; j++) sm += ssrd[tid * 16 + j];
            sspart[(size_t)(pm + tid) * NTILES + tile] = sm;
        }
        __syncthreads();
    }
#endif
}

// ---------------- K5: GEMM2 (bf16 3-term), 4-buffer, + fused final linear -----
#define SMEM5 (1024 + 4 * 24576)
__global__ void __launch_bounds__(256, 1) k5_gemm2(const __nv_bfloat16* __restrict__ Vbf,
                                                   const __nv_bfloat16* __restrict__ WT2,
                                                   const float* __restrict__ t,
                                                   const float* __restrict__ fw,
                                                   const float* __restrict__ fbias,
                                                   const float* __restrict__ sspart,
                                                   float* __restrict__ out)
{
    extern __shared__ char smem[];
    uint32_t sbase = smem_u32(smem);
    int tid = threadIdx.x;
    int wid = tid >> 5, lid = tid & 31;
    int bm = blockIdx.x * 128;

#if defined(__CUDA_ARCH_FEAT_SM103_ALL)
    const uint32_t TSLOT = sbase;
    const uint32_t MB0 = sbase + 16;
    const uint32_t MB1 = sbase + 24;
    const uint32_t MB2 = sbase + 32;
    const uint32_t MB3 = sbase + 40;
    const uint32_t SDATA = sbase + 1024;

    if (wid == 0) TC_ALLOC(TSLOT, 64);
    if (tid == 0) {
        MBARRIER_INIT(MB0, 1); MBARRIER_INIT(MB1, 1);
        MBARRIER_INIT(MB2, 1); MBARRIER_INIT(MB3, 1);
    }
    __syncthreads();
    uint32_t tmem;
    asm volatile("ld.shared.b32 %0, [%1];" : "=r"(tmem) : "r"(TSLOT));

    const uint32_t IDESC = (1u << 4) | (1u << 7) | (1u << 10) | (8u << 17) | (8u << 24);

    auto load_stage = [&](int s) {
        int buf = s & 3;
        int ks = s * 64;
        uint32_t ab = SDATA + buf * 24576;
        uint32_t wb = ab + 16384;
        const __nv_bfloat16* Asrc = Vbf + (size_t)bm * VW + ks;
        const __nv_bfloat16* Wsrc = WT2 + ks;
#pragma unroll
        for (int j = 0; j < 4; j++) {
            int idx = tid + j * 256;
            int row = idx >> 3, c = idx & 7;
            uint32_t off = (uint32_t)(row * 128 + c * 16);
            uint32_t sw = off ^ ((off >> 3) & 0x70);
            CP_ASYNC16(ab + sw, (const void*)(Asrc + (size_t)row * VW + c * 8));
        }
#pragma unroll
        for (int j = 0; j < 2; j++) {
            int idx = tid + j * 256;
            int row = idx >> 3, c = idx & 7;
            uint32_t off = (uint32_t)(row * 128 + c * 16);
            uint32_t sw = off ^ ((off >> 3) & 0x70);
            CP_ASYNC16(wb + sw, (const void*)(Wsrc + (size_t)row * VW + c * 8));
        }
        CP_COMMIT();
    };

    int ph0 = 0, ph1 = 0, ph2 = 0, ph3 = 0;
    load_stage(0);
    load_stage(1);
    load_stage(2);
    for (int s = 0; s < NST2; s++) {
        if (s + 3 < NST2) {
            if (s >= 1) {
                int b = (s - 1) & 3;
                if (b == 0)      { MBARRIER_WAIT_PARITY(MB0, ph0); ph0 ^= 1; }
                else if (b == 1) { MBARRIER_WAIT_PARITY(MB1, ph1); ph1 ^= 1; }
                else if (b == 2) { MBARRIER_WAIT_PARITY(MB2, ph2); ph2 ^= 1; }
                else             { MBARRIER_WAIT_PARITY(MB3, ph3); ph3 ^= 1; }
            }
            load_stage(s + 3);
        }
        if (s + 3 < NST2)      CP_WAIT3();
        else if (s + 2 < NST2) CP_WAIT2();
        else if (s + 1 < NST2) CP_WAIT1();
        else                   CP_WAIT0();
        __syncthreads();
        FENCE_ASYNC_SH();
        if (wid == 0) {
            if (elect_one()) {
                int buf = s & 3;
                uint32_t ab = SDATA + buf * 24576;
                uint64_t ad = make_desc(ab);
                uint64_t bd = make_desc(ab + 16384);
                uint32_t en0 = (s > 0) ? 1u : 0u;
                mma_f16_ss(tmem, ad + 0, bd + 0, IDESC, en0);
                mma_f16_ss(tmem, ad + 2, bd + 2, IDESC, 1u);
                mma_f16_ss(tmem, ad + 4, bd + 0, IDESC, 1u);
                mma_f16_ss(tmem, ad + 6, bd + 2, IDESC, 1u);
                mma_f16_ss(tmem, ad + 0, bd + 4, IDESC, 1u);
                mma_f16_ss(tmem, ad + 2, bd + 6, IDESC, 1u);
                if (buf == 0)      TC_COMMIT(MB0);
                else if (buf == 1) TC_COMMIT(MB1);
                else if (buf == 2) TC_COMMIT(MB2);
                else               TC_COMMIT(MB3);
            }
        }
    }
    {
        int b = (NST2 - 1) & 3;   // 75 & 3 = 3
        if (b == 0)      MBARRIER_WAIT_PARITY(MB0, ph0);
        else if (b == 1) MBARRIER_WAIT_PARITY(MB1, ph1);
        else if (b == 2) MBARRIER_WAIT_PARITY(MB2, ph2);
        else             MBARRIER_WAIT_PARITY(MB3, ph3);
    }
    TC_FENCE_AFTER();

    if (wid < 4) {
        int m = bm + wid * 32 + lid;
        uint32_t r[32], r2[32];
        TC_LD_X32(r, tmem);
        TC_LD_X32(r2, tmem + 32);
        TC_WAIT_LD();

        const float* sp = sspart + (size_t)m * NTILES;
        float ss = 0.f;
#pragma unroll
        for (int q = 0; q < NTILES; q++) ss += sp[q];
        float sc = 1.0f / (sqrtf(ss / (float)TOTAL) + 1e-8f);

        float o0 = 0.f, o1 = 0.f, o2 = 0.f, o3 = 0.f;
#pragma unroll
        for (int q = 0; q < 32; q++) {
            float a = __uint_as_float(r[q]);
            o0 += a * fw[q * 4 + 0]; o1 += a * fw[q * 4 + 1];
            o2 += a * fw[q * 4 + 2]; o3 += a * fw[q * 4 + 3];
        }
#pragma unroll
        for (int q = 0; q < 32; q++) {
            float a = __uint_as_float(r2[q]);
            o0 += a * fw[(32 + q) * 4 + 0]; o1 += a * fw[(32 + q) * 4 + 1];
            o2 += a * fw[(32 + q) * 4 + 2]; o3 += a * fw[(32 + q) * 4 + 3];
        }
        o0 *= sc; o1 *= sc; o2 *= sc; o3 *= sc;
        o0 += fbias[0]; o1 += fbias[1]; o2 += fbias[2]; o3 += fbias[3];
        float p0 = g_p[m * 3 + 0], p1 = g_p[m * 3 + 1], p2 = g_p[m * 3 + 2];
        float tv = t[m];
        o0 += p0 * fw[256 + 0] + p1 * fw[260 + 0] + p2 * fw[264 + 0] + tv * fw[268 + 0];
        o1 += p0 * fw[256 + 1] + p1 * fw[260 + 1] + p2 * fw[264 + 1] + tv * fw[268 + 1];
        o2 += p0 * fw[256 + 2] + p1 * fw[260 + 2] + p2 * fw[264 + 2] + tv * fw[268 + 2];
        o3 += p0 * fw[256 + 3] + p1 * fw[260 + 3] + p2 * fw[264 + 3] + tv * fw[268 + 3];
        *(float4*)(out + (size_t)m * 4) = make_float4(o0, o1, o2, o3);
    }
    __syncthreads();
    if (wid == 0) {
        TC_RELINQ();
        TC_DEALLOC(tmem, 64);
    }
#else
    // ---- FFMA fallback (256 threads) ----
    float* Ds = (float*)smem;
    float* Bs = Ds + 64 * 64;
    for (int m0 = 0; m0 < 128; m0 += 64) {
        int mrow = (tid >> 2);
        int m = bm + m0 + mrow;
        int nq = (tid & 3) * 16;
        float acc[16];
#pragma unroll
        for (int a = 0; a < 16; a++) acc[a] = 0.f;
        for (int k0 = 0; k0 < KPAD2; k0 += 16) {
            __syncthreads();
            for (int idx = tid; idx < 1024; idx += 256) {
                int kk = idx >> 6, n = idx & 63;
                int k = k0 + kk;
                const __nv_bfloat16* wr = WT2 + (size_t)n * VW + (size_t)(k >> 5) * 64 + (k & 31);
                Bs[kk * 64 + n] = __bfloat162float(wr[0]) + __bfloat162float(wr[32]);
            }
            __syncthreads();
#pragma unroll
            for (int kk = 0; kk < 16; kk++) {
                int k = k0 + kk;
                const __nv_bfloat16* ar = Vbf + (size_t)m * VW + (size_t)(k >> 5) * 64 + (k & 31);
                float av = __bfloat162float(ar[0]) + __bfloat162float(ar[32]);
#pragma unroll
                for (int a = 0; a < 16; a++) acc[a] += av * Bs[kk * 64 + nq + a];
            }
        }
        __syncthreads();
        for (int a = 0; a < 16; a++) Ds[mrow * 64 + nq + a] = acc[a];
        __syncthreads();
        if (tid < 64) {
            int m2 = bm + m0 + tid;
            const float* sp = sspart + (size_t)m2 * NTILES;
            float ss = 0.f;
            for (int q = 0; q < NTILES; q++) ss += sp[q];
            float sc = 1.0f / (sqrtf(ss / (float)TOTAL) + 1e-8f);
            float o0 = 0.f, o1 = 0.f, o2 = 0.f, o3 = 0.f;
            for (int q = 0; q < 64; q++) {
                float a = Ds[tid * 64 + q];
                o0 += a * fw[q * 4 + 0]; o1 += a * fw[q * 4 + 1];
                o2 += a * fw[q * 4 + 2]; o3 += a * fw[q * 4 + 3];
            }
            o0 *= sc; o1 *= sc; o2 *= sc; o3 *= sc;
            o0 += fbias[0]; o1 += fbias[1]; o2 += fbias[2]; o3 += fbias[3];
            float p0 = g_p[m2 * 3 + 0], p1 = g_p[m2 * 3 + 1], p2 = g_p[m2 * 3 + 2];
            float tv = t[m2];
            o0 += p0 * fw[256 + 0] + p1 * fw[260 + 0] + p2 * fw[264 + 0] + tv * fw[268 + 0];
            o1 += p0 * fw[256 + 1] + p1 * fw[260 + 1] + p2 * fw[264 + 1] + tv * fw[268 + 1];
            o2 += p0 * fw[256 + 2] + p1 * fw[260 + 2] + p2 * fw[264 + 2] + tv * fw[268 + 2];
            o3 += p0 * fw[256 + 3] + p1 * fw[260 + 3] + p2 * fw[264 + 3] + tv * fw[268 + 3];
            *(float4*)(out + (size_t)m2 * 4) = make_float4(o0, o1, o2, o3);
        }
        __syncthreads();
    }
#endif
}

// ---------------- launcher ----------------------------------------------------
extern "C" void kernel_launch(void* const* d_in, const int* in_sizes, int n_in,
                              void* d_out, int out_size)
{
    const float* pos      = (const float*)d_in[0];
    const float* t        = (const float*)d_in[2];
    const float* table0   = (const float*)d_in[3];
    const float* table1   = (const float*)d_in[4];
    const float* table2   = (const float*)d_in[5];
    const float* table3   = (const float*)d_in[6];
    const float* st1      = (const float*)d_in[7];
    const float* st2      = (const float*)d_in[8];
    const float* tf       = (const float*)d_in[9];
    const float* sph_proj = (const float*)d_in[10];
    const float* tb1      = (const float*)d_in[11];
    const float* tb2      = (const float*)d_in[12];
    const float* gn1      = (const float*)d_in[13];
    const float* gw1      = (const float*)d_in[14];
    const float* gn2      = (const float*)d_in[15];
    const float* gw2      = (const float*)d_in[16];
    const float* gn3      = (const float*)d_in[17];
    const float* gw3      = (const float*)d_in[18];
    const float* vn1      = (const float*)d_in[19];
    const float* vw1      = (const float*)d_in[20];
    const float* vn2      = (const float*)d_in[21];
    const float* vw2      = (const float*)d_in[22];
    const float* fw       = (const float*)d_in[23];
    const float* fb       = (const float*)d_in[24];
    float* out = (float*)d_out;

    cudaFuncSetAttribute(k3_gemm1, cudaFuncAttributeMaxDynamicSharedMemorySize, SMEM1);
    cudaFuncSetAttribute(k5_gemm2, cudaFuncAttributeMaxDynamicSharedMemorySize, SMEM5);

    k1_preamble<<<NPTS / 256, 256>>>(pos, t, sph_proj, tb1, tb2,
                                     gn1, gw1, gn2, gw2, gn3, gw3);

    k2m<<<NPTS + CWBLK + CW2BLK, 256>>>(t, table0, table1, table2, table3,
                                        st1, st2, tf, vn1, vw1, vw2, vn2);

    __half* Abf;        cudaGetSymbolAddress((void**)&Abf, g_Abf);
    __nv_bfloat16* Vbf; cudaGetSymbolAddress((void**)&Vbf, g_Vbf);
    __half* WT;         cudaGetSymbolAddress((void**)&WT,  g_WT);
    __nv_bfloat16* WT2; cudaGetSymbolAddress((void**)&WT2, g_WT2);
    float* Sp;          cudaGetSymbolAddress((void**)&Sp,  g_sspart);

    dim3 g1(NTILES, NPTS / 256);          // (19, 128)
    k3_gemm1<<<g1, 256, SMEM1>>>(Abf, WT, Vbf, Sp);

    k5_gemm2<<<NPTS / 128, 256, SMEM5>>>(Vbf, WT2, t, fw, fb, Sp, out);
}

// round 16
// speedup vs baseline: 1.9111x; 1.1483x over previous
#include <cuda_runtime.h>
#include <cuda.h>
#include <cuda_bf16.h>
#include <cuda_fp16.h>
#include <math.h>
#include <stdint.h>

#define NPTS 32768
#define TOTAL 2336
#define KPAD1 2368         // GEMM1 K padded (74 stages of 32 logical k)
#define NST1 74
#define KPAD2 2432         // GEMM2 K (76 blocks)
#define NST2 76
#define TWOTOTAL 4672
#define INNER 64
#define AW1 2368           // g_Abf row (fp16 single): plain k layout
#define VW 4864            // g_Vbf / g_WT2 row (bf16): 76 blocks x [hi32|lo32]
#define WTS 2368           // g_WT row (fp16 single): plain k layout
#define WTROWS 4864        // permuted W1 rows (19 tiles x 256)
#define NTILES 19
#define NGRP 292           // TOTAL / 8
#define CWBLK (152 * 74)
#define CW2BLK 584
#define NB3 5              // k3 TMA ring depth

// ---------------- scratch (static device memory; zero-initialized) -----------
__device__ float g_p[NPTS * 3];
__device__ __align__(128) __half g_Abf[(size_t)NPTS * AW1];          // A fp16 single
__device__ __align__(128) __nv_bfloat16 g_Vbf[(size_t)NPTS * VW];    // V bf16 hi/lo
__device__ __align__(128) __half g_WT[(size_t)WTROWS * WTS];         // W1 fp16 single
__device__ __align__(128) __nv_bfloat16 g_WT2[(size_t)64 * VW];      // (vn2*vw2)^T bf16 split
__device__ float g_sspart[(size_t)NPTS * NTILES];
__device__ float g_down[NPTS * INNER];     // fallback only

// ---------------- common helpers ---------------------------------------------
__device__ __forceinline__ uint32_t smem_u32(const void* p) {
    uint32_t a;
    asm("{ .reg .u64 t; cvta.to.shared.u64 t, %1; cvt.u32.u64 %0, t; }" : "=r"(a) : "l"(p));
    return a;
}
__device__ __forceinline__ float sigmoidf_(float x) { return 1.0f / (1.0f + expf(-x)); }
// exact gelu (used in k1, feeds index thresholds -> keep precise)
__device__ __forceinline__ float gelu_tanh(float x) {
    float x3 = x * x * x;
    return 0.5f * x * (1.0f + tanhf(0.7978845608028654f * (x + 0.044715f * x3)));
}
// fast gelu (k3 epilogue only)
__device__ __forceinline__ float gelu_fast(float x) {
    float x3 = x * x * x;
    float arg = 0.7978845608028654f * (x + 0.044715f * x3);
    float th;
    asm("tanh.approx.f32 %0, %1;" : "=f"(th) : "f"(arg));
    return 0.5f * x * (1.0f + th);
}
__device__ __forceinline__ int wrapi(int v, int d) {
    if (v < 0) v += d; else if (v >= d) v -= d; return v;
}
__device__ const int FACE3[6][3] = {{1,0,0},{-1,0,0},{0,1,0},{0,-1,0},{0,0,1},{0,0,-1}};
__device__ const int ST8[8][4]   = {{1,0,0,0},{-1,0,0,0},{0,1,0,0},{0,-1,0,0},
                                    {0,0,1,0},{0,0,-1,0},{0,0,0,1},{0,0,0,-1}};

// cp.async helpers (baseline PTX; used by k5)
#define CP_ASYNC16(smem, gmem) \
    asm volatile("cp.async.cg.shared.global [%0], [%1], 16;" :: "r"(smem), "l"(gmem) : "memory")
#define CP_COMMIT() asm volatile("cp.async.commit_group;" ::: "memory")
#define CP_WAIT3()  asm volatile("cp.async.wait_group 3;" ::: "memory")
#define CP_WAIT2()  asm volatile("cp.async.wait_group 2;" ::: "memory")
#define CP_WAIT1()  asm volatile("cp.async.wait_group 1;" ::: "memory")
#define CP_WAIT0()  asm volatile("cp.async.wait_group 0;" ::: "memory")

#if defined(__CUDA_ARCH_FEAT_SM103_ALL)
// ---------------- tcgen05 / TMA helpers (sm_103a pass only) -------------------
__device__ __forceinline__ uint32_t elect_one() {
    uint32_t p;
    asm volatile("{ .reg .pred p; elect.sync _|p, 0xFFFFFFFF; selp.b32 %0,1,0,p; }" : "=r"(p));
    return p;
}
#define MBARRIER_INIT(addr, cnt) \
    asm volatile("mbarrier.init.shared.b64 [%0], %1;" :: "r"(addr), "r"(cnt) : "memory")
#define MBARRIER_EXPECT_TX(mbar, bytes) \
    asm volatile("mbarrier.arrive.expect_tx.shared.b64 _, [%0], %1;" :: "r"(mbar), "r"(bytes) : "memory")
#define MBARRIER_WAIT_PARITY(addr, parity) do { \
    uint32_t _m = (addr); uint32_t _p = (parity); uint32_t _d; \
    asm volatile("{ .reg .pred p; mbarrier.try_wait.parity.acquire.cta.shared::cta.b64 p, [%1], %2; selp.b32 %0,1,0,p; }" \
        : "=r"(_d) : "r"(_m), "r"(_p) : "memory"); \
    if (!_d) { \
        asm volatile("{ .reg .pred P1; WL_%=: mbarrier.try_wait.parity.acquire.cta.shared::cta.b64 P1, [%0], %1, 0x989680; @P1 bra.uni WD_%=; bra.uni WL_%=; WD_%=: }" \
            :: "r"(_m), "r"(_p) : "memory"); \
    } } while (0)
#define TMA_LOAD_2D(smem, map, c0, c1, mbar) \
    asm volatile("cp.async.bulk.tensor.2d.shared::cta.global.tile.mbarrier::complete_tx::bytes " \
                 "[%0], [%1, {%2, %3}], [%4];" \
                 :: "r"(smem), "l"(map), "r"(c0), "r"(c1), "r"(mbar) : "memory")
#define TC_ALLOC(slot, n)  asm volatile("tcgen05.alloc.cta_group::1.sync.aligned.shared::cta.b32 [%0], %1;" :: "r"(slot), "r"(n) : "memory")
#define TC_DEALLOC(t, n)   asm volatile("tcgen05.dealloc.cta_group::1.sync.aligned.b32 %0, %1;" :: "r"(t), "r"(n))
#define TC_RELINQ()        asm volatile("tcgen05.relinquish_alloc_permit.cta_group::1.sync.aligned;")
#define TC_COMMIT(mbar)    asm volatile("tcgen05.commit.cta_group::1.mbarrier::arrive::one.shared::cluster.b64 [%0];" :: "r"(mbar) : "memory")
#define TC_WAIT_LD()       asm volatile("tcgen05.wait::ld.sync.aligned;" ::: "memory")
#define TC_FENCE_AFTER()   asm volatile("tcgen05.fence::after_thread_sync;" ::: "memory")
#define FENCE_ASYNC_SH()   asm volatile("fence.proxy.async.shared::cta;" ::: "memory")
#define TC_LD_X32(r, addr) \
    asm volatile("tcgen05.ld.sync.aligned.32x32b.x32.b32 " \
        "{%0,%1,%2,%3,%4,%5,%6,%7,%8,%9,%10,%11,%12,%13,%14,%15," \
        "%16,%17,%18,%19,%20,%21,%22,%23,%24,%25,%26,%27,%28,%29,%30,%31}, [%32];" \
        : "=r"((r)[0]),"=r"((r)[1]),"=r"((r)[2]),"=r"((r)[3]),"=r"((r)[4]),"=r"((r)[5]),"=r"((r)[6]),"=r"((r)[7]), \
          "=r"((r)[8]),"=r"((r)[9]),"=r"((r)[10]),"=r"((r)[11]),"=r"((r)[12]),"=r"((r)[13]),"=r"((r)[14]),"=r"((r)[15]), \
          "=r"((r)[16]),"=r"((r)[17]),"=r"((r)[18]),"=r"((r)[19]),"=r"((r)[20]),"=r"((r)[21]),"=r"((r)[22]),"=r"((r)[23]), \
          "=r"((r)[24]),"=r"((r)[25]),"=r"((r)[26]),"=r"((r)[27]),"=r"((r)[28]),"=r"((r)[29]),"=r"((r)[30]),"=r"((r)[31]) \
        : "r"(addr))
// SW128 K-major: layout=2, SBO=64, LBO=1
static constexpr uint64_t SMEM_DESC_SW128 =
    (uint64_t(2) << 61) | (uint64_t(1) << 46) | (uint64_t(64) << 32) | (uint64_t(1) << 16);
// SW64 K-major: layout=4, SBO=32, LBO=1 (atom = 8 rows x 64B)
static constexpr uint64_t SMEM_DESC_SW64 =
    (uint64_t(4) << 61) | (uint64_t(1) << 46) | (uint64_t(32) << 32) | (uint64_t(1) << 16);
__device__ __forceinline__ uint64_t make_desc(uint32_t addr) {
    return SMEM_DESC_SW128 | ((uint64_t)(addr >> 4) & 0x3FFF);
}
__device__ __forceinline__ uint64_t make_desc64(uint32_t addr) {
    return SMEM_DESC_SW64 | ((uint64_t)(addr >> 4) & 0x3FFF);
}
__device__ __forceinline__ void mma_f16_ss(uint32_t d, uint64_t a, uint64_t b,
                                           uint32_t idesc, uint32_t en) {
    asm volatile("{ .reg .pred p; setp.ne.u32 p, %4, 0;"
                 "tcgen05.mma.cta_group::1.kind::f16 [%0], %1, %2, %3, {%5,%5,%5,%5}, p; }"
                 :: "r"(d), "l"(a), "l"(b), "r"(idesc), "r"(en), "r"(0u) : "memory");
}
#endif

// ---------------- K1: per-point preamble MLP -> p ----------------------------
__global__ void k1_preamble(const float* __restrict__ pos, const float* __restrict__ t,
                            const float* __restrict__ sph_proj,
                            const float* __restrict__ tb1, const float* __restrict__ tb2,
                            const float* __restrict__ gn1, const float* __restrict__ gw1,
                            const float* __restrict__ gn2, const float* __restrict__ gw2,
                            const float* __restrict__ gn3, const float* __restrict__ gw3)
{
    int i = blockIdx.x * blockDim.x + threadIdx.x;
    if (i >= NPTS) return;

    float x = pos[i * 3 + 0], y = pos[i * 3 + 1], z = pos[i * 3 + 2];
    float rho = sqrtf(x * x + y * y + z * z);
    float phi = atan2f(y, x);
    float cz = z / rho;
    cz = fminf(1.0f, fmaxf(-1.0f, cz));
    float theta = acosf(cz);

    float h[12];
#pragma unroll
    for (int j = 0; j < 8; j++)
        h[j] = rho * sph_proj[j] + phi * sph_proj[8 + j] + theta * sph_proj[16 + j];
    float tv = t[i];
    float ct = cosf(tv + tb1[0]);
    float st = sinf(tv + tb2[0]);
    h[8] = ct; h[9] = st;
    h[10] = ct * sigmoidf_(ct);
    h[11] = st * sigmoidf_(st);

    float ss = 0.f;
#pragma unroll
    for (int j = 0; j < 12; j++) ss += h[j] * h[j];
    float sc = 1.0f / (sqrtf(ss / 12.0f) + 1e-8f);
    float hn[12];
#pragma unroll
    for (int j = 0; j < 12; j++) hn[j] = gn1[j] * h[j] * sc;
    float y1[32];
#pragma unroll
    for (int j = 0; j < 32; j++) y1[j] = 0.f;
#pragma unroll
    for (int r = 0; r < 12; r++) {
        float a = hn[r];
#pragma unroll
        for (int j = 0; j < 32; j++) y1[j] += a * gw1[r * 32 + j];
    }
    float h2[16];
#pragma unroll
    for (int k = 0; k < 16; k++) h2[k] = y1[k] * gelu_tanh(y1[16 + k]);

    ss = 0.f;
#pragma unroll
    for (int j = 0; j < 16; j++) ss += h2[j] * h2[j];
    sc = 1.0f / (sqrtf(ss / 16.0f) + 1e-8f);
    float hn2[16];
#pragma unroll
    for (int j = 0; j < 16; j++) hn2[j] = gn2[j] * h2[j] * sc;
    float y2[32];
#pragma unroll
    for (int j = 0; j < 32; j++) y2[j] = 0.f;
#pragma unroll
    for (int r = 0; r < 16; r++) {
        float a = hn2[r];
#pragma unroll
        for (int j = 0; j < 32; j++) y2[j] += a * gw2[r * 32 + j];
    }
    float h3[16];
#pragma unroll
    for (int k = 0; k < 16; k++) h3[k] = y2[k] * gelu_tanh(y2[16 + k]);

    ss = 0.f;
#pragma unroll
    for (int j = 0; j < 16; j++) ss += h3[j] * h3[j];
    sc = 1.0f / (sqrtf(ss / 16.0f) + 1e-8f);
    float z3[3] = {0.f, 0.f, 0.f};
#pragma unroll
    for (int r = 0; r < 16; r++) {
        float a = gn3[r] * h3[r] * sc;
#pragma unroll
        for (int j = 0; j < 3; j++) z3[j] += a * gw3[r * 3 + j];
    }
    g_p[i * 3 + 0] = sigmoidf_(z3[0]);
    g_p[i * 3 + 1] = sigmoidf_(z3[1]);
    g_p[i * 3 + 2] = sigmoidf_(z3[2]);
}

// ---------------- K2m: fused gather + convW(fp16) + convW2 --------------------
__global__ void __launch_bounds__(256) k2m(const float* __restrict__ t,
                          const float* __restrict__ table0, const float* __restrict__ table1,
                          const float* __restrict__ table2, const float* __restrict__ table3,
                          const float* __restrict__ st1, const float* __restrict__ st2,
                          const float* __restrict__ tf, const float* __restrict__ vn1,
                          const float* __restrict__ vw1, const float* __restrict__ vw2,
                          const float* __restrict__ vn2)
{
    int bid = blockIdx.x;
    __shared__ const float* segp[47];
    __shared__ __align__(16) float red[256];
    __shared__ float sh[32][33];

    if (bid < NPTS) {
        int i = bid;
        float p0 = g_p[i * 3 + 0], p1 = g_p[i * 3 + 1], p2 = g_p[i * 3 + 2];
        float tt = t[i];

        int s = threadIdx.x;
        if (s < 47) {
            const float* base = nullptr;
            if (s < 28) {
                int tb = s / 7;
                int o = s % 7;
                int d, F; const float* T;
                if (tb == 0)      { d = 128; F = 16;  T = table0; }
                else if (tb == 1) { d = 64;  F = 32;  T = table1; }
                else if (tb == 2) { d = 32;  F = 64;  T = table2; }
                else              { d = 16;  F = 128; T = table3; }
                int ix = (int)(p0 * (float)(d - 1));
                int iy = (int)(p1 * (float)(d - 1));
                int iz = (int)(p2 * (float)(d - 1));
                if (o > 0) {
                    ix = wrapi(ix + FACE3[o - 1][0], d);
                    iy = wrapi(iy + FACE3[o - 1][1], d);
                    iz = wrapi(iz + FACE3[o - 1][2], d);
                }
                base = T + (size_t)((ix * d + iy) * d + iz) * F;
            } else if (s < 46) {
                int grp = (s - 28) / 9;
                int o = (s - 28) % 9;
                if (grp == 0) {
                    int a = (int)(p0 * 15.0f), b = (int)(p1 * 15.0f),
                        c = (int)(p2 * 15.0f), e = (int)(tt * 63.0f);
                    if (o > 0) {
                        a = wrapi(a + ST8[o - 1][0], 16);
                        b = wrapi(b + ST8[o - 1][1], 16);
                        c = wrapi(c + ST8[o - 1][2], 16);
                        e = wrapi(e + ST8[o - 1][3], 64);
                    }
                    base = st1 + (size_t)(((a * 16 + b) * 16 + c) * 64 + e) * 64;
                } else {
                    int a = (int)(p0 * 63.0f), b = (int)(p1 * 63.0f),
                        c = (int)(p2 * 31.0f), e = (int)(tt * 15.0f);
                    if (o > 0) {
                        a = wrapi(a + ST8[o - 1][0], 64);
                        b = wrapi(b + ST8[o - 1][1], 64);
                        c = wrapi(c + ST8[o - 1][2], 32);
                        e = wrapi(e + ST8[o - 1][3], 16);
                    }
                    base = st2 + (size_t)(((a * 64 + b) * 32 + c) * 16 + e) * 8;
                }
            } else {
                int a = (int)(p0 * 3.0f), b = (int)(p1 * 3.0f),
                    c = (int)(p2 * 3.0f), e = (int)(tt * 65535.0f);
                base = tf + (size_t)(((a * 4 + b) * 4 + c) * 65536 + e) * 8;
            }
            segp[s] = base;
        }
        __syncthreads();

        float4 v0[2], v1[2];
        float ss = 0.f;
#pragma unroll
        for (int gi = 0; gi < 2; gi++) {
            int g = threadIdx.x + gi * 256;
            if (g < NGRP) {
                int f0 = g * 8;
                int seg, off;
                if (f0 < 112)       { seg = f0 >> 4;                 off = f0 & 15; }
                else if (f0 < 336)  { int q = f0 - 112;  seg = 7  + (q >> 5); off = q & 31; }
                else if (f0 < 784)  { int q = f0 - 336;  seg = 14 + (q >> 6); off = q & 63; }
                else if (f0 < 1680) { int q = f0 - 784;  seg = 21 + (q >> 7); off = q & 127; }
                else if (f0 < 2256) { int q = f0 - 1680; seg = 28 + (q >> 6); off = q & 63; }
                else if (f0 < 2328) { int q = f0 - 2256; seg = 37 + (q >> 3); off = q & 7; }
                else                { seg = 46;                      off = f0 - 2328; }
                const float* sp = segp[seg] + off;
                float4 a = *(const float4*)sp;
                float4 b = *(const float4*)(sp + 4);
                v0[gi] = a; v1[gi] = b;
                ss += a.x * a.x + a.y * a.y + a.z * a.z + a.w * a.w
                    + b.x * b.x + b.y * b.y + b.z * b.z + b.w * b.w;
            }
        }
        red[threadIdx.x] = ss;
        __syncthreads();
        for (int w = 128; w > 0; w >>= 1) {
            if (threadIdx.x < w) red[threadIdx.x] += red[threadIdx.x + w];
            __syncthreads();
        }
        float rms = sqrtf(red[0] / (float)TOTAL);
        float sc = 1.0f / (rms + 1e-8f);
        __half* orow = g_Abf + (size_t)i * AW1;
#pragma unroll
        for (int gi = 0; gi < 2; gi++) {
            int g = threadIdx.x + gi * 256;
            if (g < NGRP) {
                int f0 = g * 8;
                float4 n0 = *(const float4*)&vn1[f0];
                float4 n1 = *(const float4*)&vn1[f0 + 4];
                float v[8] = { v0[gi].x * n0.x * sc, v0[gi].y * n0.y * sc,
                               v0[gi].z * n0.z * sc, v0[gi].w * n0.w * sc,
                               v1[gi].x * n1.x * sc, v1[gi].y * n1.y * sc,
                               v1[gi].z * n1.z * sc, v1[gi].w * n1.w * sc };
                uint32_t hw[4];
#pragma unroll
                for (int j = 0; j < 4; j++) {
                    __half h0 = __float2half(v[2 * j]);
                    __half h1 = __float2half(v[2 * j + 1]);
                    hw[j] = (uint32_t)(*(unsigned short*)&h0) | ((uint32_t)(*(unsigned short*)&h1) << 16);
                }
                *(uint4*)(orow + f0) = make_uint4(hw[0], hw[1], hw[2], hw[3]);
            }
        }
    } else if (bid < NPTS + CWBLK) {
        int b2 = bid - NPTS;
        int n0 = (b2 % 152) * 32, k0 = (b2 / 152) * 32;
        int tx = threadIdx.x & 31, ty = threadIdx.x >> 5;
        int tile = n0 >> 8, half = (n0 >> 7) & 1;
        int f0 = tile * 128 + (n0 & 127);
#pragma unroll
        for (int ii = 0; ii < 4; ii++) {
            int r = ty + ii * 8;
            int k = k0 + r;
            int f = f0 + tx;
            float v = 0.f;
            if (f < TOTAL && k < TOTAL)
                v = vw1[(size_t)k * TWOTOTAL + half * TOTAL + f];
            sh[r][tx] = v;
        }
        __syncthreads();
#pragma unroll
        for (int ii = 0; ii < 4; ii++) {
            int r = ty + ii * 8;
            int n = n0 + r;
            g_WT[(size_t)n * WTS + (k0 + tx)] = __float2half(sh[tx][r]);
        }
    } else {
        int idx = (bid - NPTS - CWBLK) * 256 + threadIdx.x;
        if (idx < TOTAL * 64) {
            int k = idx >> 6, n = idx & 63;
            float v = vn2[k] * vw2[idx];
            __nv_bfloat16 h = __float2bfloat16(v);
            float hf = __bfloat162float(h);
            __nv_bfloat16 l = __float2bfloat16(v - hf);
            size_t base = (size_t)n * VW + (size_t)((k >> 5) * 64);
            g_WT2[base + (k & 31)] = h;
            g_WT2[base + 32 + (k & 31)] = l;
        }
    }
}

// ---------------- K3: TMA-fed single-fp16 GEMM1, 5-buffer ring ----------------
// Stage = 32 logical k: A 16KB (256 rows x 64B, SW64) + W 16KB (SW64).
#define STG1 32768
#define SMEM1 (1024 + NB3 * STG1)

__global__ void __launch_bounds__(256, 1) k3_gemm1(const __half* __restrict__ Abf,
                                                   const __half* __restrict__ WT,
                                                   __nv_bfloat16* __restrict__ Vbf,
                                                   float* __restrict__ sspart,
                                                   const __grid_constant__ CUtensorMap tmA,
                                                   const __grid_constant__ CUtensorMap tmW)
{
    extern __shared__ char smem[];
    uint32_t sbase = smem_u32(smem);
    int tid = threadIdx.x;
    int wid = tid >> 5, lid = tid & 31;
    int tile = blockIdx.x;
    int bm = blockIdx.y * 256;
    int bn = tile * 256;

#if defined(__CUDA_ARCH_FEAT_SM103_ALL)
    const uint32_t TSLOT = sbase;
    const uint32_t FULB = sbase + 16;   // 5 x 8B
    const uint32_t EMPB = sbase + 64;   // 5 x 8B
    const uint32_t DONE = sbase + 112;
    const uint32_t SDATA = sbase + 1024;

    if (wid == 0) TC_ALLOC(TSLOT, 512);
    if (tid == 0) {
#pragma unroll
        for (int b = 0; b < NB3; b++) {
            MBARRIER_INIT(FULB + b * 8, 1);
            MBARRIER_INIT(EMPB + b * 8, 1);
        }
        MBARRIER_INIT(DONE, 1);
        FENCE_ASYNC_SH();
    }
    __syncthreads();
    uint32_t tmem;
    asm volatile("ld.shared.b32 %0, [%1];" : "=r"(tmem) : "r"(TSLOT));

    const uint32_t IDESC = (1u << 4) | (32u << 17) | (8u << 24);

    if (wid == 0 && elect_one()) {
        // single-thread TMA producer + MMA consumer
        int pf[NB3] = {0, 0, 0, 0, 0};
        int pe[NB3] = {0, 0, 0, 0, 1};   // buffer NB3-1 is fresh at its first wait
        // prologue: stages 0..NB3-2
#pragma unroll
        for (int b = 0; b < NB3 - 1; b++) {
            uint32_t ab = SDATA + b * STG1;
            MBARRIER_EXPECT_TX(FULB + b * 8, (uint32_t)STG1);
            TMA_LOAD_2D(ab,         &tmA, b * 32, bm, FULB + b * 8);
            TMA_LOAD_2D(ab + 16384, &tmW, b * 32, bn, FULB + b * 8);
        }
        for (int s = 0; s < NST1; s++) {
            int b = s % NB3;
            MBARRIER_WAIT_PARITY(FULB + b * 8, pf[b]); pf[b] ^= 1;
            uint32_t ab = SDATA + b * STG1;
            uint64_t wd = make_desc64(ab + 16384);
#pragma unroll
            for (int half = 0; half < 2; half++) {
                uint64_t ad = make_desc64(ab + half * 8192);
                uint32_t dt = tmem + half * 256;
                uint32_t en0 = (s > 0) ? 1u : 0u;
                mma_f16_ss(dt, ad + 0, wd + 0, IDESC, en0);
                mma_f16_ss(dt, ad + 2, wd + 2, IDESC, 1u);
            }
            TC_COMMIT(EMPB + b * 8);
            int nxt = s + NB3 - 1;
            if (nxt < NST1) {
                int nb = nxt % NB3;
                MBARRIER_WAIT_PARITY(EMPB + nb * 8, pe[nb]); pe[nb] ^= 1;
                uint32_t nab = SDATA + nb * STG1;
                MBARRIER_EXPECT_TX(FULB + nb * 8, (uint32_t)STG1);
                TMA_LOAD_2D(nab,         &tmA, nxt * 32, bm, FULB + nb * 8);
                TMA_LOAD_2D(nab + 16384, &tmW, nxt * 32, bn, FULB + nb * 8);
            }
        }
        TC_COMMIT(DONE);
    }
    MBARRIER_WAIT_PARITY(DONE, 0);
    TC_FENCE_AFTER();

    // fused epilogue: a = cols 0-127, g = cols 128-255 -> v = a*gelu(g)
    {
        int m = bm + ((wid < 4) ? 0 : 128) + (wid & 3) * 32 + lid;
        uint32_t dbase = tmem + ((wid < 4) ? 0 : 256);
        float ssacc = 0.f;
#pragma unroll
        for (int cp = 0; cp < 4; cp++) {
            uint32_t ra[32], rg[32];
            TC_LD_X32(ra, dbase + cp * 32);
            TC_LD_X32(rg, dbase + 128 + cp * 32);
            TC_WAIT_LD();
            uint32_t o[32];
#pragma unroll
            for (int j = 0; j < 32; j += 2) {
                float a0 = __uint_as_float(ra[j]),     a1 = __uint_as_float(ra[j + 1]);
                float g0 = __uint_as_float(rg[j]),     g1 = __uint_as_float(rg[j + 1]);
                float v0 = a0 * gelu_fast(g0), v1 = a1 * gelu_fast(g1);
                ssacc += v0 * v0 + v1 * v1;
                __nv_bfloat16 h0 = __float2bfloat16(v0);
                __nv_bfloat16 h1 = __float2bfloat16(v1);
                __nv_bfloat16 l0 = __float2bfloat16(v0 - __bfloat162float(h0));
                __nv_bfloat16 l1 = __float2bfloat16(v1 - __bfloat162float(h1));
                unsigned short uh0 = *(unsigned short*)&h0, uh1 = *(unsigned short*)&h1;
                unsigned short ul0 = *(unsigned short*)&l0, ul1 = *(unsigned short*)&l1;
                o[j >> 1]        = (uint32_t)uh0 | ((uint32_t)uh1 << 16);
                o[16 + (j >> 1)] = (uint32_t)ul0 | ((uint32_t)ul1 << 16);
            }
            int fb = tile * 4 + cp;
            uint4* dst = (uint4*)(Vbf + (size_t)m * VW + fb * 64);
#pragma unroll
            for (int q = 0; q < 8; q++)
                dst[q] = make_uint4(o[4 * q], o[4 * q + 1], o[4 * q + 2], o[4 * q + 3]);
        }
        sspart[(size_t)m * NTILES + tile] = ssacc;
    }
    __syncthreads();
    if (wid == 0) {
        TC_RELINQ();
        TC_DEALLOC(tmem, 512);
    }
#else
    // ---- FFMA fallback (generic pass; never selected on sm_103a) ----
    float* Da   = (float*)smem;
    float* As   = Da + 128 * 128;
    float* Bs   = As + 16 * 128;
    float* ssrd = Bs + 16 * 128;
    int tx = tid % 16, ty = tid / 16;
    for (int pass = 0; pass < 2; pass++) {
        int pm = bm + pass * 128;
        for (int half = 0; half < 2; half++) {
            int pn = bn + half * 128;
            float acc[8][8];
#pragma unroll
            for (int a = 0; a < 8; a++)
#pragma unroll
                for (int b = 0; b < 8; b++) acc[a][b] = 0.f;
            for (int k0 = 0; k0 < KPAD1; k0 += 16) {
                __syncthreads();
                for (int idx = tid; idx < 2048; idx += 256) {
                    int row = idx >> 4, kk = idx & 15;
                    int k = k0 + kk;
                    As[kk * 128 + row] = __half2float(Abf[(size_t)(pm + row) * AW1 + k]);
                    Bs[kk * 128 + row] = __half2float(WT[(size_t)(pn + row) * WTS + k]);
                }
                __syncthreads();
#pragma unroll
                for (int k = 0; k < 16; k++) {
                    float af[8], bf[8];
#pragma unroll
                    for (int a = 0; a < 8; a++) af[a] = As[k * 128 + ty * 8 + a];
#pragma unroll
                    for (int b = 0; b < 8; b++) bf[b] = Bs[k * 128 + tx * 8 + b];
#pragma unroll
                    for (int a = 0; a < 8; a++)
#pragma unroll
                        for (int b = 0; b < 8; b++) acc[a][b] += af[a] * bf[b];
                }
            }
            __syncthreads();
            if (half == 0) {
#pragma unroll
                for (int a = 0; a < 8; a++)
#pragma unroll
                    for (int b = 0; b < 8; b++)
                        Da[(ty * 8 + a) * 128 + tx * 8 + b] = acc[a][b];
            } else {
#pragma unroll
                for (int a = 0; a < 8; a++) {
                    int row = ty * 8 + a;
                    float ssp = 0.f;
#pragma unroll
                    for (int b = 0; b < 8; b++) {
                        int col = tx * 8 + b;
                        float av = Da[row * 128 + col];
                        float v = av * gelu_tanh(acc[a][b]);
                        ssp += v * v;
                        __nv_bfloat16 h = __float2bfloat16(v);
                        __nv_bfloat16 l = __float2bfloat16(v - __bfloat162float(h));
                        int f = tile * 128 + col;
                        int fb = f >> 5, pos = f & 31;
                        Vbf[(size_t)(pm + row) * VW + fb * 64 + pos] = h;
                        Vbf[(size_t)(pm + row) * VW + fb * 64 + 32 + pos] = l;
                    }
                    ssrd[row * 16 + tx] = ssp;
                }
            }
            __syncthreads();
        }
        if (tid < 128) {
            float sm = 0.f;
            for (int j = 0; j < 16; j++) sm += ssrd[tid * 16 + j];
            sspart[(size_t)(pm + tid) * NTILES + tile] = sm;
        }
        __syncthreads();
    }
#endif
}

// ---------------- K5: GEMM2 (bf16 3-term), 4-buffer, + fused final linear -----
#define SMEM5 (1024 + 4 * 24576)
__global__ void __launch_bounds__(256, 1) k5_gemm2(const __nv_bfloat16* __restrict__ Vbf,
                                                   const __nv_bfloat16* __restrict__ WT2,
                                                   const float* __restrict__ t,
                                                   const float* __restrict__ fw,
                                                   const float* __restrict__ fbias,
                                                   const float* __restrict__ sspart,
                                                   float* __restrict__ out)
{
    extern __shared__ char smem[];
    uint32_t sbase = smem_u32(smem);
    int tid = threadIdx.x;
    int wid = tid >> 5, lid = tid & 31;
    int bm = blockIdx.x * 128;

#if defined(__CUDA_ARCH_FEAT_SM103_ALL)
    const uint32_t TSLOT = sbase;
    const uint32_t MB0 = sbase + 16;
    const uint32_t MB1 = sbase + 24;
    const uint32_t MB2 = sbase + 32;
    const uint32_t MB3 = sbase + 40;
    const uint32_t SDATA = sbase + 1024;

    if (wid == 0) TC_ALLOC(TSLOT, 64);
    if (tid == 0) {
        MBARRIER_INIT(MB0, 1); MBARRIER_INIT(MB1, 1);
        MBARRIER_INIT(MB2, 1); MBARRIER_INIT(MB3, 1);
    }
    __syncthreads();
    uint32_t tmem;
    asm volatile("ld.shared.b32 %0, [%1];" : "=r"(tmem) : "r"(TSLOT));

    const uint32_t IDESC = (1u << 4) | (1u << 7) | (1u << 10) | (8u << 17) | (8u << 24);

    auto load_stage = [&](int s) {
        int buf = s & 3;
        int ks = s * 64;
        uint32_t ab = SDATA + buf * 24576;
        uint32_t wb = ab + 16384;
        const __nv_bfloat16* Asrc = Vbf + (size_t)bm * VW + ks;
        const __nv_bfloat16* Wsrc = WT2 + ks;
#pragma unroll
        for (int j = 0; j < 4; j++) {
            int idx = tid + j * 256;
            int row = idx >> 3, c = idx & 7;
            uint32_t off = (uint32_t)(row * 128 + c * 16);
            uint32_t sw = off ^ ((off >> 3) & 0x70);
            CP_ASYNC16(ab + sw, (const void*)(Asrc + (size_t)row * VW + c * 8));
        }
#pragma unroll
        for (int j = 0; j < 2; j++) {
            int idx = tid + j * 256;
            int row = idx >> 3, c = idx & 7;
            uint32_t off = (uint32_t)(row * 128 + c * 16);
            uint32_t sw = off ^ ((off >> 3) & 0x70);
            CP_ASYNC16(wb + sw, (const void*)(Wsrc + (size_t)row * VW + c * 8));
        }
        CP_COMMIT();
    };

    int ph0 = 0, ph1 = 0, ph2 = 0, ph3 = 0;
    load_stage(0);
    load_stage(1);
    load_stage(2);
    for (int s = 0; s < NST2; s++) {
        if (s + 3 < NST2) {
            if (s >= 1) {
                int b = (s - 1) & 3;
                if (b == 0)      { MBARRIER_WAIT_PARITY(MB0, ph0); ph0 ^= 1; }
                else if (b == 1) { MBARRIER_WAIT_PARITY(MB1, ph1); ph1 ^= 1; }
                else if (b == 2) { MBARRIER_WAIT_PARITY(MB2, ph2); ph2 ^= 1; }
                else             { MBARRIER_WAIT_PARITY(MB3, ph3); ph3 ^= 1; }
            }
            load_stage(s + 3);
        }
        if (s + 3 < NST2)      CP_WAIT3();
        else if (s + 2 < NST2) CP_WAIT2();
        else if (s + 1 < NST2) CP_WAIT1();
        else                   CP_WAIT0();
        __syncthreads();
        FENCE_ASYNC_SH();
        if (wid == 0) {
            if (elect_one()) {
                int buf = s & 3;
                uint32_t ab = SDATA + buf * 24576;
                uint64_t ad = make_desc(ab);
                uint64_t bd = make_desc(ab + 16384);
                uint32_t en0 = (s > 0) ? 1u : 0u;
                mma_f16_ss(tmem, ad + 0, bd + 0, IDESC, en0);
                mma_f16_ss(tmem, ad + 2, bd + 2, IDESC, 1u);
                mma_f16_ss(tmem, ad + 4, bd + 0, IDESC, 1u);
                mma_f16_ss(tmem, ad + 6, bd + 2, IDESC, 1u);
                mma_f16_ss(tmem, ad + 0, bd + 4, IDESC, 1u);
                mma_f16_ss(tmem, ad + 2, bd + 6, IDESC, 1u);
                if (buf == 0)      TC_COMMIT(MB0);
                else if (buf == 1) TC_COMMIT(MB1);
                else if (buf == 2) TC_COMMIT(MB2);
                else               TC_COMMIT(MB3);
            }
        }
    }
    {
        int b = (NST2 - 1) & 3;   // 75 & 3 = 3
        if (b == 0)      MBARRIER_WAIT_PARITY(MB0, ph0);
        else if (b == 1) MBARRIER_WAIT_PARITY(MB1, ph1);
        else if (b == 2) MBARRIER_WAIT_PARITY(MB2, ph2);
        else             MBARRIER_WAIT_PARITY(MB3, ph3);
    }
    TC_FENCE_AFTER();

    if (wid < 4) {
        int m = bm + wid * 32 + lid;
        uint32_t r[32], r2[32];
        TC_LD_X32(r, tmem);
        TC_LD_X32(r2, tmem + 32);
        TC_WAIT_LD();

        const float* sp = sspart + (size_t)m * NTILES;
        float ss = 0.f;
#pragma unroll
        for (int q = 0; q < NTILES; q++) ss += sp[q];
        float sc = 1.0f / (sqrtf(ss / (float)TOTAL) + 1e-8f);

        float o0 = 0.f, o1 = 0.f, o2 = 0.f, o3 = 0.f;
#pragma unroll
        for (int q = 0; q < 32; q++) {
            float a = __uint_as_float(r[q]);
            o0 += a * fw[q * 4 + 0]; o1 += a * fw[q * 4 + 1];
            o2 += a * fw[q * 4 + 2]; o3 += a * fw[q * 4 + 3];
        }
#pragma unroll
        for (int q = 0; q < 32; q++) {
            float a = __uint_as_float(r2[q]);
            o0 += a * fw[(32 + q) * 4 + 0]; o1 += a * fw[(32 + q) * 4 + 1];
            o2 += a * fw[(32 + q) * 4 + 2]; o3 += a * fw[(32 + q) * 4 + 3];
        }
        o0 *= sc; o1 *= sc; o2 *= sc; o3 *= sc;
        o0 += fbias[0]; o1 += fbias[1]; o2 += fbias[2]; o3 += fbias[3];
        float p0 = g_p[m * 3 + 0], p1 = g_p[m * 3 + 1], p2 = g_p[m * 3 + 2];
        float tv = t[m];
        o0 += p0 * fw[256 + 0] + p1 * fw[260 + 0] + p2 * fw[264 + 0] + tv * fw[268 + 0];
        o1 += p0 * fw[256 + 1] + p1 * fw[260 + 1] + p2 * fw[264 + 1] + tv * fw[268 + 1];
        o2 += p0 * fw[256 + 2] + p1 * fw[260 + 2] + p2 * fw[264 + 2] + tv * fw[268 + 2];
        o3 += p0 * fw[256 + 3] + p1 * fw[260 + 3] + p2 * fw[264 + 3] + tv * fw[268 + 3];
        *(float4*)(out + (size_t)m * 4) = make_float4(o0, o1, o2, o3);
    }
    __syncthreads();
    if (wid == 0) {
        TC_RELINQ();
        TC_DEALLOC(tmem, 64);
    }
#else
    // ---- FFMA fallback (256 threads) ----
    float* Ds = (float*)smem;
    float* Bs = Ds + 64 * 64;
    for (int m0 = 0; m0 < 128; m0 += 64) {
        int mrow = (tid >> 2);
        int m = bm + m0 + mrow;
        int nq = (tid & 3) * 16;
        float acc[16];
#pragma unroll
        for (int a = 0; a < 16; a++) acc[a] = 0.f;
        for (int k0 = 0; k0 < KPAD2; k0 += 16) {
            __syncthreads();
            for (int idx = tid; idx < 1024; idx += 256) {
                int kk = idx >> 6, n = idx & 63;
                int k = k0 + kk;
                const __nv_bfloat16* wr = WT2 + (size_t)n * VW + (size_t)(k >> 5) * 64 + (k & 31);
                Bs[kk * 64 + n] = __bfloat162float(wr[0]) + __bfloat162float(wr[32]);
            }
            __syncthreads();
#pragma unroll
            for (int kk = 0; kk < 16; kk++) {
                int k = k0 + kk;
                const __nv_bfloat16* ar = Vbf + (size_t)m * VW + (size_t)(k >> 5) * 64 + (k & 31);
                float av = __bfloat162float(ar[0]) + __bfloat162float(ar[32]);
#pragma unroll
                for (int a = 0; a < 16; a++) acc[a] += av * Bs[kk * 64 + nq + a];
            }
        }
        __syncthreads();
        for (int a = 0; a < 16; a++) Ds[mrow * 64 + nq + a] = acc[a];
        __syncthreads();
        if (tid < 64) {
            int m2 = bm + m0 + tid;
            const float* sp = sspart + (size_t)m2 * NTILES;
            float ss = 0.f;
            for (int q = 0; q < NTILES; q++) ss += sp[q];
            float sc = 1.0f / (sqrtf(ss / (float)TOTAL) + 1e-8f);
            float o0 = 0.f, o1 = 0.f, o2 = 0.f, o3 = 0.f;
            for (int q = 0; q < 64; q++) {
                float a = Ds[tid * 64 + q];
                o0 += a * fw[q * 4 + 0]; o1 += a * fw[q * 4 + 1];
                o2 += a * fw[q * 4 + 2]; o3 += a * fw[q * 4 + 3];
            }
            o0 *= sc; o1 *= sc; o2 *= sc; o3 *= sc;
            o0 += fbias[0]; o1 += fbias[1]; o2 += fbias[2]; o3 += fbias[3];
            float p0 = g_p[m2 * 3 + 0], p1 = g_p[m2 * 3 + 1], p2 = g_p[m2 * 3 + 2];
            float tv = t[m2];
            o0 += p0 * fw[256 + 0] + p1 * fw[260 + 0] + p2 * fw[264 + 0] + tv * fw[268 + 0];
            o1 += p0 * fw[256 + 1] + p1 * fw[260 + 1] + p2 * fw[264 + 1] + tv * fw[268 + 1];
            o2 += p0 * fw[256 + 2] + p1 * fw[260 + 2] + p2 * fw[264 + 2] + tv * fw[268 + 2];
            o3 += p0 * fw[256 + 3] + p1 * fw[260 + 3] + p2 * fw[264 + 3] + tv * fw[268 + 3];
            *(float4*)(out + (size_t)m2 * 4) = make_float4(o0, o1, o2, o3);
        }
        __syncthreads();
    }
#endif
}

// ---------------- host: tensormap construction --------------------------------
typedef CUresult (CUDAAPI *PFN_tmEncode)(CUtensorMap*, CUtensorMapDataType, cuuint32_t,
                                         void*, const cuuint64_t*, const cuuint64_t*,
                                         const cuuint32_t*, const cuuint32_t*,
                                         CUtensorMapInterleave, CUtensorMapSwizzle,
                                         CUtensorMapL2promotion, CUtensorMapFloatOOBfill);

static void encode_map(PFN_tmEncode enc, CUtensorMap* tm, void* base,
                       uint64_t d0, uint64_t d1)
{
    cuuint64_t dims[2]    = {(cuuint64_t)d0, (cuuint64_t)d1};
    cuuint64_t strides[1] = {(cuuint64_t)(d0 * 2)};
    cuuint32_t box[2]     = {32, 256};
    cuuint32_t estr[2]    = {1, 1};
    enc(tm, CU_TENSOR_MAP_DATA_TYPE_FLOAT16, 2, base, dims, strides, box, estr,
        CU_TENSOR_MAP_INTERLEAVE_NONE, CU_TENSOR_MAP_SWIZZLE_64B,
        CU_TENSOR_MAP_L2_PROMOTION_L2_128B, CU_TENSOR_MAP_FLOAT_OOB_FILL_NONE);
}

// ---------------- launcher ----------------------------------------------------
extern "C" void kernel_launch(void* const* d_in, const int* in_sizes, int n_in,
                              void* d_out, int out_size)
{
    const float* pos      = (const float*)d_in[0];
    const float* t        = (const float*)d_in[2];
    const float* table0   = (const float*)d_in[3];
    const float* table1   = (const float*)d_in[4];
    const float* table2   = (const float*)d_in[5];
    const float* table3   = (const float*)d_in[6];
    const float* st1      = (const float*)d_in[7];
    const float* st2      = (const float*)d_in[8];
    const float* tf       = (const float*)d_in[9];
    const float* sph_proj = (const float*)d_in[10];
    const float* tb1      = (const float*)d_in[11];
    const float* tb2      = (const float*)d_in[12];
    const float* gn1      = (const float*)d_in[13];
    const float* gw1      = (const float*)d_in[14];
    const float* gn2      = (const float*)d_in[15];
    const float* gw2      = (const float*)d_in[16];
    const float* gn3      = (const float*)d_in[17];
    const float* gw3      = (const float*)d_in[18];
    const float* vn1      = (const float*)d_in[19];
    const float* vw1      = (const float*)d_in[20];
    const float* vn2      = (const float*)d_in[21];
    const float* vw2      = (const float*)d_in[22];
    const float* fw       = (const float*)d_in[23];
    const float* fb       = (const float*)d_in[24];
    float* out = (float*)d_out;

    __half* Abf;        cudaGetSymbolAddress((void**)&Abf, g_Abf);
    __nv_bfloat16* Vbf; cudaGetSymbolAddress((void**)&Vbf, g_Vbf);
    __half* WT;         cudaGetSymbolAddress((void**)&WT,  g_WT);
    __nv_bfloat16* WT2; cudaGetSymbolAddress((void**)&WT2, g_WT2);
    float* Sp;          cudaGetSymbolAddress((void**)&Sp,  g_sspart);

    static CUtensorMap s_tmA, s_tmW;
    static bool s_init = false;
    if (!s_init) {
        void* fn = nullptr;
        cudaDriverEntryPointQueryResult qr;
        cudaGetDriverEntryPoint("cuTensorMapEncodeTiled", &fn,
                                cudaEnableDefault, &qr);
        PFN_tmEncode enc = (PFN_tmEncode)fn;
        encode_map(enc, &s_tmA, Abf, AW1, NPTS);
        encode_map(enc, &s_tmW, WT,  WTS, WTROWS);
        cudaFuncSetAttribute(k3_gemm1, cudaFuncAttributeMaxDynamicSharedMemorySize, SMEM1);
        cudaFuncSetAttribute(k5_gemm2, cudaFuncAttributeMaxDynamicSharedMemorySize, SMEM5);
        s_init = true;
    }

    k1_preamble<<<NPTS / 256, 256>>>(pos, t, sph_proj, tb1, tb2,
                                     gn1, gw1, gn2, gw2, gn3, gw3);

    k2m<<<NPTS + CWBLK + CW2BLK, 256>>>(t, table0, table1, table2, table3,
                                        st1, st2, tf, vn1, vw1, vw2, vn2);

    dim3 g1(NTILES, NPTS / 256);          // (19, 128)
    k3_gemm1<<<g1, 256, SMEM1>>>(Abf, WT, Vbf, Sp, s_tmA, s_tmW);

    k5_gemm2<<<NPTS / 128, 256, SMEM5>>>(Vbf, WT2, t, fw, fb, Sp, out);
}